// round 1
// baseline (speedup 1.0000x reference)
#include <cuda_runtime.h>
#include <math.h>

// QMixer forward, fp32, weights staged in SMEM, NPAIR pairs per CTA.
// B=128 S=128 A=8 En=8 E=16 NFal=32 NFen=16 D=64 Da=128 M=32 H=64

namespace {

constexpr int NTH    = 256;
constexpr int NPAIR  = 8;
constexpr int BSTOT  = 16384;           // B*S
constexpr int GRID   = BSTOT / NPAIR;   // 2048

// ---- SMEM float offsets ----
constexpr int OFF_WAL  = 0;                       // 32*64
constexpr int OFF_WEN  = OFF_WAL  + 32 * 64;      // 16*64
constexpr int OFF_WQ   = OFF_WEN  + 16 * 64;      // 64*128
constexpr int OFF_WK   = OFF_WQ   + 64 * 128;     // 64*128
constexpr int OFF_W1A  = OFF_WK   + 64 * 128;     // 128*64
constexpr int OFF_W1B  = OFF_W1A  + 128 * 64;     // 64*32
constexpr int OFF_WFA  = OFF_W1B  + 64 * 32;      // 64*64
constexpr int OFF_WFB  = OFF_WFA  + 64 * 64;      // 64*32
constexpr int OFF_HBW  = OFF_WFB  + 64 * 32;      // 64*32
constexpr int OFF_VW1  = OFF_HBW  + 64 * 32;      // 64*32
constexpr int OFF_VW2  = OFF_VW1  + 64 * 32;      // 32
constexpr int OFF_BAL  = OFF_VW2  + 32;           // 64
constexpr int OFF_BEN  = OFF_BAL  + 64;           // 64
constexpr int OFF_BQ   = OFF_BEN  + 64;           // 128
constexpr int OFF_BK   = OFF_BQ   + 128;          // 128
constexpr int OFF_W1B1 = OFF_BK   + 128;          // 64
constexpr int OFF_W1B2 = OFF_W1B1 + 64;           // 32
constexpr int OFF_WFB1 = OFF_W1B2 + 32;           // 64
constexpr int OFF_WFB2 = OFF_WFB1 + 64;           // 32
constexpr int OFF_HBB  = OFF_WFB2 + 32;           // 32
constexpr int OFF_VB1  = OFF_HBB  + 32;           // 32
constexpr int OFF_VB2  = OFF_VB1  + 32;           // 4 (1 used)
// scratch (per pair, reused)
constexpr int OFF_FEAT = OFF_VB2  + 4;            // 16*32
constexpr int OFF_AQ   = OFF_FEAT + 16 * 32;      // 8
constexpr int OFF_ENTT = OFF_AQ   + 8;            // 64*17 (entT[d][e], pad 17)
constexpr int OFF_Q    = OFF_ENTT + 64 * 17;      // 16*132 (pad 132, float4-aligned)
constexpr int OFF_K    = OFF_Q    + 16 * 132;     // 16*132
constexpr int OFF_E    = OFF_K    + 16 * 132;     // 16*17
constexpr int OFF_ATT  = OFF_E    + 16 * 17;      // 16*17
constexpr int OFF_AMEAN= OFF_ATT  + 16 * 17;      // 16
constexpr int OFF_AOUT = OFF_AMEAN+ 16;           // 64
constexpr int OFF_SH   = OFF_AOUT + 64;           // 8*64
constexpr int OFF_W1O  = OFF_SH   + 8 * 64;       // 8*32
constexpr int OFF_HID  = OFF_W1O  + 8 * 32;       // 32
constexpr int OFF_H2   = OFF_HID  + 32;           // 64
constexpr int OFF_H3   = OFF_H2   + 64;           // 32
constexpr int SMEM_FLOATS = OFF_H3 + 32;
constexpr int SMEM_BYTES  = SMEM_FLOATS * 4;      // ~191.8 KB

static_assert((OFF_Q & 3) == 0, "q must be 16B aligned");
static_assert((OFF_K & 3) == 0, "k must be 16B aligned");
static_assert((OFF_WQ & 3) == 0, "Wq must be 16B aligned");

} // namespace

__global__ void __launch_bounds__(NTH, 1) qmixer_kernel(
    const float* __restrict__ g_aq,     // agent_qs  [B,S,8]
    const float* __restrict__ g_ally,   // [8,B,S,32]
    const float* __restrict__ g_enemy,  // [8,B,S,16]
    const float* __restrict__ g_Wal,  const float* __restrict__ g_bal,
    const float* __restrict__ g_Wen,  const float* __restrict__ g_ben,
    const float* __restrict__ g_Wq,   const float* __restrict__ g_bq,
    const float* __restrict__ g_Wk,   const float* __restrict__ g_bk,
    const float* __restrict__ g_w1W1, const float* __restrict__ g_w1b1,
    const float* __restrict__ g_w1W2, const float* __restrict__ g_w1b2,
    const float* __restrict__ g_wfW1, const float* __restrict__ g_wfb1,
    const float* __restrict__ g_wfW2, const float* __restrict__ g_wfb2,
    const float* __restrict__ g_hbW,  const float* __restrict__ g_hbb,
    const float* __restrict__ g_vW1,  const float* __restrict__ g_vb1,
    const float* __restrict__ g_vW2,  const float* __restrict__ g_vb2,
    float* __restrict__ out)
{
    extern __shared__ float sm[];
    const int tid = threadIdx.x;

    // ---- stage all weights/biases in SMEM (once per CTA) ----
    {
        auto cp = [&](int off, const float* src, int n) {
            for (int i = tid; i < n; i += NTH) sm[off + i] = src[i];
        };
        cp(OFF_WAL,  g_Wal,  32 * 64);
        cp(OFF_WEN,  g_Wen,  16 * 64);
        cp(OFF_WQ,   g_Wq,   64 * 128);
        cp(OFF_WK,   g_Wk,   64 * 128);
        cp(OFF_W1A,  g_w1W1, 128 * 64);
        cp(OFF_W1B,  g_w1W2, 64 * 32);
        cp(OFF_WFA,  g_wfW1, 64 * 64);
        cp(OFF_WFB,  g_wfW2, 64 * 32);
        cp(OFF_HBW,  g_hbW,  64 * 32);
        cp(OFF_VW1,  g_vW1,  64 * 32);
        cp(OFF_VW2,  g_vW2,  32);
        cp(OFF_BAL,  g_bal,  64);
        cp(OFF_BEN,  g_ben,  64);
        cp(OFF_BQ,   g_bq,   128);
        cp(OFF_BK,   g_bk,   128);
        cp(OFF_W1B1, g_w1b1, 64);
        cp(OFF_W1B2, g_w1b2, 32);
        cp(OFF_WFB1, g_wfb1, 64);
        cp(OFF_WFB2, g_wfb2, 32);
        cp(OFF_HBB,  g_hbb,  32);
        cp(OFF_VB1,  g_vb1,  32);
        if (tid == 0) sm[OFF_VB2] = g_vb2[0];
    }
    __syncthreads();

    for (int p = 0; p < NPAIR; ++p) {
        const int gp = blockIdx.x * NPAIR + p;   // b*128 + s

        // ---- Phase A: load per-pair inputs ----
        {
            int e = tid >> 5, f = tid & 31;      // 8 entities x 32 feats
            sm[OFF_FEAT + e * 32 + f] = g_ally[(e * BSTOT + gp) * 32 + f];
            if (tid < 128) {
                int ee = tid >> 4, ff = tid & 15;
                sm[OFF_FEAT + (8 + ee) * 32 + ff] = g_enemy[(ee * BSTOT + gp) * 16 + ff];
            }
            if (tid < 8) sm[OFF_AQ + tid] = g_aq[gp * 8 + tid];
        }
        __syncthreads();

        // ---- Phase B: entity embeddings -> entT[d][e] (stride 17) ----
        {
            int d  = tid & 63;
            int eg = tid >> 6;                   // 0..3
            float aa0 = sm[OFF_BAL + d], aa1 = aa0;
            float ee0 = sm[OFF_BEN + d], ee1 = ee0;
            const float* f0 = &sm[OFF_FEAT + eg * 32];
            const float* f1 = &sm[OFF_FEAT + (eg + 4) * 32];
            const float* f2 = &sm[OFF_FEAT + (eg + 8) * 32];
            const float* f3 = &sm[OFF_FEAT + (eg + 12) * 32];
            #pragma unroll 8
            for (int f = 0; f < 32; ++f) {
                float w = sm[OFF_WAL + f * 64 + d];
                aa0 = fmaf(f0[f], w, aa0);
                aa1 = fmaf(f1[f], w, aa1);
            }
            #pragma unroll 8
            for (int f = 0; f < 16; ++f) {
                float w = sm[OFF_WEN + f * 64 + d];
                ee0 = fmaf(f2[f], w, ee0);
                ee1 = fmaf(f3[f], w, ee1);
            }
            sm[OFF_ENTT + d * 17 + eg]      = aa0;
            sm[OFF_ENTT + d * 17 + eg + 4]  = aa1;
            sm[OFF_ENTT + d * 17 + eg + 8]  = ee0;
            sm[OFF_ENTT + d * 17 + eg + 12] = ee1;
        }
        __syncthreads();

        // ---- Phase C: Q/K projections, 4e x 4da register tiles ----
        {
            int half = tid >> 7;                 // 0 -> q, 1 -> k
            int t2   = tid & 127;
            int da0  = (t2 & 31) << 2;
            int e0   = (t2 >> 5) << 2;
            int offW = half ? OFF_WK : OFF_WQ;
            int offB = half ? OFF_BK : OFF_BQ;
            int offD = half ? OFF_K  : OFF_Q;
            float acc[4][4];
            #pragma unroll
            for (int ei = 0; ei < 4; ++ei)
                #pragma unroll
                for (int di = 0; di < 4; ++di)
                    acc[ei][di] = sm[offB + da0 + di];
            #pragma unroll 4
            for (int d = 0; d < 64; ++d) {
                float4 w = *reinterpret_cast<const float4*>(&sm[offW + d * 128 + da0]);
                #pragma unroll
                for (int ei = 0; ei < 4; ++ei) {
                    float x = sm[OFF_ENTT + d * 17 + e0 + ei];
                    acc[ei][0] = fmaf(x, w.x, acc[ei][0]);
                    acc[ei][1] = fmaf(x, w.y, acc[ei][1]);
                    acc[ei][2] = fmaf(x, w.z, acc[ei][2]);
                    acc[ei][3] = fmaf(x, w.w, acc[ei][3]);
                }
            }
            const float sc = half ? 1.0f : 0.08838834764831845f;  // 1/sqrt(128)
            #pragma unroll
            for (int ei = 0; ei < 4; ++ei) {
                float4 v = make_float4(acc[ei][0] * sc, acc[ei][1] * sc,
                                       acc[ei][2] * sc, acc[ei][3] * sc);
                *reinterpret_cast<float4*>(&sm[offD + (e0 + ei) * 132 + da0]) = v;
            }
        }
        __syncthreads();

        // ---- Phase D: energy[i][j] = q_i . k_j (2x2 tiles, 64 threads) ----
        if (tid < 64) {
            int i0 = (tid >> 3) << 1;
            int j0 = (tid & 7) << 1;
            float e00 = 0.f, e01 = 0.f, e10 = 0.f, e11 = 0.f;
            #pragma unroll 8
            for (int da = 0; da < 128; da += 4) {
                float4 qa = *reinterpret_cast<const float4*>(&sm[OFF_Q + i0 * 132 + da]);
                float4 qb = *reinterpret_cast<const float4*>(&sm[OFF_Q + (i0 + 1) * 132 + da]);
                float4 ka = *reinterpret_cast<const float4*>(&sm[OFF_K + j0 * 132 + da]);
                float4 kb = *reinterpret_cast<const float4*>(&sm[OFF_K + (j0 + 1) * 132 + da]);
                e00 += qa.x * ka.x + qa.y * ka.y + qa.z * ka.z + qa.w * ka.w;
                e01 += qa.x * kb.x + qa.y * kb.y + qa.z * kb.z + qa.w * kb.w;
                e10 += qb.x * ka.x + qb.y * ka.y + qb.z * ka.z + qb.w * ka.w;
                e11 += qb.x * kb.x + qb.y * kb.y + qb.z * kb.z + qb.w * kb.w;
            }
            sm[OFF_E + i0 * 17 + j0]           = e00;
            sm[OFF_E + i0 * 17 + j0 + 1]       = e01;
            sm[OFF_E + (i0 + 1) * 17 + j0]     = e10;
            sm[OFF_E + (i0 + 1) * 17 + j0 + 1] = e11;
        }
        __syncthreads();

        // ---- softmax over i (query axis) per column j ----
        if (tid < 16) {
            int j = tid;
            float mx = -1e30f;
            #pragma unroll
            for (int i = 0; i < 16; ++i) mx = fmaxf(mx, sm[OFF_E + i * 17 + j]);
            float ssum = 0.f;
            #pragma unroll
            for (int i = 0; i < 16; ++i) {
                float ex = __expf(sm[OFF_E + i * 17 + j] - mx);
                sm[OFF_ATT + i * 17 + j] = ex;
                ssum += ex;
            }
            float inv = 1.0f / ssum;
            #pragma unroll
            for (int i = 0; i < 16; ++i) sm[OFF_ATT + i * 17 + j] *= inv;
        }
        __syncthreads();

        // ---- attn_mean over j ----
        if (tid < 16) {
            int i = tid;
            float s = 0.f;
            #pragma unroll
            for (int j = 0; j < 16; ++j) s += sm[OFF_ATT + i * 17 + j];
            sm[OFF_AMEAN + i] = s * 0.0625f;
        }
        __syncthreads();

        // ---- attn_out[d] = sum_e ent[e][d] * attn_mean[e] ----
        if (tid < 64) {
            int d = tid;
            float s = 0.f;
            #pragma unroll
            for (int e = 0; e < 16; ++e)
                s = fmaf(sm[OFF_ENTT + d * 17 + e], sm[OFF_AMEAN + e], s);
            sm[OFF_AOUT + d] = s;
        }
        __syncthreads();

        // ---- hypernet w1 layer 1: h[a][hu], common attn_out part hoisted ----
        {
            int hu = tid & 63;
            int ag = tid >> 6;                   // agents ag and ag+4
            float c = sm[OFF_W1B1 + hu];
            #pragma unroll 8
            for (int f = 0; f < 64; ++f)
                c = fmaf(sm[OFF_AOUT + f], sm[OFF_W1A + f * 64 + hu], c);
            float a0 = c, a1 = c;
            #pragma unroll 8
            for (int f = 0; f < 64; ++f) {
                float w = sm[OFF_W1A + (64 + f) * 64 + hu];
                a0 = fmaf(sm[OFF_ENTT + f * 17 + ag],     w, a0);
                a1 = fmaf(sm[OFF_ENTT + f * 17 + ag + 4], w, a1);
            }
            sm[OFF_SH + ag * 64 + hu]       = fmaxf(a0, 0.f);
            sm[OFF_SH + (ag + 4) * 64 + hu] = fmaxf(a1, 0.f);
        }
        __syncthreads();

        // ---- hypernet w1 layer 2: w1[a][m] = |h[a] @ W2 + b2| ----
        {
            int m = tid & 31;
            int a = tid >> 5;                    // 0..7
            float acc = sm[OFF_W1B2 + m];
            #pragma unroll 8
            for (int k = 0; k < 64; ++k)
                acc = fmaf(sm[OFF_SH + a * 64 + k], sm[OFF_W1B + k * 32 + m], acc);
            sm[OFF_W1O + a * 32 + m] = fabsf(acc);
        }
        __syncthreads();

        // ---- parallel small heads: hidden | wf-l1 | v-l1 ----
        if (tid < 32) {
            int m = tid;
            float b1v = sm[OFF_HBB + m];
            #pragma unroll 8
            for (int d = 0; d < 64; ++d)
                b1v = fmaf(sm[OFF_AOUT + d], sm[OFF_HBW + d * 32 + m], b1v);
            float hv = b1v;
            #pragma unroll
            for (int a = 0; a < 8; ++a)
                hv = fmaf(sm[OFF_AQ + a], sm[OFF_W1O + a * 32 + m], hv);
            hv = hv > 0.f ? hv : expm1f(hv);     // ELU
            sm[OFF_HID + m] = hv;
        } else if (tid < 96) {
            int hu = tid - 32;
            float acc = sm[OFF_WFB1 + hu];
            #pragma unroll 8
            for (int d = 0; d < 64; ++d)
                acc = fmaf(sm[OFF_AOUT + d], sm[OFF_WFA + d * 64 + hu], acc);
            sm[OFF_H2 + hu] = fmaxf(acc, 0.f);
        } else if (tid < 128) {
            int m = tid - 96;
            float acc = sm[OFF_VB1 + m];
            #pragma unroll 8
            for (int d = 0; d < 64; ++d)
                acc = fmaf(sm[OFF_AOUT + d], sm[OFF_VW1 + d * 32 + m], acc);
            sm[OFF_H3 + m] = fmaxf(acc, 0.f);
        }
        __syncthreads();

        // ---- final: q_tot = <hidden, wf> + v ----
        if (tid < 32) {
            int m = tid;
            float wfv = sm[OFF_WFB2 + m];
            #pragma unroll 8
            for (int k = 0; k < 64; ++k)
                wfv = fmaf(sm[OFF_H2 + k], sm[OFF_WFB + k * 32 + m], wfv);
            wfv = fabsf(wfv);
            float part = sm[OFF_HID + m] * wfv + sm[OFF_H3 + m] * sm[OFF_VW2 + m];
            #pragma unroll
            for (int off = 16; off > 0; off >>= 1)
                part += __shfl_down_sync(0xffffffffu, part, off);
            if (m == 0) out[gp] = part + sm[OFF_VB2];
        }
        __syncthreads();   // protect s_aq/feat before next pair's Phase A
    }
}

extern "C" void kernel_launch(void* const* d_in, const int* in_sizes, int n_in,
                              void* d_out, int out_size) {
    (void)in_sizes; (void)n_in; (void)out_size;
    cudaFuncSetAttribute(qmixer_kernel,
                         cudaFuncAttributeMaxDynamicSharedMemorySize, SMEM_BYTES);
    qmixer_kernel<<<GRID, NTH, SMEM_BYTES>>>(
        (const float*)d_in[0],  (const float*)d_in[1],  (const float*)d_in[2],
        (const float*)d_in[3],  (const float*)d_in[4],
        (const float*)d_in[5],  (const float*)d_in[6],
        (const float*)d_in[7],  (const float*)d_in[8],
        (const float*)d_in[9],  (const float*)d_in[10],
        (const float*)d_in[11], (const float*)d_in[12],
        (const float*)d_in[13], (const float*)d_in[14],
        (const float*)d_in[15], (const float*)d_in[16],
        (const float*)d_in[17], (const float*)d_in[18],
        (const float*)d_in[19], (const float*)d_in[20],
        (const float*)d_in[21], (const float*)d_in[22],
        (const float*)d_in[23], (const float*)d_in[24],
        (float*)d_out);
}

// round 2
// speedup vs baseline: 1.2754x; 1.2754x over previous
#include <cuda_runtime.h>
#include <math.h>

// QMixer forward, fp32 + f32x2-packed FMA, weights staged in SMEM once per CTA,
// 512 threads = 2 independent 256-thread groups, 4 pairs each (NPAIR=8/CTA).
// B=128 S=128 A=8 En=8 E=16 NFal=32 NFen=16 D=64 Da=128 M=32 H=64

namespace {

constexpr int NTH    = 512;
constexpr int NPAIR  = 8;               // per CTA
constexpr int PPG    = 4;               // pairs per group
constexpr int BSTOT  = 16384;           // B*S
constexpr int GRID   = BSTOT / NPAIR;   // 2048

// ---- weight region (shared by both groups), float offsets ----
constexpr int OFF_WAL  = 0;                       // 32*64
constexpr int OFF_WEN  = OFF_WAL  + 32 * 64;      // 16*64
constexpr int OFF_WQ   = OFF_WEN  + 16 * 64;      // 64*128
constexpr int OFF_WK   = OFF_WQ   + 64 * 128;     // 64*128
constexpr int OFF_W1A  = OFF_WK   + 64 * 128;     // 128*64
constexpr int OFF_W1B  = OFF_W1A  + 128 * 64;     // 64*32
constexpr int OFF_WFA  = OFF_W1B  + 64 * 32;      // 64*64
constexpr int OFF_WFB  = OFF_WFA  + 64 * 64;      // 64*32
constexpr int OFF_HBW  = OFF_WFB  + 64 * 32;      // 64*32
constexpr int OFF_VW1  = OFF_HBW  + 64 * 32;      // 64*32
constexpr int OFF_VW2  = OFF_VW1  + 64 * 32;      // 32
constexpr int OFF_BAL  = OFF_VW2  + 32;           // 64
constexpr int OFF_BEN  = OFF_BAL  + 64;           // 64
constexpr int OFF_BQ   = OFF_BEN  + 64;           // 128
constexpr int OFF_BK   = OFF_BQ   + 128;          // 128
constexpr int OFF_W1B1 = OFF_BK   + 128;          // 64
constexpr int OFF_W1B2 = OFF_W1B1 + 64;           // 32
constexpr int OFF_WFB1 = OFF_W1B2 + 32;           // 64
constexpr int OFF_WFB2 = OFF_WFB1 + 64;           // 32
constexpr int OFF_HBB  = OFF_WFB2 + 32;           // 32
constexpr int OFF_VB1  = OFF_HBB  + 32;           // 32
constexpr int OFF_VB2  = OFF_VB1  + 32;           // 4 (1 used)
constexpr int W_TOT    = OFF_VB2  + 4;            // 40612
constexpr int W_TOT_AL = (W_TOT + 15) & ~15;      // 40624

// ---- per-group scratch (relative offsets) ----
constexpr int S_FEAT  = 0;              // 16*32
constexpr int S_AQ    = 512;            // 8
constexpr int S_ENTT  = 520;            // 64*20 (entT[d][e], pad 20, float4-aligned)
constexpr int S_Q     = S_ENTT + 64*20; // 16*132
constexpr int S_K     = S_Q    + 16*132;// 16*132
constexpr int S_E     = S_K    + 16*132;// 16*17 (reused in-place for attn)
constexpr int S_AMEAN = S_E    + 16*17; // 16
constexpr int S_AOUT  = S_AMEAN + 16;   // 64
constexpr int S_SH    = S_AOUT + 64;    // 8*64
constexpr int S_W1O   = S_SH   + 8*64;  // 8*32
constexpr int S_HID   = S_W1O  + 8*32;  // 32
constexpr int S_H2    = S_HID  + 32;    // 64
constexpr int S_H3    = S_H2   + 64;    // 32
constexpr int SCR_SZ  = ((S_H3 + 32 + 15) & ~15); // per-group scratch floats

constexpr int SMEM_FLOATS = W_TOT_AL + 2 * SCR_SZ;
constexpr int SMEM_BYTES  = SMEM_FLOATS * 4;      // ~215.7 KB

static_assert(SMEM_BYTES <= 232448, "smem over 227KB limit");
static_assert((S_ENTT & 3) == 0 && (S_Q & 3) == 0 && (S_K & 3) == 0, "align");

typedef unsigned long long ull;

__device__ __forceinline__ ull pk(float a, float b) {
    ull r; asm("mov.b64 %0,{%1,%2};" : "=l"(r) : "f"(a), "f"(b)); return r;
}
__device__ __forceinline__ void fma2(ull& acc, ull a, ull b) {
    asm("fma.rn.f32x2 %0,%1,%2,%0;" : "+l"(acc) : "l"(a), "l"(b));
}
__device__ __forceinline__ float2 unpk(ull v) {
    float2 f; asm("mov.b64 {%0,%1},%2;" : "=f"(f.x), "=f"(f.y) : "l"(v)); return f;
}

} // namespace

__global__ void __launch_bounds__(NTH, 1) qmixer_kernel(
    const float* __restrict__ g_aq,     // agent_qs  [B,S,8]
    const float* __restrict__ g_ally,   // [8,B,S,32]
    const float* __restrict__ g_enemy,  // [8,B,S,16]
    const float* __restrict__ g_Wal,  const float* __restrict__ g_bal,
    const float* __restrict__ g_Wen,  const float* __restrict__ g_ben,
    const float* __restrict__ g_Wq,   const float* __restrict__ g_bq,
    const float* __restrict__ g_Wk,   const float* __restrict__ g_bk,
    const float* __restrict__ g_w1W1, const float* __restrict__ g_w1b1,
    const float* __restrict__ g_w1W2, const float* __restrict__ g_w1b2,
    const float* __restrict__ g_wfW1, const float* __restrict__ g_wfb1,
    const float* __restrict__ g_wfW2, const float* __restrict__ g_wfb2,
    const float* __restrict__ g_hbW,  const float* __restrict__ g_hbb,
    const float* __restrict__ g_vW1,  const float* __restrict__ g_vb1,
    const float* __restrict__ g_vW2,  const float* __restrict__ g_vb2,
    float* __restrict__ out)
{
    extern __shared__ float sm[];
    const int tid = threadIdx.x;
    const int g   = tid >> 8;            // group 0/1
    const int t   = tid & 255;           // lane within group
    const int sg  = W_TOT_AL + g * SCR_SZ;
    const int gbar = g + 1;              // named barrier id per group

    // ---- stage all weights/biases in SMEM (once per CTA, all 512 threads) ----
    {
        auto cp = [&](int off, const float* src, int n) {
            for (int i = tid; i < n; i += NTH) sm[off + i] = src[i];
        };
        cp(OFF_WAL,  g_Wal,  32 * 64);
        cp(OFF_WEN,  g_Wen,  16 * 64);
        cp(OFF_WQ,   g_Wq,   64 * 128);
        cp(OFF_WK,   g_Wk,   64 * 128);
        cp(OFF_W1A,  g_w1W1, 128 * 64);
        cp(OFF_W1B,  g_w1W2, 64 * 32);
        cp(OFF_WFA,  g_wfW1, 64 * 64);
        cp(OFF_WFB,  g_wfW2, 64 * 32);
        cp(OFF_HBW,  g_hbW,  64 * 32);
        cp(OFF_VW1,  g_vW1,  64 * 32);
        cp(OFF_VW2,  g_vW2,  32);
        cp(OFF_BAL,  g_bal,  64);
        cp(OFF_BEN,  g_ben,  64);
        cp(OFF_BQ,   g_bq,   128);
        cp(OFF_BK,   g_bk,   128);
        cp(OFF_W1B1, g_w1b1, 64);
        cp(OFF_W1B2, g_w1b2, 32);
        cp(OFF_WFB1, g_wfb1, 64);
        cp(OFF_WFB2, g_wfb2, 32);
        cp(OFF_HBB,  g_hbb,  32);
        cp(OFF_VB1,  g_vb1,  32);
        if (tid == 0) sm[OFF_VB2] = g_vb2[0];
    }
    __syncthreads();

    #define GBAR() asm volatile("bar.sync %0, 256;" :: "r"(gbar) : "memory")

    for (int p = 0; p < PPG; ++p) {
        const int gp = blockIdx.x * NPAIR + g * PPG + p;   // b*128 + s

        // ---- Phase A: per-pair inputs ----
        {
            int e = t >> 5, f = t & 31;
            sm[sg + S_FEAT + e * 32 + f] = g_ally[(e * BSTOT + gp) * 32 + f];
            if (t < 128) {
                int ee = t >> 4, ff = t & 15;
                sm[sg + S_FEAT + (8 + ee) * 32 + ff] = g_enemy[(ee * BSTOT + gp) * 16 + ff];
            }
            if (t < 8) sm[sg + S_AQ + t] = g_aq[gp * 8 + t];
        }
        GBAR();

        // ---- Phase B: entity embeddings -> entT[d][e] (stride 20) ----
        {
            int d  = t & 63;
            int eg = t >> 6;                   // 0..3
            float aa0 = sm[OFF_BAL + d], aa1 = aa0;
            float ee0 = sm[OFF_BEN + d], ee1 = ee0;
            const float* f0 = &sm[sg + S_FEAT + eg * 32];
            const float* f1 = &sm[sg + S_FEAT + (eg + 4) * 32];
            const float* f2 = &sm[sg + S_FEAT + (eg + 8) * 32];
            const float* f3 = &sm[sg + S_FEAT + (eg + 12) * 32];
            #pragma unroll 8
            for (int f = 0; f < 32; ++f) {
                float w = sm[OFF_WAL + f * 64 + d];
                aa0 = fmaf(f0[f], w, aa0);
                aa1 = fmaf(f1[f], w, aa1);
            }
            #pragma unroll 8
            for (int f = 0; f < 16; ++f) {
                float w = sm[OFF_WEN + f * 64 + d];
                ee0 = fmaf(f2[f], w, ee0);
                ee1 = fmaf(f3[f], w, ee1);
            }
            float* er = &sm[sg + S_ENTT + d * 20];
            er[eg]      = aa0;
            er[eg + 4]  = aa1;
            er[eg + 8]  = ee0;
            er[eg + 12] = ee1;
        }
        GBAR();

        // ---- Phase C: Q/K projections, f32x2-packed 4e x 4da tiles ----
        {
            int half = t >> 7;                 // 0 -> q, 1 -> k
            int t2   = t & 127;
            int da0  = (t2 & 31) << 2;
            int e0   = (t2 >> 5) << 2;
            const float* Wb = &sm[(half ? OFF_WK : OFF_WQ) + da0];
            const float* Bb = &sm[(half ? OFF_BK : OFF_BQ) + da0];
            float*       Db = &sm[sg + (half ? S_K : S_Q)];
            const float* X  = &sm[sg + S_ENTT + e0];

            ull acc[2][4];                     // [ei-pair][di]
            #pragma unroll
            for (int di = 0; di < 4; ++di) {
                float b = Bb[di];
                ull pb = pk(b, b);
                acc[0][di] = pb; acc[1][di] = pb;
            }
            #pragma unroll 4
            for (int d = 0; d < 64; ++d) {
                float4 w = *reinterpret_cast<const float4*>(Wb + d * 128);
                float4 x = *reinterpret_cast<const float4*>(X + d * 20);
                ull x01 = pk(x.x, x.y), x23 = pk(x.z, x.w);
                ull w0 = pk(w.x, w.x), w1 = pk(w.y, w.y);
                ull w2 = pk(w.z, w.z), w3 = pk(w.w, w.w);
                fma2(acc[0][0], x01, w0); fma2(acc[1][0], x23, w0);
                fma2(acc[0][1], x01, w1); fma2(acc[1][1], x23, w1);
                fma2(acc[0][2], x01, w2); fma2(acc[1][2], x23, w2);
                fma2(acc[0][3], x01, w3); fma2(acc[1][3], x23, w3);
            }
            const float sc = half ? 1.0f : 0.08838834764831845f;  // 1/sqrt(128)
            #pragma unroll
            for (int j = 0; j < 2; ++j) {
                float2 v0 = unpk(acc[j][0]), v1 = unpk(acc[j][1]);
                float2 v2 = unpk(acc[j][2]), v3 = unpk(acc[j][3]);
                *reinterpret_cast<float4*>(&Db[(e0 + 2*j)     * 132 + da0]) =
                    make_float4(v0.x * sc, v1.x * sc, v2.x * sc, v3.x * sc);
                *reinterpret_cast<float4*>(&Db[(e0 + 2*j + 1) * 132 + da0]) =
                    make_float4(v0.y * sc, v1.y * sc, v2.y * sc, v3.y * sc);
            }
        }
        GBAR();

        // ---- Phase D: energy[i][j] = q_i . k_j (2x2 tiles, 64 threads) ----
        if (t < 64) {
            int i0 = (t >> 3) << 1;
            int j0 = (t & 7) << 1;
            const float* Q = &sm[sg + S_Q];
            const float* K = &sm[sg + S_K];
            float e00 = 0.f, e01 = 0.f, e10 = 0.f, e11 = 0.f;
            #pragma unroll 8
            for (int da = 0; da < 128; da += 4) {
                float4 qa = *reinterpret_cast<const float4*>(&Q[i0 * 132 + da]);
                float4 qb = *reinterpret_cast<const float4*>(&Q[(i0 + 1) * 132 + da]);
                float4 ka = *reinterpret_cast<const float4*>(&K[j0 * 132 + da]);
                float4 kb = *reinterpret_cast<const float4*>(&K[(j0 + 1) * 132 + da]);
                e00 += qa.x * ka.x + qa.y * ka.y + qa.z * ka.z + qa.w * ka.w;
                e01 += qa.x * kb.x + qa.y * kb.y + qa.z * kb.z + qa.w * kb.w;
                e10 += qb.x * ka.x + qb.y * ka.y + qb.z * ka.z + qb.w * ka.w;
                e11 += qb.x * kb.x + qb.y * kb.y + qb.z * kb.z + qb.w * kb.w;
            }
            float* E = &sm[sg + S_E];
            E[i0 * 17 + j0]           = e00;
            E[i0 * 17 + j0 + 1]       = e01;
            E[(i0 + 1) * 17 + j0]     = e10;
            E[(i0 + 1) * 17 + j0 + 1] = e11;
        }
        GBAR();

        // ---- softmax over query axis i per column j (in place) ----
        if (t < 16) {
            int j = t;
            float* E = &sm[sg + S_E];
            float mx = -1e30f;
            #pragma unroll
            for (int i = 0; i < 16; ++i) mx = fmaxf(mx, E[i * 17 + j]);
            float ssum = 0.f;
            #pragma unroll
            for (int i = 0; i < 16; ++i) {
                float ex = __expf(E[i * 17 + j] - mx);
                E[i * 17 + j] = ex;
                ssum += ex;
            }
            float inv = 1.0f / ssum;
            #pragma unroll
            for (int i = 0; i < 16; ++i) E[i * 17 + j] *= inv;
        }
        GBAR();

        // ---- attn_mean over j ----
        if (t < 16) {
            int i = t;
            const float* E = &sm[sg + S_E];
            float s = 0.f;
            #pragma unroll
            for (int j = 0; j < 16; ++j) s += E[i * 17 + j];
            sm[sg + S_AMEAN + i] = s * 0.0625f;
        }
        GBAR();

        // ---- attn_out[d] = sum_e ent[e][d] * attn_mean[e] ----
        if (t < 64) {
            int d = t;
            float s = 0.f;
            #pragma unroll
            for (int e = 0; e < 16; ++e)
                s = fmaf(sm[sg + S_ENTT + d * 20 + e], sm[sg + S_AMEAN + e], s);
            sm[sg + S_AOUT + d] = s;
        }
        GBAR();

        // ---- hypernet w1 layer 1 (common attn_out partial hoisted) ----
        {
            int hu = t & 63;
            int ag = t >> 6;                   // agents ag and ag+4
            float c = sm[OFF_W1B1 + hu];
            #pragma unroll 8
            for (int f = 0; f < 64; ++f)
                c = fmaf(sm[sg + S_AOUT + f], sm[OFF_W1A + f * 64 + hu], c);
            float a0 = c, a1 = c;
            #pragma unroll 8
            for (int f = 0; f < 64; ++f) {
                float w = sm[OFF_W1A + (64 + f) * 64 + hu];
                a0 = fmaf(sm[sg + S_ENTT + f * 20 + ag],     w, a0);
                a1 = fmaf(sm[sg + S_ENTT + f * 20 + ag + 4], w, a1);
            }
            sm[sg + S_SH + ag * 64 + hu]       = fmaxf(a0, 0.f);
            sm[sg + S_SH + (ag + 4) * 64 + hu] = fmaxf(a1, 0.f);
        }
        GBAR();

        // ---- hypernet w1 layer 2: w1[a][m] = |h[a] @ W2 + b2| ----
        {
            int m = t & 31;
            int a = t >> 5;                    // 0..7
            float acc = sm[OFF_W1B2 + m];
            #pragma unroll 8
            for (int k = 0; k < 64; ++k)
                acc = fmaf(sm[sg + S_SH + a * 64 + k], sm[OFF_W1B + k * 32 + m], acc);
            sm[sg + S_W1O + a * 32 + m] = fabsf(acc);
        }
        GBAR();

        // ---- parallel small heads: hidden | wf-l1 | v-l1 ----
        if (t < 32) {
            int m = t;
            float b1v = sm[OFF_HBB + m];
            #pragma unroll 8
            for (int d = 0; d < 64; ++d)
                b1v = fmaf(sm[sg + S_AOUT + d], sm[OFF_HBW + d * 32 + m], b1v);
            float hv = b1v;
            #pragma unroll
            for (int a = 0; a < 8; ++a)
                hv = fmaf(sm[sg + S_AQ + a], sm[sg + S_W1O + a * 32 + m], hv);
            hv = hv > 0.f ? hv : expm1f(hv);     // ELU
            sm[sg + S_HID + m] = hv;
        } else if (t < 96) {
            int hu = t - 32;
            float acc = sm[OFF_WFB1 + hu];
            #pragma unroll 8
            for (int d = 0; d < 64; ++d)
                acc = fmaf(sm[sg + S_AOUT + d], sm[OFF_WFA + d * 64 + hu], acc);
            sm[sg + S_H2 + hu] = fmaxf(acc, 0.f);
        } else if (t < 128) {
            int m = t - 96;
            float acc = sm[OFF_VB1 + m];
            #pragma unroll 8
            for (int d = 0; d < 64; ++d)
                acc = fmaf(sm[sg + S_AOUT + d], sm[OFF_VW1 + d * 32 + m], acc);
            sm[sg + S_H3 + m] = fmaxf(acc, 0.f);
        }
        GBAR();

        // ---- final: q_tot = <hidden, wf> + v ----
        if (t < 32) {
            int m = t;
            float wfv = sm[OFF_WFB2 + m];
            #pragma unroll 8
            for (int k = 0; k < 64; ++k)
                wfv = fmaf(sm[sg + S_H2 + k], sm[OFF_WFB + k * 32 + m], wfv);
            wfv = fabsf(wfv);
            float part = sm[sg + S_HID + m] * wfv + sm[sg + S_H3 + m] * sm[OFF_VW2 + m];
            #pragma unroll
            for (int off = 16; off > 0; off >>= 1)
                part += __shfl_down_sync(0xffffffffu, part, off);
            if (m == 0) out[gp] = part + sm[OFF_VB2];
        }
        GBAR();   // protect scratch before next pair's Phase A
    }
    #undef GBAR
}

extern "C" void kernel_launch(void* const* d_in, const int* in_sizes, int n_in,
                              void* d_out, int out_size) {
    (void)in_sizes; (void)n_in; (void)out_size;
    cudaFuncSetAttribute(qmixer_kernel,
                         cudaFuncAttributeMaxDynamicSharedMemorySize, SMEM_BYTES);
    qmixer_kernel<<<GRID, NTH, SMEM_BYTES>>>(
        (const float*)d_in[0],  (const float*)d_in[1],  (const float*)d_in[2],
        (const float*)d_in[3],  (const float*)d_in[4],
        (const float*)d_in[5],  (const float*)d_in[6],
        (const float*)d_in[7],  (const float*)d_in[8],
        (const float*)d_in[9],  (const float*)d_in[10],
        (const float*)d_in[11], (const float*)d_in[12],
        (const float*)d_in[13], (const float*)d_in[14],
        (const float*)d_in[15], (const float*)d_in[16],
        (const float*)d_in[17], (const float*)d_in[18],
        (const float*)d_in[19], (const float*)d_in[20],
        (const float*)d_in[21], (const float*)d_in[22],
        (const float*)d_in[23], (const float*)d_in[24],
        (float*)d_out);
}

// round 3
// speedup vs baseline: 3.3706x; 2.6427x over previous
#include <cuda_runtime.h>
#include <math.h>

// QMixer forward on GB300.
// Precompute kernel: M = Wq*Wk^T/sqrt(Da), u = Wq*bk/sqrt(Da)  (softmax over the
// query axis cancels all E-terms constant in i, so bq-side terms vanish).
// Main kernel: 2048 CTAs x 512 thr = 2 groups x 256; each group batches its 4
// (b,s) pairs through all phases at once. All weights + M staged in SMEM.
// B=128 S=128 A=8 E=16 NFal=32 NFen=16 D=64 M=32 H=64

namespace {

constexpr int NTH   = 512;
constexpr int BSTOT = 16384;
constexpr int GRID  = BSTOT / 8;   // 8 pairs per CTA

// ---- weight region (shared), float offsets ----
constexpr int OFF_WAL  = 0;        // 32*64
constexpr int OFF_WEN  = 2048;     // 16*64
constexpr int OFF_M    = 3072;     // 64*64
constexpr int OFF_U    = 7168;     // 64
constexpr int OFF_W1A  = 7232;     // 128*64
constexpr int OFF_W1B  = 15424;    // 64*32
constexpr int OFF_WFA  = 17472;    // 64*64
constexpr int OFF_WFB  = 21568;    // 64*32
constexpr int OFF_HBW  = 23616;    // 64*32
constexpr int OFF_VW1  = 25664;    // 64*32
constexpr int OFF_VW2  = 27712;    // 32
constexpr int OFF_BAL  = 27744;    // 64
constexpr int OFF_BEN  = 27808;    // 64
constexpr int OFF_W1B1 = 27872;    // 64
constexpr int OFF_W1B2 = 27936;    // 32
constexpr int OFF_WFB1 = 27968;    // 64
constexpr int OFF_WFB2 = 28032;    // 32
constexpr int OFF_HBB  = 28064;    // 32
constexpr int OFF_VB1  = 28096;    // 32
constexpr int OFF_VB2  = 28128;    // 1
constexpr int W_TOT_AL = 28144;

// ---- per-group scratch (relative float offsets) ----
// Union region S_U1 (4352): FEAT[p*512+e*32+f] during A/B;
// Zt[p*1088+c*17+e] during Z/E; then SH/W1O/HID/H2/H3.
constexpr int S_U1    = 0;
constexpr int S_FEAT  = S_U1;            // 2048
constexpr int S_ZT    = S_U1;            // 4352
constexpr int S_SH    = S_U1;            // 2048  [p*512+a*64+hu]
constexpr int S_W1O   = S_U1 + 2048;     // 1024  [p*256+a*32+m]
constexpr int S_HID   = S_U1 + 3072;     // 128   [p*32+m]
constexpr int S_H2    = S_U1 + 3200;     // 256   [p*64+r]
constexpr int S_H3    = S_U1 + 3456;     // 128   [p*32+m]
constexpr int S_AQ    = 4352;            // 32    [p*8+a]
constexpr int S_ENTT  = 4384;            // 5120  [p*1280+d*20+e]
constexpr int S_XU    = 9504;            // 64    [p*16+e]
constexpr int S_EM    = 9568;            // 1088  [p*272+i*17+j]; later AOUT [p*64+d]
constexpr int S_AOUT  = S_EM;
constexpr int S_AMEAN = 10656;           // 64    [p*16+e]
constexpr int SCR_SZ  = 10736;

constexpr int SMEM_FLOATS = W_TOT_AL + 2 * SCR_SZ;
constexpr int SMEM_BYTES  = SMEM_FLOATS * 4;     // 198464 B
static_assert(SMEM_BYTES <= 227 * 1024, "smem");

constexpr float INVS = 0.08838834764831845f;     // 1/sqrt(128)

typedef unsigned long long ull;
__device__ __forceinline__ ull pk(float a, float b) {
    ull r; asm("mov.b64 %0,{%1,%2};" : "=l"(r) : "f"(a), "f"(b)); return r;
}
__device__ __forceinline__ void fma2(ull& acc, ull a, ull b) {
    asm("fma.rn.f32x2 %0,%1,%2,%0;" : "+l"(acc) : "l"(a), "l"(b));
}
__device__ __forceinline__ float2 unpk(ull v) {
    float2 f; asm("mov.b64 {%0,%1},%2;" : "=f"(f.x), "=f"(f.y) : "l"(v)); return f;
}

__device__ float g_M[64 * 64];
__device__ float g_U[64];

} // namespace

// ---------------- precompute: M = Wq Wk^T * invs, u = Wq bk * invs -----------
__global__ void precompute_kernel(const float* __restrict__ Wq,
                                  const float* __restrict__ Wk,
                                  const float* __restrict__ bk) {
    int t = threadIdx.x;                 // 256
    int d = blockIdx.x * 4 + (t >> 6);   // 0..63
    int c = t & 63;
    float s = 0.f;
    #pragma unroll 8
    for (int k = 0; k < 128; ++k)
        s = fmaf(Wq[d * 128 + k], Wk[c * 128 + k], s);
    g_M[d * 64 + c] = s * INVS;
    if (blockIdx.x == 0 && t < 64) {
        float su = 0.f;
        #pragma unroll 8
        for (int k = 0; k < 128; ++k)
            su = fmaf(Wq[t * 128 + k], bk[k], su);
        g_U[t] = su * INVS;
    }
}

// ---------------- main kernel ----------------
__global__ void __launch_bounds__(NTH, 1) qmixer_kernel(
    const float* __restrict__ g_aq,     // [B,S,8]
    const float* __restrict__ g_ally,   // [8,B,S,32]
    const float* __restrict__ g_enemy,  // [8,B,S,16]
    const float* __restrict__ g_Wal,  const float* __restrict__ g_bal,
    const float* __restrict__ g_Wen,  const float* __restrict__ g_ben,
    const float* __restrict__ g_w1W1, const float* __restrict__ g_w1b1,
    const float* __restrict__ g_w1W2, const float* __restrict__ g_w1b2,
    const float* __restrict__ g_wfW1, const float* __restrict__ g_wfb1,
    const float* __restrict__ g_wfW2, const float* __restrict__ g_wfb2,
    const float* __restrict__ g_hbW,  const float* __restrict__ g_hbb,
    const float* __restrict__ g_vW1,  const float* __restrict__ g_vb1,
    const float* __restrict__ g_vW2,  const float* __restrict__ g_vb2,
    float* __restrict__ out)
{
    extern __shared__ float sm[];
    const int tid = threadIdx.x;
    const int g   = tid >> 8;
    const int t   = tid & 255;
    const int sg  = W_TOT_AL + g * SCR_SZ;
    const int gbar = g + 1;
    const int gp0 = blockIdx.x * 8 + g * 4;

    // ---- stage weights (float4 where possible) ----
    {
        auto cp4 = [&](int off, const float* src, int n) {
            const float4* s4 = reinterpret_cast<const float4*>(src);
            float4* d4 = reinterpret_cast<float4*>(&sm[off]);
            for (int i = tid; i < n / 4; i += NTH) d4[i] = s4[i];
        };
        cp4(OFF_WAL,  g_Wal,  2048);
        cp4(OFF_WEN,  g_Wen,  1024);
        cp4(OFF_M,    g_M,    4096);
        cp4(OFF_U,    g_U,    64);
        cp4(OFF_W1A,  g_w1W1, 8192);
        cp4(OFF_W1B,  g_w1W2, 2048);
        cp4(OFF_WFA,  g_wfW1, 4096);
        cp4(OFF_WFB,  g_wfW2, 2048);
        cp4(OFF_HBW,  g_hbW,  2048);
        cp4(OFF_VW1,  g_vW1,  2048);
        cp4(OFF_VW2,  g_vW2,  32);
        cp4(OFF_BAL,  g_bal,  64);
        cp4(OFF_BEN,  g_ben,  64);
        cp4(OFF_W1B1, g_w1b1, 64);
        cp4(OFF_W1B2, g_w1b2, 32);
        cp4(OFF_WFB1, g_wfb1, 64);
        cp4(OFF_WFB2, g_wfb2, 32);
        cp4(OFF_HBB,  g_hbb,  32);
        cp4(OFF_VB1,  g_vb1,  32);
        if (tid == 0) sm[OFF_VB2] = g_vb2[0];
    }
    __syncthreads();

    #define GBAR() asm volatile("bar.sync %0, 256;" :: "r"(gbar) : "memory")

    // ================= Phase A: load 4 pairs' inputs =================
    {
        // ally: 4p x 8e x 8 float4
        int p = t >> 6, e = (t >> 3) & 7, f4 = t & 7;
        reinterpret_cast<float4*>(&sm[sg + S_FEAT + p * 512 + e * 32])[f4] =
            reinterpret_cast<const float4*>(&g_ally[(e * BSTOT + gp0 + p) * 32])[f4];
        if (t < 128) {  // enemy: 4p x 8e x 4 float4
            int pp = t >> 5, ee = (t >> 2) & 7, ff4 = t & 3;
            reinterpret_cast<float4*>(&sm[sg + S_FEAT + pp * 512 + (8 + ee) * 32])[ff4] =
                reinterpret_cast<const float4*>(&g_enemy[(ee * BSTOT + gp0 + pp) * 16])[ff4];
        }
        if (t < 32) {
            int pp = t >> 3, a = t & 7;
            sm[sg + S_AQ + pp * 8 + a] = g_aq[(gp0 + pp) * 8 + a];
        }
    }
    GBAR();

    // ================= Phase B: embeddings -> ENTT[p][d*20+e] =================
    {
        int p = t >> 6, d = t & 63;
        float acc[16];
        float ba = sm[OFF_BAL + d], be = sm[OFF_BEN + d];
        #pragma unroll
        for (int e = 0; e < 8; ++e) { acc[e] = ba; acc[8 + e] = be; }
        const float* FEAT = &sm[sg + S_FEAT + p * 512];
        #pragma unroll
        for (int f4 = 0; f4 < 8; ++f4) {
            int f = f4 * 4;
            float w0 = sm[OFF_WAL + f * 64 + d];
            float w1 = sm[OFF_WAL + (f + 1) * 64 + d];
            float w2 = sm[OFF_WAL + (f + 2) * 64 + d];
            float w3 = sm[OFF_WAL + (f + 3) * 64 + d];
            #pragma unroll
            for (int e = 0; e < 8; ++e) {
                float4 x = *reinterpret_cast<const float4*>(&FEAT[e * 32 + f]);
                acc[e] = fmaf(x.x, w0, acc[e]);
                acc[e] = fmaf(x.y, w1, acc[e]);
                acc[e] = fmaf(x.z, w2, acc[e]);
                acc[e] = fmaf(x.w, w3, acc[e]);
            }
        }
        #pragma unroll
        for (int f4 = 0; f4 < 4; ++f4) {
            int f = f4 * 4;
            float w0 = sm[OFF_WEN + f * 64 + d];
            float w1 = sm[OFF_WEN + (f + 1) * 64 + d];
            float w2 = sm[OFF_WEN + (f + 2) * 64 + d];
            float w3 = sm[OFF_WEN + (f + 3) * 64 + d];
            #pragma unroll
            for (int e = 0; e < 8; ++e) {
                float4 x = *reinterpret_cast<const float4*>(&FEAT[(8 + e) * 32 + f]);
                acc[8+e] = fmaf(x.x, w0, acc[8+e]);
                acc[8+e] = fmaf(x.y, w1, acc[8+e]);
                acc[8+e] = fmaf(x.z, w2, acc[8+e]);
                acc[8+e] = fmaf(x.w, w3, acc[8+e]);
            }
        }
        float* er = &sm[sg + S_ENTT + p * 1280 + d * 20];
        #pragma unroll
        for (int e = 0; e < 16; ++e) er[e] = acc[e];
    }
    GBAR();

    // ================= Phase Z: Z = X^T M  -> Zt[p][c*17+e] =================
    {
        int p = t >> 6, r = t & 63;
        int e0 = (r >> 4) * 4, c0 = (r & 15) * 4;
        ull acc[4][2];  // [e][c-pair]
        #pragma unroll
        for (int e = 0; e < 4; ++e) { acc[e][0] = 0ull; acc[e][1] = 0ull; }
        const float* X = &sm[sg + S_ENTT + p * 1280 + e0];
        const float* M = &sm[OFF_M + c0];
        #pragma unroll 4
        for (int d = 0; d < 64; ++d) {
            float4 m4 = *reinterpret_cast<const float4*>(M + d * 64);
            float4 x4 = *reinterpret_cast<const float4*>(X + d * 20);
            ull mp0 = pk(m4.x, m4.y), mp1 = pk(m4.z, m4.w);
            ull xs0 = pk(x4.x, x4.x), xs1 = pk(x4.y, x4.y);
            ull xs2 = pk(x4.z, x4.z), xs3 = pk(x4.w, x4.w);
            fma2(acc[0][0], xs0, mp0); fma2(acc[0][1], xs0, mp1);
            fma2(acc[1][0], xs1, mp0); fma2(acc[1][1], xs1, mp1);
            fma2(acc[2][0], xs2, mp0); fma2(acc[2][1], xs2, mp1);
            fma2(acc[3][0], xs3, mp0); fma2(acc[3][1], xs3, mp1);
        }
        float* Zt = &sm[sg + S_ZT + p * 1088];
        #pragma unroll
        for (int e = 0; e < 4; ++e) {
            float2 v0 = unpk(acc[e][0]), v1 = unpk(acc[e][1]);
            Zt[(c0    ) * 17 + e0 + e] = v0.x;
            Zt[(c0 + 1) * 17 + e0 + e] = v0.y;
            Zt[(c0 + 2) * 17 + e0 + e] = v1.x;
            Zt[(c0 + 3) * 17 + e0 + e] = v1.y;
        }
    }
    GBAR();

    // ================= Phase E: E[i][j] = Z[i]·x_j ; spare threads: xu =======
    if (t < 128) {
        int p = t >> 5, q = t & 31;
        int i0 = (q >> 2) * 2, j0 = (q & 3) * 4;
        const float* Zt = &sm[sg + S_ZT + p * 1088];
        const float* X  = &sm[sg + S_ENTT + p * 1280 + j0];
        ull acc[2][2];
        acc[0][0] = acc[0][1] = acc[1][0] = acc[1][1] = 0ull;
        #pragma unroll 4
        for (int c = 0; c < 64; ++c) {
            float z0 = Zt[c * 17 + i0];
            float z1 = Zt[c * 17 + i0 + 1];
            float4 x4 = *reinterpret_cast<const float4*>(X + c * 20);
            ull xp0 = pk(x4.x, x4.y), xp1 = pk(x4.z, x4.w);
            ull zs0 = pk(z0, z0), zs1 = pk(z1, z1);
            fma2(acc[0][0], zs0, xp0); fma2(acc[0][1], zs0, xp1);
            fma2(acc[1][0], zs1, xp0); fma2(acc[1][1], zs1, xp1);
        }
        float* E = &sm[sg + S_EM + p * 272];
        #pragma unroll
        for (int ii = 0; ii < 2; ++ii) {
            float2 v0 = unpk(acc[ii][0]), v1 = unpk(acc[ii][1]);
            E[(i0 + ii) * 17 + j0]     = v0.x;
            E[(i0 + ii) * 17 + j0 + 1] = v0.y;
            E[(i0 + ii) * 17 + j0 + 2] = v1.x;
            E[(i0 + ii) * 17 + j0 + 3] = v1.y;
        }
    } else if (t < 192) {
        int idx = t - 128;
        int p = idx >> 4, e = idx & 15;
        const float* X = &sm[sg + S_ENTT + p * 1280 + e];
        float s = 0.f;
        #pragma unroll 8
        for (int d = 0; d < 64; ++d)
            s = fmaf(X[d * 20], sm[OFF_U + d], s);
        sm[sg + S_XU + p * 16 + e] = s;
    }
    GBAR();

    // ================= softmax over i (per column j) + amean ================
    if (t < 64) {
        int p = t >> 4, j = t & 15;
        float* E = &sm[sg + S_EM + p * 272];
        const float* XU = &sm[sg + S_XU + p * 16];
        float col[16];
        #pragma unroll
        for (int i = 0; i < 16; ++i) col[i] = E[i * 17 + j] + XU[i];
        float mx = col[0];
        #pragma unroll
        for (int i = 1; i < 16; ++i) mx = fmaxf(mx, col[i]);
        float ssum = 0.f;
        #pragma unroll
        for (int i = 0; i < 16; ++i) { col[i] = __expf(col[i] - mx); ssum += col[i]; }
        float inv = 1.0f / ssum;
        #pragma unroll
        for (int i = 0; i < 16; ++i) E[i * 17 + j] = col[i] * inv;
        __syncwarp();
        // amean: warp holds 2 complete pairs (lanes 0-15 pair a, 16-31 pair b)
        int i = j;          // reuse lane's low 4 bits as row index
        const float* Er = &sm[sg + S_EM + p * 272 + i * 17];
        float s = 0.f;
        #pragma unroll
        for (int jj = 0; jj < 16; ++jj) s += Er[jj];
        sm[sg + S_AMEAN + p * 16 + i] = s * 0.0625f;
    }
    GBAR();

    // ================= attn_out[p][d] (overlays E region) ==================
    {
        int p = t >> 6, d = t & 63;
        const float* X = &sm[sg + S_ENTT + p * 1280 + d * 20];
        const float* AM = &sm[sg + S_AMEAN + p * 16];
        float4 x0 = *reinterpret_cast<const float4*>(X);
        float4 x1 = *reinterpret_cast<const float4*>(X + 4);
        float4 x2 = *reinterpret_cast<const float4*>(X + 8);
        float4 x3 = *reinterpret_cast<const float4*>(X + 12);
        float4 a0 = *reinterpret_cast<const float4*>(AM);
        float4 a1 = *reinterpret_cast<const float4*>(AM + 4);
        float4 a2 = *reinterpret_cast<const float4*>(AM + 8);
        float4 a3 = *reinterpret_cast<const float4*>(AM + 12);
        float s = x0.x*a0.x + x0.y*a0.y + x0.z*a0.z + x0.w*a0.w
                + x1.x*a1.x + x1.y*a1.y + x1.z*a1.z + x1.w*a1.w
                + x2.x*a2.x + x2.y*a2.y + x2.z*a2.z + x2.w*a2.w
                + x3.x*a3.x + x3.y*a3.y + x3.z*a3.z + x3.w*a3.w;
        GBAR();                       // all E reads (none) / amean reads done; order vs overlay write
        sm[sg + S_AOUT + p * 64 + d] = s;
    }
    GBAR();

    // ================= hypernet w1 layer 1 -> SH[p][a*64+hu] ================
    {
        int p = t >> 6, hu = t & 63;
        const float* AO = &sm[sg + S_AOUT + p * 64];
        float c = sm[OFF_W1B1 + hu];
        #pragma unroll 8
        for (int f = 0; f < 64; ++f)
            c = fmaf(AO[f], sm[OFF_W1A + f * 64 + hu], c);
        ull acc[4];
        ull pc = pk(c, c);
        acc[0] = pc; acc[1] = pc; acc[2] = pc; acc[3] = pc;
        const float* X = &sm[sg + S_ENTT + p * 1280];
        #pragma unroll 4
        for (int f = 0; f < 64; ++f) {
            float w = sm[OFF_W1A + (64 + f) * 64 + hu];
            ull ws = pk(w, w);
            const ull* xr = reinterpret_cast<const ull*>(X + f * 20);
            fma2(acc[0], xr[0], ws);
            fma2(acc[1], xr[1], ws);
            fma2(acc[2], xr[2], ws);
            fma2(acc[3], xr[3], ws);
        }
        float* SH = &sm[sg + S_SH + p * 512];
        #pragma unroll
        for (int ap = 0; ap < 4; ++ap) {
            float2 v = unpk(acc[ap]);
            SH[(2 * ap) * 64 + hu]     = fmaxf(v.x, 0.f);
            SH[(2 * ap + 1) * 64 + hu] = fmaxf(v.y, 0.f);
        }
    }
    GBAR();

    // ================= w1 layer 2: W1O[p][a*32+m] = |SH@W2 + b2| ============
    {
        int p = t >> 6, r = t & 63;
        int a = r >> 3, m0 = (r & 7) * 4;
        ull acc0 = pk(sm[OFF_W1B2 + m0],     sm[OFF_W1B2 + m0 + 1]);
        ull acc1 = pk(sm[OFF_W1B2 + m0 + 2], sm[OFF_W1B2 + m0 + 3]);
        const float* SH = &sm[sg + S_SH + p * 512 + a * 64];
        const float* W = &sm[OFF_W1B + m0];
        #pragma unroll 4
        for (int k = 0; k < 64; ++k) {
            float4 w4 = *reinterpret_cast<const float4*>(W + k * 32);
            float shv = SH[k];
            ull ss = pk(shv, shv);
            fma2(acc0, ss, pk(w4.x, w4.y));
            fma2(acc1, ss, pk(w4.z, w4.w));
        }
        float2 v0 = unpk(acc0), v1 = unpk(acc1);
        *reinterpret_cast<float4*>(&sm[sg + S_W1O + p * 256 + a * 32 + m0]) =
            make_float4(fabsf(v0.x), fabsf(v0.y), fabsf(v1.x), fabsf(v1.y));
    }
    GBAR();

    // ================= heads: wf-l1 (all), hidden (r<32), v-l1 (r>=32) ======
    {
        int p = t >> 6, r = t & 63;
        const float* AO = &sm[sg + S_AOUT + p * 64];
        float accW = sm[OFF_WFB1 + r];
        #pragma unroll 8
        for (int f = 0; f < 64; ++f)
            accW = fmaf(AO[f], sm[OFF_WFA + f * 64 + r], accW);
        sm[sg + S_H2 + p * 64 + r] = fmaxf(accW, 0.f);
        if (r < 32) {
            int m = r;
            float bb = sm[OFF_HBB + m];
            #pragma unroll 8
            for (int d = 0; d < 64; ++d)
                bb = fmaf(AO[d], sm[OFF_HBW + d * 32 + m], bb);
            float hv = bb;
            const float* W1O = &sm[sg + S_W1O + p * 256];
            const float* AQ  = &sm[sg + S_AQ + p * 8];
            #pragma unroll
            for (int a = 0; a < 8; ++a)
                hv = fmaf(AQ[a], W1O[a * 32 + m], hv);
            sm[sg + S_HID + p * 32 + m] = hv > 0.f ? hv : expm1f(hv);
        } else {
            int m = r - 32;
            float av = sm[OFF_VB1 + m];
            #pragma unroll 8
            for (int d = 0; d < 64; ++d)
                av = fmaf(AO[d], sm[OFF_VW1 + d * 32 + m], av);
            sm[sg + S_H3 + p * 32 + m] = fmaxf(av, 0.f);
        }
    }
    GBAR();

    // ================= final: q_tot = <hidden, |wf|> + v ====================
    if (t < 128) {
        int p = t >> 5, m = t & 31;
        const float* H2 = &sm[sg + S_H2 + p * 64];
        float wf = sm[OFF_WFB2 + m];
        #pragma unroll 8
        for (int k = 0; k < 64; ++k)
            wf = fmaf(H2[k], sm[OFF_WFB + k * 32 + m], wf);
        wf = fabsf(wf);
        float part = sm[sg + S_HID + p * 32 + m] * wf
                   + sm[sg + S_H3 + p * 32 + m] * sm[OFF_VW2 + m];
        #pragma unroll
        for (int off = 16; off > 0; off >>= 1)
            part += __shfl_down_sync(0xffffffffu, part, off);
        if (m == 0) out[gp0 + p] = part + sm[OFF_VB2];
    }
    #undef GBAR
}

extern "C" void kernel_launch(void* const* d_in, const int* in_sizes, int n_in,
                              void* d_out, int out_size) {
    (void)in_sizes; (void)n_in; (void)out_size;
    // inputs: 0 aq, 1 ally, 2 enemy, 3 W_al, 4 b_al, 5 W_en, 6 b_en,
    // 7 Wq, 8 bq, 9 Wk, 10 bk, 11 w1_W1, 12 w1_b1, 13 w1_W2, 14 w1_b2,
    // 15 wf_W1, 16 wf_b1, 17 wf_W2, 18 wf_b2, 19 hb_W, 20 hb_b,
    // 21 v_W1, 22 v_b1, 23 v_W2, 24 v_b2
    precompute_kernel<<<16, 256>>>(
        (const float*)d_in[7], (const float*)d_in[9], (const float*)d_in[10]);
    cudaFuncSetAttribute(qmixer_kernel,
                         cudaFuncAttributeMaxDynamicSharedMemorySize, SMEM_BYTES);
    qmixer_kernel<<<GRID, NTH, SMEM_BYTES>>>(
        (const float*)d_in[0],  (const float*)d_in[1],  (const float*)d_in[2],
        (const float*)d_in[3],  (const float*)d_in[4],
        (const float*)d_in[5],  (const float*)d_in[6],
        (const float*)d_in[11], (const float*)d_in[12],
        (const float*)d_in[13], (const float*)d_in[14],
        (const float*)d_in[15], (const float*)d_in[16],
        (const float*)d_in[17], (const float*)d_in[18],
        (const float*)d_in[19], (const float*)d_in[20],
        (const float*)d_in[21], (const float*)d_in[22],
        (const float*)d_in[23], (const float*)d_in[24],
        (float*)d_out);
}

// round 4
// speedup vs baseline: 3.3728x; 1.0007x over previous
#include <cuda_runtime.h>
#include <math.h>

// QMixer forward on GB300.
// Precompute kernel: M = Wq*Wk^T/sqrt(Da), u = Wq*bk/sqrt(Da)  (softmax over the
// query axis cancels all E-terms constant in i, so bq-side terms vanish).
// Main kernel: 2048 CTAs x 512 thr = 2 groups x 256; each group batches its 4
// (b,s) pairs through all phases at once. All weights + M staged in SMEM.
// B=128 S=128 A=8 E=16 NFal=32 NFen=16 D=64 M=32 H=64

namespace {

constexpr int NTH   = 512;
constexpr int BSTOT = 16384;
constexpr int GRID  = BSTOT / 8;   // 8 pairs per CTA

// ---- weight region (shared), float offsets ----
constexpr int OFF_WAL  = 0;        // 32*64
constexpr int OFF_WEN  = 2048;     // 16*64
constexpr int OFF_M    = 3072;     // 64*64
constexpr int OFF_U    = 7168;     // 64
constexpr int OFF_W1A  = 7232;     // 128*64
constexpr int OFF_W1B  = 15424;    // 64*32
constexpr int OFF_WFA  = 17472;    // 64*64
constexpr int OFF_WFB  = 21568;    // 64*32
constexpr int OFF_HBW  = 23616;    // 64*32
constexpr int OFF_VW1  = 25664;    // 64*32
constexpr int OFF_VW2  = 27712;    // 32
constexpr int OFF_BAL  = 27744;    // 64
constexpr int OFF_BEN  = 27808;    // 64
constexpr int OFF_W1B1 = 27872;    // 64
constexpr int OFF_W1B2 = 27936;    // 32
constexpr int OFF_WFB1 = 27968;    // 64
constexpr int OFF_WFB2 = 28032;    // 32
constexpr int OFF_HBB  = 28064;    // 32
constexpr int OFF_VB1  = 28096;    // 32
constexpr int OFF_VB2  = 28128;    // 1
constexpr int W_TOT_AL = 28144;

// ---- per-group scratch (relative float offsets) ----
// Union region S_U1 (4352): FEAT[p*512+e*32+f] during A/B;
// Zt[p*1088+c*17+e] during Z/E; then SH/W1O/HID/H2/H3.
constexpr int S_U1    = 0;
constexpr int S_FEAT  = S_U1;            // 2048
constexpr int S_ZT    = S_U1;            // 4352
constexpr int S_SH    = S_U1;            // 2048  [p*512+a*64+hu]
constexpr int S_W1O   = S_U1 + 2048;     // 1024  [p*256+a*32+m]
constexpr int S_HID   = S_U1 + 3072;     // 128   [p*32+m]
constexpr int S_H2    = S_U1 + 3200;     // 256   [p*64+r]
constexpr int S_H3    = S_U1 + 3456;     // 128   [p*32+m]
constexpr int S_AQ    = 4352;            // 32    [p*8+a]
constexpr int S_ENTT  = 4384;            // 5120  [p*1280+d*20+e]
constexpr int S_XU    = 9504;            // 64    [p*16+e]
constexpr int S_EM    = 9568;            // 1088  [p*272+i*17+j]; later AOUT [p*64+d]
constexpr int S_AOUT  = S_EM;
constexpr int S_AMEAN = 10656;           // 64    [p*16+e]
constexpr int SCR_SZ  = 10736;

constexpr int SMEM_FLOATS = W_TOT_AL + 2 * SCR_SZ;
constexpr int SMEM_BYTES  = SMEM_FLOATS * 4;     // 198464 B
static_assert(SMEM_BYTES <= 227 * 1024, "smem");

constexpr float INVS = 0.08838834764831845f;     // 1/sqrt(128)

typedef unsigned long long ull;
__device__ __forceinline__ ull pk(float a, float b) {
    ull r; asm("mov.b64 %0,{%1,%2};" : "=l"(r) : "f"(a), "f"(b)); return r;
}
__device__ __forceinline__ void fma2(ull& acc, ull a, ull b) {
    asm("fma.rn.f32x2 %0,%1,%2,%0;" : "+l"(acc) : "l"(a), "l"(b));
}
__device__ __forceinline__ float2 unpk(ull v) {
    float2 f; asm("mov.b64 {%0,%1},%2;" : "=f"(f.x), "=f"(f.y) : "l"(v)); return f;
}

__device__ float g_M[64 * 64];
__device__ float g_U[64];

} // namespace

// ---------------- precompute: M = Wq Wk^T * invs, u = Wq bk * invs -----------
__global__ void precompute_kernel(const float* __restrict__ Wq,
                                  const float* __restrict__ Wk,
                                  const float* __restrict__ bk) {
    int t = threadIdx.x;                 // 256
    int d = blockIdx.x * 4 + (t >> 6);   // 0..63
    int c = t & 63;
    float s = 0.f;
    #pragma unroll 8
    for (int k = 0; k < 128; ++k)
        s = fmaf(Wq[d * 128 + k], Wk[c * 128 + k], s);
    g_M[d * 64 + c] = s * INVS;
    if (blockIdx.x == 0 && t < 64) {
        float su = 0.f;
        #pragma unroll 8
        for (int k = 0; k < 128; ++k)
            su = fmaf(Wq[t * 128 + k], bk[k], su);
        g_U[t] = su * INVS;
    }
}

// ---------------- main kernel ----------------
__global__ void __launch_bounds__(NTH, 1) qmixer_kernel(
    const float* __restrict__ g_aq,     // [B,S,8]
    const float* __restrict__ g_ally,   // [8,B,S,32]
    const float* __restrict__ g_enemy,  // [8,B,S,16]
    const float* __restrict__ g_Wal,  const float* __restrict__ g_bal,
    const float* __restrict__ g_Wen,  const float* __restrict__ g_ben,
    const float* __restrict__ g_w1W1, const float* __restrict__ g_w1b1,
    const float* __restrict__ g_w1W2, const float* __restrict__ g_w1b2,
    const float* __restrict__ g_wfW1, const float* __restrict__ g_wfb1,
    const float* __restrict__ g_wfW2, const float* __restrict__ g_wfb2,
    const float* __restrict__ g_hbW,  const float* __restrict__ g_hbb,
    const float* __restrict__ g_vW1,  const float* __restrict__ g_vb1,
    const float* __restrict__ g_vW2,  const float* __restrict__ g_vb2,
    float* __restrict__ out)
{
    extern __shared__ float sm[];
    const int tid = threadIdx.x;
    const int g   = tid >> 8;
    const int t   = tid & 255;
    const int sg  = W_TOT_AL + g * SCR_SZ;
    const int gbar = g + 1;
    const int gp0 = blockIdx.x * 8 + g * 4;

    // ---- stage weights (float4 where possible) ----
    {
        auto cp4 = [&](int off, const float* src, int n) {
            const float4* s4 = reinterpret_cast<const float4*>(src);
            float4* d4 = reinterpret_cast<float4*>(&sm[off]);
            for (int i = tid; i < n / 4; i += NTH) d4[i] = s4[i];
        };
        cp4(OFF_WAL,  g_Wal,  2048);
        cp4(OFF_WEN,  g_Wen,  1024);
        cp4(OFF_M,    g_M,    4096);
        cp4(OFF_U,    g_U,    64);
        cp4(OFF_W1A,  g_w1W1, 8192);
        cp4(OFF_W1B,  g_w1W2, 2048);
        cp4(OFF_WFA,  g_wfW1, 4096);
        cp4(OFF_WFB,  g_wfW2, 2048);
        cp4(OFF_HBW,  g_hbW,  2048);
        cp4(OFF_VW1,  g_vW1,  2048);
        cp4(OFF_VW2,  g_vW2,  32);
        cp4(OFF_BAL,  g_bal,  64);
        cp4(OFF_BEN,  g_ben,  64);
        cp4(OFF_W1B1, g_w1b1, 64);
        cp4(OFF_W1B2, g_w1b2, 32);
        cp4(OFF_WFB1, g_wfb1, 64);
        cp4(OFF_WFB2, g_wfb2, 32);
        cp4(OFF_HBB,  g_hbb,  32);
        cp4(OFF_VB1,  g_vb1,  32);
        if (tid == 0) sm[OFF_VB2] = g_vb2[0];
    }
    __syncthreads();

    #define GBAR() asm volatile("bar.sync %0, 256;" :: "r"(gbar) : "memory")

    // ================= Phase A: load 4 pairs' inputs =================
    {
        // ally: 4p x 8e x 8 float4
        int p = t >> 6, e = (t >> 3) & 7, f4 = t & 7;
        reinterpret_cast<float4*>(&sm[sg + S_FEAT + p * 512 + e * 32])[f4] =
            reinterpret_cast<const float4*>(&g_ally[(e * BSTOT + gp0 + p) * 32])[f4];
        if (t < 128) {  // enemy: 4p x 8e x 4 float4
            int pp = t >> 5, ee = (t >> 2) & 7, ff4 = t & 3;
            reinterpret_cast<float4*>(&sm[sg + S_FEAT + pp * 512 + (8 + ee) * 32])[ff4] =
                reinterpret_cast<const float4*>(&g_enemy[(ee * BSTOT + gp0 + pp) * 16])[ff4];
        }
        if (t < 32) {
            int pp = t >> 3, a = t & 7;
            sm[sg + S_AQ + pp * 8 + a] = g_aq[(gp0 + pp) * 8 + a];
        }
    }
    GBAR();

    // ================= Phase B: embeddings -> ENTT[p][d*20+e] =================
    {
        int p = t >> 6, d = t & 63;
        float acc[16];
        float ba = sm[OFF_BAL + d], be = sm[OFF_BEN + d];
        #pragma unroll
        for (int e = 0; e < 8; ++e) { acc[e] = ba; acc[8 + e] = be; }
        const float* FEAT = &sm[sg + S_FEAT + p * 512];
        #pragma unroll
        for (int f4 = 0; f4 < 8; ++f4) {
            int f = f4 * 4;
            float w0 = sm[OFF_WAL + f * 64 + d];
            float w1 = sm[OFF_WAL + (f + 1) * 64 + d];
            float w2 = sm[OFF_WAL + (f + 2) * 64 + d];
            float w3 = sm[OFF_WAL + (f + 3) * 64 + d];
            #pragma unroll
            for (int e = 0; e < 8; ++e) {
                float4 x = *reinterpret_cast<const float4*>(&FEAT[e * 32 + f]);
                acc[e] = fmaf(x.x, w0, acc[e]);
                acc[e] = fmaf(x.y, w1, acc[e]);
                acc[e] = fmaf(x.z, w2, acc[e]);
                acc[e] = fmaf(x.w, w3, acc[e]);
            }
        }
        #pragma unroll
        for (int f4 = 0; f4 < 4; ++f4) {
            int f = f4 * 4;
            float w0 = sm[OFF_WEN + f * 64 + d];
            float w1 = sm[OFF_WEN + (f + 1) * 64 + d];
            float w2 = sm[OFF_WEN + (f + 2) * 64 + d];
            float w3 = sm[OFF_WEN + (f + 3) * 64 + d];
            #pragma unroll
            for (int e = 0; e < 8; ++e) {
                float4 x = *reinterpret_cast<const float4*>(&FEAT[(8 + e) * 32 + f]);
                acc[8+e] = fmaf(x.x, w0, acc[8+e]);
                acc[8+e] = fmaf(x.y, w1, acc[8+e]);
                acc[8+e] = fmaf(x.z, w2, acc[8+e]);
                acc[8+e] = fmaf(x.w, w3, acc[8+e]);
            }
        }
        float* er = &sm[sg + S_ENTT + p * 1280 + d * 20];
        #pragma unroll
        for (int e = 0; e < 16; ++e) er[e] = acc[e];
    }
    GBAR();

    // ================= Phase Z: Z = X^T M  -> Zt[p][c*17+e] =================
    {
        int p = t >> 6, r = t & 63;
        int e0 = (r >> 4) * 4, c0 = (r & 15) * 4;
        ull acc[4][2];  // [e][c-pair]
        #pragma unroll
        for (int e = 0; e < 4; ++e) { acc[e][0] = 0ull; acc[e][1] = 0ull; }
        const float* X = &sm[sg + S_ENTT + p * 1280 + e0];
        const float* M = &sm[OFF_M + c0];
        #pragma unroll 4
        for (int d = 0; d < 64; ++d) {
            float4 m4 = *reinterpret_cast<const float4*>(M + d * 64);
            float4 x4 = *reinterpret_cast<const float4*>(X + d * 20);
            ull mp0 = pk(m4.x, m4.y), mp1 = pk(m4.z, m4.w);
            ull xs0 = pk(x4.x, x4.x), xs1 = pk(x4.y, x4.y);
            ull xs2 = pk(x4.z, x4.z), xs3 = pk(x4.w, x4.w);
            fma2(acc[0][0], xs0, mp0); fma2(acc[0][1], xs0, mp1);
            fma2(acc[1][0], xs1, mp0); fma2(acc[1][1], xs1, mp1);
            fma2(acc[2][0], xs2, mp0); fma2(acc[2][1], xs2, mp1);
            fma2(acc[3][0], xs3, mp0); fma2(acc[3][1], xs3, mp1);
        }
        float* Zt = &sm[sg + S_ZT + p * 1088];
        #pragma unroll
        for (int e = 0; e < 4; ++e) {
            float2 v0 = unpk(acc[e][0]), v1 = unpk(acc[e][1]);
            Zt[(c0    ) * 17 + e0 + e] = v0.x;
            Zt[(c0 + 1) * 17 + e0 + e] = v0.y;
            Zt[(c0 + 2) * 17 + e0 + e] = v1.x;
            Zt[(c0 + 3) * 17 + e0 + e] = v1.y;
        }
    }
    GBAR();

    // ================= Phase E: E[i][j] = Z[i]·x_j ; spare threads: xu =======
    if (t < 128) {
        int p = t >> 5, q = t & 31;
        int i0 = (q >> 2) * 2, j0 = (q & 3) * 4;
        const float* Zt = &sm[sg + S_ZT + p * 1088];
        const float* X  = &sm[sg + S_ENTT + p * 1280 + j0];
        ull acc[2][2];
        acc[0][0] = acc[0][1] = acc[1][0] = acc[1][1] = 0ull;
        #pragma unroll 4
        for (int c = 0; c < 64; ++c) {
            float z0 = Zt[c * 17 + i0];
            float z1 = Zt[c * 17 + i0 + 1];
            float4 x4 = *reinterpret_cast<const float4*>(X + c * 20);
            ull xp0 = pk(x4.x, x4.y), xp1 = pk(x4.z, x4.w);
            ull zs0 = pk(z0, z0), zs1 = pk(z1, z1);
            fma2(acc[0][0], zs0, xp0); fma2(acc[0][1], zs0, xp1);
            fma2(acc[1][0], zs1, xp0); fma2(acc[1][1], zs1, xp1);
        }
        float* E = &sm[sg + S_EM + p * 272];
        #pragma unroll
        for (int ii = 0; ii < 2; ++ii) {
            float2 v0 = unpk(acc[ii][0]), v1 = unpk(acc[ii][1]);
            E[(i0 + ii) * 17 + j0]     = v0.x;
            E[(i0 + ii) * 17 + j0 + 1] = v0.y;
            E[(i0 + ii) * 17 + j0 + 2] = v1.x;
            E[(i0 + ii) * 17 + j0 + 3] = v1.y;
        }
    } else if (t < 192) {
        int idx = t - 128;
        int p = idx >> 4, e = idx & 15;
        const float* X = &sm[sg + S_ENTT + p * 1280 + e];
        float s = 0.f;
        #pragma unroll 8
        for (int d = 0; d < 64; ++d)
            s = fmaf(X[d * 20], sm[OFF_U + d], s);
        sm[sg + S_XU + p * 16 + e] = s;
    }
    GBAR();

    // ================= softmax over i (per column j) + amean ================
    if (t < 64) {
        int p = t >> 4, j = t & 15;
        float* E = &sm[sg + S_EM + p * 272];
        const float* XU = &sm[sg + S_XU + p * 16];
        float col[16];
        #pragma unroll
        for (int i = 0; i < 16; ++i) col[i] = E[i * 17 + j] + XU[i];
        float mx = col[0];
        #pragma unroll
        for (int i = 1; i < 16; ++i) mx = fmaxf(mx, col[i]);
        float ssum = 0.f;
        #pragma unroll
        for (int i = 0; i < 16; ++i) { col[i] = __expf(col[i] - mx); ssum += col[i]; }
        float inv = 1.0f / ssum;
        #pragma unroll
        for (int i = 0; i < 16; ++i) E[i * 17 + j] = col[i] * inv;
        __syncwarp();
        // amean: warp holds 2 complete pairs (lanes 0-15 pair a, 16-31 pair b)
        int i = j;          // reuse lane's low 4 bits as row index
        const float* Er = &sm[sg + S_EM + p * 272 + i * 17];
        float s = 0.f;
        #pragma unroll
        for (int jj = 0; jj < 16; ++jj) s += Er[jj];
        sm[sg + S_AMEAN + p * 16 + i] = s * 0.0625f;
    }
    GBAR();

    // ================= attn_out[p][d] (overlays E region) ==================
    {
        int p = t >> 6, d = t & 63;
        const float* X = &sm[sg + S_ENTT + p * 1280 + d * 20];
        const float* AM = &sm[sg + S_AMEAN + p * 16];
        float4 x0 = *reinterpret_cast<const float4*>(X);
        float4 x1 = *reinterpret_cast<const float4*>(X + 4);
        float4 x2 = *reinterpret_cast<const float4*>(X + 8);
        float4 x3 = *reinterpret_cast<const float4*>(X + 12);
        float4 a0 = *reinterpret_cast<const float4*>(AM);
        float4 a1 = *reinterpret_cast<const float4*>(AM + 4);
        float4 a2 = *reinterpret_cast<const float4*>(AM + 8);
        float4 a3 = *reinterpret_cast<const float4*>(AM + 12);
        float s = x0.x*a0.x + x0.y*a0.y + x0.z*a0.z + x0.w*a0.w
                + x1.x*a1.x + x1.y*a1.y + x1.z*a1.z + x1.w*a1.w
                + x2.x*a2.x + x2.y*a2.y + x2.z*a2.z + x2.w*a2.w
                + x3.x*a3.x + x3.y*a3.y + x3.z*a3.z + x3.w*a3.w;
        GBAR();                       // all E reads (none) / amean reads done; order vs overlay write
        sm[sg + S_AOUT + p * 64 + d] = s;
    }
    GBAR();

    // ================= hypernet w1 layer 1 -> SH[p][a*64+hu] ================
    {
        int p = t >> 6, hu = t & 63;
        const float* AO = &sm[sg + S_AOUT + p * 64];
        float c = sm[OFF_W1B1 + hu];
        #pragma unroll 8
        for (int f = 0; f < 64; ++f)
            c = fmaf(AO[f], sm[OFF_W1A + f * 64 + hu], c);
        ull acc[4];
        ull pc = pk(c, c);
        acc[0] = pc; acc[1] = pc; acc[2] = pc; acc[3] = pc;
        const float* X = &sm[sg + S_ENTT + p * 1280];
        #pragma unroll 4
        for (int f = 0; f < 64; ++f) {
            float w = sm[OFF_W1A + (64 + f) * 64 + hu];
            ull ws = pk(w, w);
            const ull* xr = reinterpret_cast<const ull*>(X + f * 20);
            fma2(acc[0], xr[0], ws);
            fma2(acc[1], xr[1], ws);
            fma2(acc[2], xr[2], ws);
            fma2(acc[3], xr[3], ws);
        }
        float* SH = &sm[sg + S_SH + p * 512];
        #pragma unroll
        for (int ap = 0; ap < 4; ++ap) {
            float2 v = unpk(acc[ap]);
            SH[(2 * ap) * 64 + hu]     = fmaxf(v.x, 0.f);
            SH[(2 * ap + 1) * 64 + hu] = fmaxf(v.y, 0.f);
        }
    }
    GBAR();

    // ================= w1 layer 2: W1O[p][a*32+m] = |SH@W2 + b2| ============
    {
        int p = t >> 6, r = t & 63;
        int a = r >> 3, m0 = (r & 7) * 4;
        ull acc0 = pk(sm[OFF_W1B2 + m0],     sm[OFF_W1B2 + m0 + 1]);
        ull acc1 = pk(sm[OFF_W1B2 + m0 + 2], sm[OFF_W1B2 + m0 + 3]);
        const float* SH = &sm[sg + S_SH + p * 512 + a * 64];
        const float* W = &sm[OFF_W1B + m0];
        #pragma unroll 4
        for (int k = 0; k < 64; ++k) {
            float4 w4 = *reinterpret_cast<const float4*>(W + k * 32);
            float shv = SH[k];
            ull ss = pk(shv, shv);
            fma2(acc0, ss, pk(w4.x, w4.y));
            fma2(acc1, ss, pk(w4.z, w4.w));
        }
        float2 v0 = unpk(acc0), v1 = unpk(acc1);
        *reinterpret_cast<float4*>(&sm[sg + S_W1O + p * 256 + a * 32 + m0]) =
            make_float4(fabsf(v0.x), fabsf(v0.y), fabsf(v1.x), fabsf(v1.y));
    }
    GBAR();

    // ================= heads: wf-l1 (all), hidden (r<32), v-l1 (r>=32) ======
    {
        int p = t >> 6, r = t & 63;
        const float* AO = &sm[sg + S_AOUT + p * 64];
        float accW = sm[OFF_WFB1 + r];
        #pragma unroll 8
        for (int f = 0; f < 64; ++f)
            accW = fmaf(AO[f], sm[OFF_WFA + f * 64 + r], accW);
        sm[sg + S_H2 + p * 64 + r] = fmaxf(accW, 0.f);
        if (r < 32) {
            int m = r;
            float bb = sm[OFF_HBB + m];
            #pragma unroll 8
            for (int d = 0; d < 64; ++d)
                bb = fmaf(AO[d], sm[OFF_HBW + d * 32 + m], bb);
            float hv = bb;
            const float* W1O = &sm[sg + S_W1O + p * 256];
            const float* AQ  = &sm[sg + S_AQ + p * 8];
            #pragma unroll
            for (int a = 0; a < 8; ++a)
                hv = fmaf(AQ[a], W1O[a * 32 + m], hv);
            sm[sg + S_HID + p * 32 + m] = hv > 0.f ? hv : expm1f(hv);
        } else {
            int m = r - 32;
            float av = sm[OFF_VB1 + m];
            #pragma unroll 8
            for (int d = 0; d < 64; ++d)
                av = fmaf(AO[d], sm[OFF_VW1 + d * 32 + m], av);
            sm[sg + S_H3 + p * 32 + m] = fmaxf(av, 0.f);
        }
    }
    GBAR();

    // ================= final: q_tot = <hidden, |wf|> + v ====================
    if (t < 128) {
        int p = t >> 5, m = t & 31;
        const float* H2 = &sm[sg + S_H2 + p * 64];
        float wf = sm[OFF_WFB2 + m];
        #pragma unroll 8
        for (int k = 0; k < 64; ++k)
            wf = fmaf(H2[k], sm[OFF_WFB + k * 32 + m], wf);
        wf = fabsf(wf);
        float part = sm[sg + S_HID + p * 32 + m] * wf
                   + sm[sg + S_H3 + p * 32 + m] * sm[OFF_VW2 + m];
        #pragma unroll
        for (int off = 16; off > 0; off >>= 1)
            part += __shfl_down_sync(0xffffffffu, part, off);
        if (m == 0) out[gp0 + p] = part + sm[OFF_VB2];
    }
    #undef GBAR
}

extern "C" void kernel_launch(void* const* d_in, const int* in_sizes, int n_in,
                              void* d_out, int out_size) {
    (void)in_sizes; (void)n_in; (void)out_size;
    // inputs: 0 aq, 1 ally, 2 enemy, 3 W_al, 4 b_al, 5 W_en, 6 b_en,
    // 7 Wq, 8 bq, 9 Wk, 10 bk, 11 w1_W1, 12 w1_b1, 13 w1_W2, 14 w1_b2,
    // 15 wf_W1, 16 wf_b1, 17 wf_W2, 18 wf_b2, 19 hb_W, 20 hb_b,
    // 21 v_W1, 22 v_b1, 23 v_W2, 24 v_b2
    precompute_kernel<<<16, 256>>>(
        (const float*)d_in[7], (const float*)d_in[9], (const float*)d_in[10]);
    cudaFuncSetAttribute(qmixer_kernel,
                         cudaFuncAttributeMaxDynamicSharedMemorySize, SMEM_BYTES);
    qmixer_kernel<<<GRID, NTH, SMEM_BYTES>>>(
        (const float*)d_in[0],  (const float*)d_in[1],  (const float*)d_in[2],
        (const float*)d_in[3],  (const float*)d_in[4],
        (const float*)d_in[5],  (const float*)d_in[6],
        (const float*)d_in[11], (const float*)d_in[12],
        (const float*)d_in[13], (const float*)d_in[14],
        (const float*)d_in[15], (const float*)d_in[16],
        (const float*)d_in[17], (const float*)d_in[18],
        (const float*)d_in[19], (const float*)d_in[20],
        (const float*)d_in[21], (const float*)d_in[22],
        (const float*)d_in[23], (const float*)d_in[24],
        (float*)d_out);
}

// round 5
// speedup vs baseline: 3.3874x; 1.0043x over previous
#include <cuda_runtime.h>
#include <math.h>

// QMixer forward on GB300 — round 5.
// Algebra: M = Wq Wk^T/sqrt(Da), u = Wq bk/sqrt(Da) (softmax over query axis).
// 2048 CTAs x 512 thr = 2 groups x 256; each group batches 4 (b,s) pairs.
// This round: crossbar-wavefront reduction (consolidated AO-GEMM via WCAT,
// SH retile with f32x2 agent pairs, vectorized stores/broadcasts).

namespace {

constexpr int NTH   = 512;
constexpr int BSTOT = 16384;
constexpr int GRID  = BSTOT / 8;

// ---- weight region (shared), float offsets ----
constexpr int OFF_WAL  = 0;        // 32*64
constexpr int OFF_WEN  = 2048;     // 16*64
constexpr int OFF_M    = 3072;     // 64*64
constexpr int OFF_U    = 7168;     // 64
constexpr int OFF_W1A2 = 7232;     // 64*64  (w1_W1 rows 64..127)
constexpr int OFF_W1B  = 11328;    // 64*32  (w1_W2)
constexpr int OFF_WFB  = 13376;    // 64*32  (wf_W2)
constexpr int OFF_VW2  = 15424;    // 32
constexpr int OFF_BAL  = 15456;    // 64
constexpr int OFF_BEN  = 15520;    // 64
constexpr int OFF_W1B2 = 15584;    // 32
constexpr int OFF_WFB2 = 15616;    // 32
constexpr int OFF_WCAT = 15648;    // 64*192: [w1_W1 rows0-63 | wf_W1 | hb_W | v_W1]
constexpr int OFF_BCAT = 27936;    // 192:   [w1_b1 | wf_b1 | hb_b | v_b1]
constexpr int OFF_VB2  = 28128;    // 1
constexpr int W_TOT_AL = 28144;

// ---- per-group scratch (relative float offsets) ----
// Union U1 (4352): FEAT (A/B) -> ZT (Z/E) -> {C,H2,HBP,H3,SH,W1O} (post-softmax)
constexpr int S_U1    = 0;
constexpr int S_FEAT  = S_U1;            // 2048 [p*512+e*32+f]
constexpr int S_ZT    = S_U1;            // 4352 [p*1088+c*17+e]
constexpr int S_C     = S_U1;            // 256  [p*64+hu]
constexpr int S_H2    = S_U1 + 256;      // 256  [p*64+r]
constexpr int S_HBP   = S_U1 + 512;      // 128  [p*32+m]
constexpr int S_H3    = S_U1 + 640;      // 128  [p*32+m]
constexpr int S_SH    = S_U1 + 768;      // 2048 [p*512+a*64+hu]
constexpr int S_W1O   = S_U1 + 2816;     // 1024 [p*256+a*32+m]
constexpr int S_AQ    = 4352;            // 32   [p*8+a]
constexpr int S_ENTT  = 4384;            // 5120 [p*1280+d*20+e]
constexpr int S_XU    = 9504;            // 64   [p*16+e]
constexpr int S_EM    = 9568;            // 1088 [p*272+i*17+j]
constexpr int S_AMEAN = 10656;           // 64   [p*16+e]
constexpr int S_AOT   = 10720;           // 256  [d*4+p]  (attn_out transposed)
constexpr int SCR_SZ  = 10976;

constexpr int SMEM_FLOATS = W_TOT_AL + 2 * SCR_SZ;
constexpr int SMEM_BYTES  = SMEM_FLOATS * 4;     // 200384 B
static_assert(SMEM_BYTES <= 227 * 1024, "smem");

constexpr float INVS = 0.08838834764831845f;     // 1/sqrt(128)

typedef unsigned long long ull;
__device__ __forceinline__ ull pk(float a, float b) {
    ull r; asm("mov.b64 %0,{%1,%2};" : "=l"(r) : "f"(a), "f"(b)); return r;
}
__device__ __forceinline__ void fma2(ull& acc, ull a, ull b) {
    asm("fma.rn.f32x2 %0,%1,%2,%0;" : "+l"(acc) : "l"(a), "l"(b));
}
__device__ __forceinline__ float2 unpk(ull v) {
    float2 f; asm("mov.b64 {%0,%1},%2;" : "=f"(f.x), "=f"(f.y) : "l"(v)); return f;
}

__device__ float g_M[64 * 64];
__device__ float g_U[64];

} // namespace

// ---------------- precompute: M = Wq Wk^T * invs, u = Wq bk * invs -----------
__global__ void precompute_kernel(const float* __restrict__ Wq,
                                  const float* __restrict__ Wk,
                                  const float* __restrict__ bk) {
    int t = threadIdx.x;                 // 256
    int d = blockIdx.x * 4 + (t >> 6);
    int c = t & 63;
    float s = 0.f;
    #pragma unroll 8
    for (int k = 0; k < 128; ++k)
        s = fmaf(Wq[d * 128 + k], Wk[c * 128 + k], s);
    g_M[d * 64 + c] = s * INVS;
    if (blockIdx.x == 0 && t < 64) {
        float su = 0.f;
        #pragma unroll 8
        for (int k = 0; k < 128; ++k)
            su = fmaf(Wq[t * 128 + k], bk[k], su);
        g_U[t] = su * INVS;
    }
}

// ---------------- main kernel ----------------
__global__ void __launch_bounds__(NTH, 1) qmixer_kernel(
    const float* __restrict__ g_aq,     // [B,S,8]
    const float* __restrict__ g_ally,   // [8,B,S,32]
    const float* __restrict__ g_enemy,  // [8,B,S,16]
    const float* __restrict__ g_Wal,  const float* __restrict__ g_bal,
    const float* __restrict__ g_Wen,  const float* __restrict__ g_ben,
    const float* __restrict__ g_w1W1, const float* __restrict__ g_w1b1,
    const float* __restrict__ g_w1W2, const float* __restrict__ g_w1b2,
    const float* __restrict__ g_wfW1, const float* __restrict__ g_wfb1,
    const float* __restrict__ g_wfW2, const float* __restrict__ g_wfb2,
    const float* __restrict__ g_hbW,  const float* __restrict__ g_hbb,
    const float* __restrict__ g_vW1,  const float* __restrict__ g_vb1,
    const float* __restrict__ g_vW2,  const float* __restrict__ g_vb2,
    float* __restrict__ out)
{
    extern __shared__ float sm[];
    const int tid = threadIdx.x;
    const int g   = tid >> 8;
    const int t   = tid & 255;
    const int sg  = W_TOT_AL + g * SCR_SZ;
    const int gbar = g + 1;
    const int gp0 = blockIdx.x * 8 + g * 4;

    // ---- stage weights ----
    {
        auto cp4 = [&](int off, const float* src, int n) {
            const float4* s4 = reinterpret_cast<const float4*>(src);
            float4* d4 = reinterpret_cast<float4*>(&sm[off]);
            for (int i = tid; i < n / 4; i += NTH) d4[i] = s4[i];
        };
        cp4(OFF_WAL,  g_Wal,  2048);
        cp4(OFF_WEN,  g_Wen,  1024);
        cp4(OFF_M,    g_M,    4096);
        cp4(OFF_U,    g_U,    64);
        cp4(OFF_W1B,  g_w1W2, 2048);
        cp4(OFF_WFB,  g_wfW2, 2048);
        cp4(OFF_VW2,  g_vW2,  32);
        cp4(OFF_BAL,  g_bal,  64);
        cp4(OFF_BEN,  g_ben,  64);
        cp4(OFF_W1B2, g_w1b2, 32);
        cp4(OFF_WFB2, g_wfb2, 32);
        // W1A split: rows 0-63 into WCAT cols 0-63, rows 64-127 -> W1A2
        for (int i = tid; i < 4096; i += NTH) {
            int f = i >> 6, c = i & 63;
            sm[OFF_WCAT + f * 192 + c]      = g_w1W1[i];
            sm[OFF_WCAT + f * 192 + 64 + c] = g_wfW1[i];
            sm[OFF_W1A2 + i] = g_w1W1[4096 + i];
        }
        for (int i = tid; i < 2048; i += NTH) {
            int f = i >> 5, m = i & 31;
            sm[OFF_WCAT + f * 192 + 128 + m] = g_hbW[i];
            sm[OFF_WCAT + f * 192 + 160 + m] = g_vW1[i];
        }
        if (tid < 192) {
            float b;
            if (tid < 64)       b = g_w1b1[tid];
            else if (tid < 128) b = g_wfb1[tid - 64];
            else if (tid < 160) b = g_hbb[tid - 128];
            else                b = g_vb1[tid - 160];
            sm[OFF_BCAT + tid] = b;
        }
        if (tid == 0) sm[OFF_VB2] = g_vb2[0];
    }
    __syncthreads();

    #define GBAR() asm volatile("bar.sync %0, 256;" :: "r"(gbar) : "memory")

    // ================= Phase A: load 4 pairs' inputs =================
    {
        int p = t >> 6, e = (t >> 3) & 7, f4 = t & 7;
        reinterpret_cast<float4*>(&sm[sg + S_FEAT + p * 512 + e * 32])[f4] =
            reinterpret_cast<const float4*>(&g_ally[(e * BSTOT + gp0 + p) * 32])[f4];
        if (t < 128) {
            int pp = t >> 5, ee = (t >> 2) & 7, ff4 = t & 3;
            reinterpret_cast<float4*>(&sm[sg + S_FEAT + pp * 512 + (8 + ee) * 32])[ff4] =
                reinterpret_cast<const float4*>(&g_enemy[(ee * BSTOT + gp0 + pp) * 16])[ff4];
        }
        if (t < 32) {
            int pp = t >> 3, a = t & 7;
            sm[sg + S_AQ + pp * 8 + a] = g_aq[(gp0 + pp) * 8 + a];
        }
    }
    GBAR();

    // ================= Phase B: embeddings -> ENTT[p][d*20+e] =================
    {
        int p = t >> 6, d = t & 63;
        float acc[16];
        float ba = sm[OFF_BAL + d], be = sm[OFF_BEN + d];
        #pragma unroll
        for (int e = 0; e < 8; ++e) { acc[e] = ba; acc[8 + e] = be; }
        const float* FEAT = &sm[sg + S_FEAT + p * 512];
        #pragma unroll
        for (int f4 = 0; f4 < 8; ++f4) {
            int f = f4 * 4;
            float w0 = sm[OFF_WAL + f * 64 + d];
            float w1 = sm[OFF_WAL + (f + 1) * 64 + d];
            float w2 = sm[OFF_WAL + (f + 2) * 64 + d];
            float w3 = sm[OFF_WAL + (f + 3) * 64 + d];
            #pragma unroll
            for (int e = 0; e < 8; ++e) {
                float4 x = *reinterpret_cast<const float4*>(&FEAT[e * 32 + f]);
                acc[e] = fmaf(x.x, w0, acc[e]);
                acc[e] = fmaf(x.y, w1, acc[e]);
                acc[e] = fmaf(x.z, w2, acc[e]);
                acc[e] = fmaf(x.w, w3, acc[e]);
            }
        }
        #pragma unroll
        for (int f4 = 0; f4 < 4; ++f4) {
            int f = f4 * 4;
            float w0 = sm[OFF_WEN + f * 64 + d];
            float w1 = sm[OFF_WEN + (f + 1) * 64 + d];
            float w2 = sm[OFF_WEN + (f + 2) * 64 + d];
            float w3 = sm[OFF_WEN + (f + 3) * 64 + d];
            #pragma unroll
            for (int e = 0; e < 8; ++e) {
                float4 x = *reinterpret_cast<const float4*>(&FEAT[(8 + e) * 32 + f]);
                acc[8+e] = fmaf(x.x, w0, acc[8+e]);
                acc[8+e] = fmaf(x.y, w1, acc[8+e]);
                acc[8+e] = fmaf(x.z, w2, acc[8+e]);
                acc[8+e] = fmaf(x.w, w3, acc[8+e]);
            }
        }
        float* er = &sm[sg + S_ENTT + p * 1280 + d * 20];
        *reinterpret_cast<float4*>(&er[0])  = make_float4(acc[0], acc[1], acc[2], acc[3]);
        *reinterpret_cast<float4*>(&er[4])  = make_float4(acc[4], acc[5], acc[6], acc[7]);
        *reinterpret_cast<float4*>(&er[8])  = make_float4(acc[8], acc[9], acc[10], acc[11]);
        *reinterpret_cast<float4*>(&er[12]) = make_float4(acc[12], acc[13], acc[14], acc[15]);
    }
    GBAR();

    // ================= Phase Z: Z = X^T M  -> Zt[p][c*17+e] =================
    {
        int p = t >> 6, r = t & 63;
        int e0 = (r >> 4) * 4, c0 = (r & 15) * 4;
        ull acc[4][2];
        #pragma unroll
        for (int e = 0; e < 4; ++e) { acc[e][0] = 0ull; acc[e][1] = 0ull; }
        const float* X = &sm[sg + S_ENTT + p * 1280 + e0];
        const float* M = &sm[OFF_M + c0];
        #pragma unroll 4
        for (int d = 0; d < 64; ++d) {
            float4 m4 = *reinterpret_cast<const float4*>(M + d * 64);
            float4 x4 = *reinterpret_cast<const float4*>(X + d * 20);
            ull mp0 = pk(m4.x, m4.y), mp1 = pk(m4.z, m4.w);
            ull xs0 = pk(x4.x, x4.x), xs1 = pk(x4.y, x4.y);
            ull xs2 = pk(x4.z, x4.z), xs3 = pk(x4.w, x4.w);
            fma2(acc[0][0], xs0, mp0); fma2(acc[0][1], xs0, mp1);
            fma2(acc[1][0], xs1, mp0); fma2(acc[1][1], xs1, mp1);
            fma2(acc[2][0], xs2, mp0); fma2(acc[2][1], xs2, mp1);
            fma2(acc[3][0], xs3, mp0); fma2(acc[3][1], xs3, mp1);
        }
        float* Zt = &sm[sg + S_ZT + p * 1088];
        #pragma unroll
        for (int e = 0; e < 4; ++e) {
            float2 v0 = unpk(acc[e][0]), v1 = unpk(acc[e][1]);
            Zt[(c0    ) * 17 + e0 + e] = v0.x;
            Zt[(c0 + 1) * 17 + e0 + e] = v0.y;
            Zt[(c0 + 2) * 17 + e0 + e] = v1.x;
            Zt[(c0 + 3) * 17 + e0 + e] = v1.y;
        }
    }
    GBAR();

    // ================= Phase E: E[i][j] = Z[i]·x_j ; spare threads: xu =======
    if (t < 128) {
        int p = t >> 5, q = t & 31;
        int i0 = (q >> 2) * 2, j0 = (q & 3) * 4;
        const float* Zt = &sm[sg + S_ZT + p * 1088];
        const float* X  = &sm[sg + S_ENTT + p * 1280 + j0];
        ull acc[2][2];
        acc[0][0] = acc[0][1] = acc[1][0] = acc[1][1] = 0ull;
        #pragma unroll 4
        for (int c = 0; c < 64; ++c) {
            float z0 = Zt[c * 17 + i0];
            float z1 = Zt[c * 17 + i0 + 1];
            float4 x4 = *reinterpret_cast<const float4*>(X + c * 20);
            ull xp0 = pk(x4.x, x4.y), xp1 = pk(x4.z, x4.w);
            ull zs0 = pk(z0, z0), zs1 = pk(z1, z1);
            fma2(acc[0][0], zs0, xp0); fma2(acc[0][1], zs0, xp1);
            fma2(acc[1][0], zs1, xp0); fma2(acc[1][1], zs1, xp1);
        }
        float* E = &sm[sg + S_EM + p * 272];
        #pragma unroll
        for (int ii = 0; ii < 2; ++ii) {
            float2 v0 = unpk(acc[ii][0]), v1 = unpk(acc[ii][1]);
            E[(i0 + ii) * 17 + j0]     = v0.x;
            E[(i0 + ii) * 17 + j0 + 1] = v0.y;
            E[(i0 + ii) * 17 + j0 + 2] = v1.x;
            E[(i0 + ii) * 17 + j0 + 3] = v1.y;
        }
    } else if (t < 192) {
        int idx = t - 128;
        int p = idx >> 4, e = idx & 15;
        const float* X = &sm[sg + S_ENTT + p * 1280 + e];
        float s = 0.f;
        #pragma unroll 8
        for (int d = 0; d < 64; ++d)
            s = fmaf(X[d * 20], sm[OFF_U + d], s);
        sm[sg + S_XU + p * 16 + e] = s;
    }
    GBAR();

    // ================= softmax over i (per column j) + amean ================
    if (t < 64) {
        int p = t >> 4, j = t & 15;
        float* E = &sm[sg + S_EM + p * 272];
        const float* XU = &sm[sg + S_XU + p * 16];
        float col[16];
        #pragma unroll
        for (int i = 0; i < 16; ++i) col[i] = E[i * 17 + j] + XU[i];
        float mx = col[0];
        #pragma unroll
        for (int i = 1; i < 16; ++i) mx = fmaxf(mx, col[i]);
        float ssum = 0.f;
        #pragma unroll
        for (int i = 0; i < 16; ++i) { col[i] = __expf(col[i] - mx); ssum += col[i]; }
        float inv = 1.0f / ssum;
        #pragma unroll
        for (int i = 0; i < 16; ++i) E[i * 17 + j] = col[i] * inv;
        __syncwarp();
        int i = j;
        const float* Er = &sm[sg + S_EM + p * 272 + i * 17];
        float s = 0.f;
        #pragma unroll
        for (int jj = 0; jj < 16; ++jj) s += Er[jj];
        sm[sg + S_AMEAN + p * 16 + i] = s * 0.0625f;
    }
    GBAR();

    // ================= attn_out -> AOT[d*4+p] (transposed) ==================
    {
        int p = t >> 6, d = t & 63;
        const float* X = &sm[sg + S_ENTT + p * 1280 + d * 20];
        const float* AM = &sm[sg + S_AMEAN + p * 16];
        float4 x0 = *reinterpret_cast<const float4*>(X);
        float4 x1 = *reinterpret_cast<const float4*>(X + 4);
        float4 x2 = *reinterpret_cast<const float4*>(X + 8);
        float4 x3 = *reinterpret_cast<const float4*>(X + 12);
        float4 a0 = *reinterpret_cast<const float4*>(AM);
        float4 a1 = *reinterpret_cast<const float4*>(AM + 4);
        float4 a2 = *reinterpret_cast<const float4*>(AM + 8);
        float4 a3 = *reinterpret_cast<const float4*>(AM + 12);
        float s = x0.x*a0.x + x0.y*a0.y + x0.z*a0.z + x0.w*a0.w
                + x1.x*a1.x + x1.y*a1.y + x1.z*a1.z + x1.w*a1.w
                + x2.x*a2.x + x2.y*a2.y + x2.z*a2.z + x2.w*a2.w
                + x3.x*a3.x + x3.y*a3.y + x3.z*a3.z + x3.w*a3.w;
        sm[sg + S_AOT + d * 4 + p] = s;
    }
    GBAR();

    // ================= AOG: all attn_out projections in one GEMM ===========
    // cols 0-63: C (w1 common part, raw) | 64-127: H2 (relu) |
    // 128-159: HBP (raw) | 160-191: H3 (relu)
    if (t < 192) {
        const int col = t;
        const float* WC  = &sm[OFF_WCAT + col];
        const float* AOT = &sm[sg + S_AOT];
        float a0 = 0.f, a1 = 0.f, a2 = 0.f, a3 = 0.f;
        #pragma unroll 8
        for (int f = 0; f < 64; ++f) {
            float w = WC[f * 192];
            float4 ao = *reinterpret_cast<const float4*>(&AOT[f * 4]);
            a0 = fmaf(w, ao.x, a0);
            a1 = fmaf(w, ao.y, a1);
            a2 = fmaf(w, ao.z, a2);
            a3 = fmaf(w, ao.w, a3);
        }
        float b = sm[OFF_BCAT + col];
        a0 += b; a1 += b; a2 += b; a3 += b;
        if (col < 64) {
            sm[sg + S_C +   0 + col] = a0;
            sm[sg + S_C +  64 + col] = a1;
            sm[sg + S_C + 128 + col] = a2;
            sm[sg + S_C + 192 + col] = a3;
        } else if (col < 128) {
            int r = col - 64;
            sm[sg + S_H2 +   0 + r] = fmaxf(a0, 0.f);
            sm[sg + S_H2 +  64 + r] = fmaxf(a1, 0.f);
            sm[sg + S_H2 + 128 + r] = fmaxf(a2, 0.f);
            sm[sg + S_H2 + 192 + r] = fmaxf(a3, 0.f);
        } else if (col < 160) {
            int m = col - 128;
            sm[sg + S_HBP +  0 + m] = a0;
            sm[sg + S_HBP + 32 + m] = a1;
            sm[sg + S_HBP + 64 + m] = a2;
            sm[sg + S_HBP + 96 + m] = a3;
        } else {
            int m = col - 160;
            sm[sg + S_H3 +  0 + m] = fmaxf(a0, 0.f);
            sm[sg + S_H3 + 32 + m] = fmaxf(a1, 0.f);
            sm[sg + S_H3 + 64 + m] = fmaxf(a2, 0.f);
            sm[sg + S_H3 + 96 + m] = fmaxf(a3, 0.f);
        }
    }
    GBAR();

    // ================= SH2: s_h = relu(C + x_a @ W1A2) ======================
    // thread: (p, ap=r&3 -> agents {2ap,2ap+1} packed, hu0=(r>>2)*4)
    {
        int p = t >> 6, r = t & 63;
        int ap = r & 3;
        int hu0 = (r >> 2) * 4;
        ull acc[4];
        const float* C = &sm[sg + S_C + p * 64];
        #pragma unroll
        for (int j = 0; j < 4; ++j) { float c = C[hu0 + j]; acc[j] = pk(c, c); }
        const float* W = &sm[OFF_W1A2 + hu0];
        const float* X = &sm[sg + S_ENTT + p * 1280 + 2 * ap];
        #pragma unroll 4
        for (int f = 0; f < 64; ++f) {
            float4 w4 = *reinterpret_cast<const float4*>(&W[f * 64]);
            ull xp = *reinterpret_cast<const ull*>(&X[f * 20]);
            fma2(acc[0], xp, pk(w4.x, w4.x));
            fma2(acc[1], xp, pk(w4.y, w4.y));
            fma2(acc[2], xp, pk(w4.z, w4.z));
            fma2(acc[3], xp, pk(w4.w, w4.w));
        }
        float* SH = &sm[sg + S_SH + p * 512];
        #pragma unroll
        for (int j = 0; j < 4; ++j) {
            float2 v = unpk(acc[j]);
            SH[(2 * ap)     * 64 + hu0 + j] = fmaxf(v.x, 0.f);
            SH[(2 * ap + 1) * 64 + hu0 + j] = fmaxf(v.y, 0.f);
        }
    }
    GBAR();

    // ================= W1O: w1[a][m] = |SH[a] @ W1B + b2| ===================
    {
        int p = t >> 6, r = t & 63;
        int a = r >> 3, m0 = (r & 7) * 4;
        ull acc0 = pk(sm[OFF_W1B2 + m0],     sm[OFF_W1B2 + m0 + 1]);
        ull acc1 = pk(sm[OFF_W1B2 + m0 + 2], sm[OFF_W1B2 + m0 + 3]);
        const float* SH = &sm[sg + S_SH + p * 512 + a * 64];
        const float* W  = &sm[OFF_W1B + m0];
        #pragma unroll 4
        for (int k0 = 0; k0 < 64; k0 += 4) {
            float4 s4 = *reinterpret_cast<const float4*>(&SH[k0]);
            #pragma unroll
            for (int j = 0; j < 4; ++j) {
                float4 w4 = *reinterpret_cast<const float4*>(&W[(k0 + j) * 32]);
                float sv = (&s4.x)[j];
                ull ss = pk(sv, sv);
                fma2(acc0, ss, pk(w4.x, w4.y));
                fma2(acc1, ss, pk(w4.z, w4.w));
            }
        }
        float2 v0 = unpk(acc0), v1 = unpk(acc1);
        *reinterpret_cast<float4*>(&sm[sg + S_W1O + p * 256 + a * 32 + m0]) =
            make_float4(fabsf(v0.x), fabsf(v0.y), fabsf(v1.x), fabsf(v1.y));
    }
    GBAR();

    // ================= hidden + final (fused) ===============================
    if (t < 128) {
        int p = t >> 5, m = t & 31;
        // hidden = elu(sum_a aq*w1 + b1)
        float hv = sm[sg + S_HBP + p * 32 + m];
        const float* W1O = &sm[sg + S_W1O + p * 256];
        const float* AQ  = &sm[sg + S_AQ + p * 8];
        float4 q0 = *reinterpret_cast<const float4*>(&AQ[0]);
        float4 q1 = *reinterpret_cast<const float4*>(&AQ[4]);
        hv = fmaf(q0.x, W1O[0 * 32 + m], hv);
        hv = fmaf(q0.y, W1O[1 * 32 + m], hv);
        hv = fmaf(q0.z, W1O[2 * 32 + m], hv);
        hv = fmaf(q0.w, W1O[3 * 32 + m], hv);
        hv = fmaf(q1.x, W1O[4 * 32 + m], hv);
        hv = fmaf(q1.y, W1O[5 * 32 + m], hv);
        hv = fmaf(q1.z, W1O[6 * 32 + m], hv);
        hv = fmaf(q1.w, W1O[7 * 32 + m], hv);
        hv = hv > 0.f ? hv : expm1f(hv);
        // wf layer 2
        const float* H2 = &sm[sg + S_H2 + p * 64];
        float wf = sm[OFF_WFB2 + m];
        #pragma unroll 4
        for (int k0 = 0; k0 < 64; k0 += 4) {
            float4 h4 = *reinterpret_cast<const float4*>(&H2[k0]);
            wf = fmaf(h4.x, sm[OFF_WFB + (k0    ) * 32 + m], wf);
            wf = fmaf(h4.y, sm[OFF_WFB + (k0 + 1) * 32 + m], wf);
            wf = fmaf(h4.z, sm[OFF_WFB + (k0 + 2) * 32 + m], wf);
            wf = fmaf(h4.w, sm[OFF_WFB + (k0 + 3) * 32 + m], wf);
        }
        wf = fabsf(wf);
        float part = hv * wf + sm[sg + S_H3 + p * 32 + m] * sm[OFF_VW2 + m];
        #pragma unroll
        for (int off = 16; off > 0; off >>= 1)
            part += __shfl_down_sync(0xffffffffu, part, off);
        if (m == 0) out[gp0 + p] = part + sm[OFF_VB2];
    }
    #undef GBAR
}

extern "C" void kernel_launch(void* const* d_in, const int* in_sizes, int n_in,
                              void* d_out, int out_size) {
    (void)in_sizes; (void)n_in; (void)out_size;
    precompute_kernel<<<16, 256>>>(
        (const float*)d_in[7], (const float*)d_in[9], (const float*)d_in[10]);
    cudaFuncSetAttribute(qmixer_kernel,
                         cudaFuncAttributeMaxDynamicSharedMemorySize, SMEM_BYTES);
    qmixer_kernel<<<GRID, NTH, SMEM_BYTES>>>(
        (const float*)d_in[0],  (const float*)d_in[1],  (const float*)d_in[2],
        (const float*)d_in[3],  (const float*)d_in[4],
        (const float*)d_in[5],  (const float*)d_in[6],
        (const float*)d_in[11], (const float*)d_in[12],
        (const float*)d_in[13], (const float*)d_in[14],
        (const float*)d_in[15], (const float*)d_in[16],
        (const float*)d_in[17], (const float*)d_in[18],
        (const float*)d_in[19], (const float*)d_in[20],
        (const float*)d_in[21], (const float*)d_in[22],
        (const float*)d_in[23], (const float*)d_in[24],
        (float*)d_out);
}

// round 6
// speedup vs baseline: 3.8295x; 1.1305x over previous
#include <cuda_runtime.h>
#include <math.h>

// QMixer forward on GB300 — round 6.
// Algebra: M = Wq Wk^T/sqrt(Da), u = Wq bk/sqrt(Da) (softmax over query axis).
// 4096 CTAs x 256 thr, 4 pairs per CTA, 3 CTAs/SM (smem ~72.6KB).
// Hot lane-distinct weights (WAL/WEN/M) in SMEM; streaming weights via LDG/L2.

namespace {

constexpr int NTH   = 256;
constexpr int BSTOT = 16384;
constexpr int GRID  = BSTOT / 4;   // 4096

// ---- smem weight region, float offsets ----
constexpr int OFF_WAL  = 0;        // 32*64
constexpr int OFF_WEN  = 2048;     // 16*64
constexpr int OFF_M    = 3072;     // 64*64
constexpr int OFF_U    = 7168;     // 64
constexpr int OFF_BAL  = 7232;     // 64
constexpr int OFF_BEN  = 7296;     // 64
constexpr int OFF_W1B2 = 7360;     // 32
constexpr int OFF_WFB2 = 7392;     // 32
constexpr int OFF_BCAT = 7424;     // 192 [w1_b1 | wf_b1 | hb_b | v_b1]
constexpr int OFF_VW2  = 7616;     // 32
constexpr int OFF_VB2  = 7648;     // 1
constexpr int W_TOT_AL = 7664;

// ---- scratch (float offsets) ----
// Union U1 (4352): FEAT (A/B) -> ZT (Z/E) -> {C,H2,HBP,H3,SH,W1O}
constexpr int S_U1    = W_TOT_AL;        // 4352
constexpr int S_FEAT  = S_U1;            //      [p*512+e*32+f]
constexpr int S_ZT    = S_U1;            //      [p*1088+c*17+e]
constexpr int S_C     = S_U1;            // 256  [p*64+hu]
constexpr int S_H2    = S_U1 + 256;      // 256  [p*64+r]
constexpr int S_HBP   = S_U1 + 512;      // 128  [p*32+m]
constexpr int S_H3    = S_U1 + 640;      // 128  [p*32+m]
constexpr int S_SH    = S_U1 + 768;      // 2048 [p*512+a*64+hu]
constexpr int S_W1O   = S_U1 + 2816;     // 1024 [p*256+a*32+m]
constexpr int S_AQ    = S_U1 + 4352;     // 32   [p*8+a]
constexpr int S_ENTT  = S_AQ + 32;       // 5120 [p*1280+d*20+e]
constexpr int S_EM    = S_ENTT + 5120;   // 1088 [p*272+i*17+j]
constexpr int S_AMEAN = S_EM + 1088;     // 64   [p*16+e]
constexpr int S_AOT   = S_AMEAN + 64;    // 256  [d*4+p]; XU (64) overlays (dead before AOT write)
constexpr int S_XU    = S_AOT;           // 64   [p*16+e]
constexpr int SMEM_FLOATS = S_AOT + 256;

constexpr int SMEM_BYTES  = SMEM_FLOATS * 4;     // 74304 B
static_assert(3 * SMEM_BYTES <= 232448, "3 CTAs must fit");

constexpr float INVS = 0.08838834764831845f;     // 1/sqrt(128)

typedef unsigned long long ull;
__device__ __forceinline__ ull pk(float a, float b) {
    ull r; asm("mov.b64 %0,{%1,%2};" : "=l"(r) : "f"(a), "f"(b)); return r;
}
__device__ __forceinline__ void fma2(ull& acc, ull a, ull b) {
    asm("fma.rn.f32x2 %0,%1,%2,%0;" : "+l"(acc) : "l"(a), "l"(b));
}
__device__ __forceinline__ float2 unpk(ull v) {
    float2 f; asm("mov.b64 {%0,%1},%2;" : "=f"(f.x), "=f"(f.y) : "l"(v)); return f;
}

__device__ float g_M[64 * 64];
__device__ float g_U[64];
__device__ float g_WCAT[64 * 192];   // [w1_W1 rows0-63 | wf_W1 | hb_W | v_W1]

} // namespace

// ------------- precompute: M, u, WCAT -------------
__global__ void precompute_kernel(const float* __restrict__ Wq,
                                  const float* __restrict__ Wk,
                                  const float* __restrict__ bk,
                                  const float* __restrict__ w1W1,
                                  const float* __restrict__ wfW1,
                                  const float* __restrict__ hbW,
                                  const float* __restrict__ vW1) {
    int t = threadIdx.x;                 // 256
    int d = blockIdx.x * 4 + (t >> 6);
    int c = t & 63;
    float s = 0.f;
    #pragma unroll 8
    for (int k = 0; k < 128; ++k)
        s = fmaf(Wq[d * 128 + k], Wk[c * 128 + k], s);
    g_M[d * 64 + c] = s * INVS;
    if (blockIdx.x == 0 && t < 64) {
        float su = 0.f;
        #pragma unroll 8
        for (int k = 0; k < 128; ++k)
            su = fmaf(Wq[t * 128 + k], bk[k], su);
        g_U[t] = su * INVS;
    }
    // WCAT: 12288 elements over 16 blocks x 256 threads x 3
    for (int i = blockIdx.x * NTH + t; i < 64 * 192; i += 16 * NTH) {
        int f = i / 192, cc = i % 192;
        float v;
        if (cc < 64)       v = w1W1[f * 64 + cc];
        else if (cc < 128) v = wfW1[f * 64 + cc - 64];
        else if (cc < 160) v = hbW[f * 32 + cc - 128];
        else               v = vW1[f * 32 + cc - 160];
        g_WCAT[i] = v;
    }
}

// ------------- main kernel -------------
__global__ void __launch_bounds__(NTH, 3) qmixer_kernel(
    const float* __restrict__ g_aq,     // [B,S,8]
    const float* __restrict__ g_ally,   // [8,B,S,32]
    const float* __restrict__ g_enemy,  // [8,B,S,16]
    const float* __restrict__ g_Wal,  const float* __restrict__ g_bal,
    const float* __restrict__ g_Wen,  const float* __restrict__ g_ben,
    const float* __restrict__ g_w1W1, const float* __restrict__ g_w1b1,
    const float* __restrict__ g_w1W2, const float* __restrict__ g_w1b2,
    const float* __restrict__ g_wfb1,
    const float* __restrict__ g_wfW2, const float* __restrict__ g_wfb2,
    const float* __restrict__ g_hbb,
    const float* __restrict__ g_vb1,
    const float* __restrict__ g_vW2,  const float* __restrict__ g_vb2,
    float* __restrict__ out)
{
    extern __shared__ float sm[];
    const int t = threadIdx.x;
    const int gp0 = blockIdx.x * 4;
    const float* __restrict__ g_W1A2 = g_w1W1 + 4096;   // rows 64..127

    // ---- stage smem weights ----
    {
        auto cp4 = [&](int off, const float* src, int n) {
            const float4* s4 = reinterpret_cast<const float4*>(src);
            float4* d4 = reinterpret_cast<float4*>(&sm[off]);
            for (int i = t; i < n / 4; i += NTH) d4[i] = s4[i];
        };
        cp4(OFF_WAL,  g_Wal,  2048);
        cp4(OFF_WEN,  g_Wen,  1024);
        cp4(OFF_M,    g_M,    4096);
        cp4(OFF_U,    g_U,    64);
        cp4(OFF_BAL,  g_bal,  64);
        cp4(OFF_BEN,  g_ben,  64);
        cp4(OFF_W1B2, g_w1b2, 32);
        cp4(OFF_WFB2, g_wfb2, 32);
        cp4(OFF_VW2,  g_vW2,  32);
        if (t < 192) {
            float b;
            if (t < 64)       b = g_w1b1[t];
            else if (t < 128) b = g_wfb1[t - 64];
            else if (t < 160) b = g_hbb[t - 128];
            else              b = g_vb1[t - 160];
            sm[OFF_BCAT + t] = b;
        }
        if (t == 0) sm[OFF_VB2] = g_vb2[0];
    }

    // ================= Phase A: load 4 pairs' inputs (no barrier needed yet) =
    {
        int p = t >> 6, e = (t >> 3) & 7, f4 = t & 7;
        reinterpret_cast<float4*>(&sm[S_FEAT + p * 512 + e * 32])[f4] =
            reinterpret_cast<const float4*>(&g_ally[(e * BSTOT + gp0 + p) * 32])[f4];
        if (t < 128) {
            int pp = t >> 5, ee = (t >> 2) & 7, ff4 = t & 3;
            reinterpret_cast<float4*>(&sm[S_FEAT + pp * 512 + (8 + ee) * 32])[ff4] =
                reinterpret_cast<const float4*>(&g_enemy[(ee * BSTOT + gp0 + pp) * 16])[ff4];
        }
        if (t < 32) {
            int pp = t >> 3, a = t & 7;
            sm[S_AQ + pp * 8 + a] = g_aq[(gp0 + pp) * 8 + a];
        }
    }
    __syncthreads();

    // ================= Phase B: embeddings -> ENTT[p][d*20+e] ==============
    {
        int p = t >> 6, d = t & 63;
        float acc[16];
        float ba = sm[OFF_BAL + d], be = sm[OFF_BEN + d];
        #pragma unroll
        for (int e = 0; e < 8; ++e) { acc[e] = ba; acc[8 + e] = be; }
        const float* FEAT = &sm[S_FEAT + p * 512];
        #pragma unroll
        for (int f4 = 0; f4 < 8; ++f4) {
            int f = f4 * 4;
            float w0 = sm[OFF_WAL + f * 64 + d];
            float w1 = sm[OFF_WAL + (f + 1) * 64 + d];
            float w2 = sm[OFF_WAL + (f + 2) * 64 + d];
            float w3 = sm[OFF_WAL + (f + 3) * 64 + d];
            #pragma unroll
            for (int e = 0; e < 8; ++e) {
                float4 x = *reinterpret_cast<const float4*>(&FEAT[e * 32 + f]);
                acc[e] = fmaf(x.x, w0, acc[e]);
                acc[e] = fmaf(x.y, w1, acc[e]);
                acc[e] = fmaf(x.z, w2, acc[e]);
                acc[e] = fmaf(x.w, w3, acc[e]);
            }
        }
        #pragma unroll
        for (int f4 = 0; f4 < 4; ++f4) {
            int f = f4 * 4;
            float w0 = sm[OFF_WEN + f * 64 + d];
            float w1 = sm[OFF_WEN + (f + 1) * 64 + d];
            float w2 = sm[OFF_WEN + (f + 2) * 64 + d];
            float w3 = sm[OFF_WEN + (f + 3) * 64 + d];
            #pragma unroll
            for (int e = 0; e < 8; ++e) {
                float4 x = *reinterpret_cast<const float4*>(&FEAT[(8 + e) * 32 + f]);
                acc[8+e] = fmaf(x.x, w0, acc[8+e]);
                acc[8+e] = fmaf(x.y, w1, acc[8+e]);
                acc[8+e] = fmaf(x.z, w2, acc[8+e]);
                acc[8+e] = fmaf(x.w, w3, acc[8+e]);
            }
        }
        float* er = &sm[S_ENTT + p * 1280 + d * 20];
        *reinterpret_cast<float4*>(&er[0])  = make_float4(acc[0], acc[1], acc[2], acc[3]);
        *reinterpret_cast<float4*>(&er[4])  = make_float4(acc[4], acc[5], acc[6], acc[7]);
        *reinterpret_cast<float4*>(&er[8])  = make_float4(acc[8], acc[9], acc[10], acc[11]);
        *reinterpret_cast<float4*>(&er[12]) = make_float4(acc[12], acc[13], acc[14], acc[15]);
    }
    __syncthreads();

    // ================= Phase Z: Z = X^T M  -> Zt[p][c*17+e] ================
    {
        int p = t >> 6, r = t & 63;
        int e0 = (r >> 4) * 4, c0 = (r & 15) * 4;
        ull acc[4][2];
        #pragma unroll
        for (int e = 0; e < 4; ++e) { acc[e][0] = 0ull; acc[e][1] = 0ull; }
        const float* X = &sm[S_ENTT + p * 1280 + e0];
        const float* M = &sm[OFF_M + c0];
        #pragma unroll 4
        for (int d = 0; d < 64; ++d) {
            float4 m4 = *reinterpret_cast<const float4*>(M + d * 64);
            float4 x4 = *reinterpret_cast<const float4*>(X + d * 20);
            ull mp0 = pk(m4.x, m4.y), mp1 = pk(m4.z, m4.w);
            ull xs0 = pk(x4.x, x4.x), xs1 = pk(x4.y, x4.y);
            ull xs2 = pk(x4.z, x4.z), xs3 = pk(x4.w, x4.w);
            fma2(acc[0][0], xs0, mp0); fma2(acc[0][1], xs0, mp1);
            fma2(acc[1][0], xs1, mp0); fma2(acc[1][1], xs1, mp1);
            fma2(acc[2][0], xs2, mp0); fma2(acc[2][1], xs2, mp1);
            fma2(acc[3][0], xs3, mp0); fma2(acc[3][1], xs3, mp1);
        }
        float* Zt = &sm[S_ZT + p * 1088];
        #pragma unroll
        for (int e = 0; e < 4; ++e) {
            float2 v0 = unpk(acc[e][0]), v1 = unpk(acc[e][1]);
            Zt[(c0    ) * 17 + e0 + e] = v0.x;
            Zt[(c0 + 1) * 17 + e0 + e] = v0.y;
            Zt[(c0 + 2) * 17 + e0 + e] = v1.x;
            Zt[(c0 + 3) * 17 + e0 + e] = v1.y;
        }
    }
    __syncthreads();

    // ================= Phase E: E[i][j] = Z[i]·x_j ; spare threads: xu ======
    if (t < 128) {
        int p = t >> 5, q = t & 31;
        int i0 = (q >> 2) * 2, j0 = (q & 3) * 4;
        const float* Zt = &sm[S_ZT + p * 1088];
        const float* X  = &sm[S_ENTT + p * 1280 + j0];
        ull acc[2][2];
        acc[0][0] = acc[0][1] = acc[1][0] = acc[1][1] = 0ull;
        #pragma unroll 4
        for (int c = 0; c < 64; ++c) {
            float z0 = Zt[c * 17 + i0];
            float z1 = Zt[c * 17 + i0 + 1];
            float4 x4 = *reinterpret_cast<const float4*>(X + c * 20);
            ull xp0 = pk(x4.x, x4.y), xp1 = pk(x4.z, x4.w);
            ull zs0 = pk(z0, z0), zs1 = pk(z1, z1);
            fma2(acc[0][0], zs0, xp0); fma2(acc[0][1], zs0, xp1);
            fma2(acc[1][0], zs1, xp0); fma2(acc[1][1], zs1, xp1);
        }
        float* E = &sm[S_EM + p * 272];
        #pragma unroll
        for (int ii = 0; ii < 2; ++ii) {
            float2 v0 = unpk(acc[ii][0]), v1 = unpk(acc[ii][1]);
            E[(i0 + ii) * 17 + j0]     = v0.x;
            E[(i0 + ii) * 17 + j0 + 1] = v0.y;
            E[(i0 + ii) * 17 + j0 + 2] = v1.x;
            E[(i0 + ii) * 17 + j0 + 3] = v1.y;
        }
    } else if (t < 192) {
        int idx = t - 128;
        int p = idx >> 4, e = idx & 15;
        const float* X = &sm[S_ENTT + p * 1280 + e];
        float s = 0.f;
        #pragma unroll 8
        for (int d = 0; d < 64; ++d)
            s = fmaf(X[d * 20], sm[OFF_U + d], s);
        sm[S_XU + p * 16 + e] = s;
    }
    __syncthreads();

    // ================= softmax over i (per column j) + amean ================
    if (t < 64) {
        int p = t >> 4, j = t & 15;
        float* E = &sm[S_EM + p * 272];
        const float* XU = &sm[S_XU + p * 16];
        float col[16];
        #pragma unroll
        for (int i = 0; i < 16; ++i) col[i] = E[i * 17 + j] + XU[i];
        float mx = col[0];
        #pragma unroll
        for (int i = 1; i < 16; ++i) mx = fmaxf(mx, col[i]);
        float ssum = 0.f;
        #pragma unroll
        for (int i = 0; i < 16; ++i) { col[i] = __expf(col[i] - mx); ssum += col[i]; }
        float inv = 1.0f / ssum;
        #pragma unroll
        for (int i = 0; i < 16; ++i) E[i * 17 + j] = col[i] * inv;
        __syncwarp();
        int i = j;
        const float* Er = &sm[S_EM + p * 272 + i * 17];
        float s = 0.f;
        #pragma unroll
        for (int jj = 0; jj < 16; ++jj) s += Er[jj];
        sm[S_AMEAN + p * 16 + i] = s * 0.0625f;
    }
    __syncthreads();

    // ================= attn_out -> AOT[d*4+p] (overlays XU, now dead) =======
    {
        int p = t >> 6, d = t & 63;
        const float* X = &sm[S_ENTT + p * 1280 + d * 20];
        const float* AM = &sm[S_AMEAN + p * 16];
        float4 x0 = *reinterpret_cast<const float4*>(X);
        float4 x1 = *reinterpret_cast<const float4*>(X + 4);
        float4 x2 = *reinterpret_cast<const float4*>(X + 8);
        float4 x3 = *reinterpret_cast<const float4*>(X + 12);
        float4 a0 = *reinterpret_cast<const float4*>(AM);
        float4 a1 = *reinterpret_cast<const float4*>(AM + 4);
        float4 a2 = *reinterpret_cast<const float4*>(AM + 8);
        float4 a3 = *reinterpret_cast<const float4*>(AM + 12);
        float s = x0.x*a0.x + x0.y*a0.y + x0.z*a0.z + x0.w*a0.w
                + x1.x*a1.x + x1.y*a1.y + x1.z*a1.z + x1.w*a1.w
                + x2.x*a2.x + x2.y*a2.y + x2.z*a2.z + x2.w*a2.w
                + x3.x*a3.x + x3.y*a3.y + x3.z*a3.z + x3.w*a3.w;
        __syncthreads();   // XU reads done before overlay write
        sm[S_AOT + d * 4 + p] = s;
    }
    __syncthreads();

    // ================= AOG: all attn_out projections (weights via LDG) =====
    if (t < 192) {
        const int col = t;
        const float* __restrict__ WC = &g_WCAT[col];
        const float* AOT = &sm[S_AOT];
        float a0 = 0.f, a1 = 0.f, a2 = 0.f, a3 = 0.f;
        #pragma unroll 8
        for (int f = 0; f < 64; ++f) {
            float w = __ldg(&WC[f * 192]);
            float4 ao = *reinterpret_cast<const float4*>(&AOT[f * 4]);
            a0 = fmaf(w, ao.x, a0);
            a1 = fmaf(w, ao.y, a1);
            a2 = fmaf(w, ao.z, a2);
            a3 = fmaf(w, ao.w, a3);
        }
        float b = sm[OFF_BCAT + col];
        a0 += b; a1 += b; a2 += b; a3 += b;
        if (col < 64) {
            sm[S_C +   0 + col] = a0;
            sm[S_C +  64 + col] = a1;
            sm[S_C + 128 + col] = a2;
            sm[S_C + 192 + col] = a3;
        } else if (col < 128) {
            int r = col - 64;
            sm[S_H2 +   0 + r] = fmaxf(a0, 0.f);
            sm[S_H2 +  64 + r] = fmaxf(a1, 0.f);
            sm[S_H2 + 128 + r] = fmaxf(a2, 0.f);
            sm[S_H2 + 192 + r] = fmaxf(a3, 0.f);
        } else if (col < 160) {
            int m = col - 128;
            sm[S_HBP +  0 + m] = a0;
            sm[S_HBP + 32 + m] = a1;
            sm[S_HBP + 64 + m] = a2;
            sm[S_HBP + 96 + m] = a3;
        } else {
            int m = col - 160;
            sm[S_H3 +  0 + m] = fmaxf(a0, 0.f);
            sm[S_H3 + 32 + m] = fmaxf(a1, 0.f);
            sm[S_H3 + 64 + m] = fmaxf(a2, 0.f);
            sm[S_H3 + 96 + m] = fmaxf(a3, 0.f);
        }
    }
    __syncthreads();

    // ================= SH2: s_h = relu(C + x_a @ W1A2) (W1A2 via LDG) ======
    {
        int p = t >> 6, r = t & 63;
        int ap = r & 3;
        int hu0 = (r >> 2) * 4;
        ull acc[4];
        const float* C = &sm[S_C + p * 64];
        #pragma unroll
        for (int j = 0; j < 4; ++j) { float c = C[hu0 + j]; acc[j] = pk(c, c); }
        const float* __restrict__ W = &g_W1A2[hu0];
        const float* X = &sm[S_ENTT + p * 1280 + 2 * ap];
        #pragma unroll 4
        for (int f = 0; f < 64; ++f) {
            float4 w4 = __ldg(reinterpret_cast<const float4*>(&W[f * 64]));
            ull xp = *reinterpret_cast<const ull*>(&X[f * 20]);
            fma2(acc[0], xp, pk(w4.x, w4.x));
            fma2(acc[1], xp, pk(w4.y, w4.y));
            fma2(acc[2], xp, pk(w4.z, w4.z));
            fma2(acc[3], xp, pk(w4.w, w4.w));
        }
        float* SH = &sm[S_SH + p * 512];
        #pragma unroll
        for (int j = 0; j < 4; ++j) {
            float2 v = unpk(acc[j]);
            SH[(2 * ap)     * 64 + hu0 + j] = fmaxf(v.x, 0.f);
            SH[(2 * ap + 1) * 64 + hu0 + j] = fmaxf(v.y, 0.f);
        }
    }
    __syncthreads();

    // ================= W1O: w1[a][m] = |SH[a] @ w1_W2 + b2| (LDG) ==========
    {
        int p = t >> 6, r = t & 63;
        int a = r >> 3, m0 = (r & 7) * 4;
        ull acc0 = pk(sm[OFF_W1B2 + m0],     sm[OFF_W1B2 + m0 + 1]);
        ull acc1 = pk(sm[OFF_W1B2 + m0 + 2], sm[OFF_W1B2 + m0 + 3]);
        const float* SH = &sm[S_SH + p * 512 + a * 64];
        const float* __restrict__ W = &g_w1W2[m0];
        #pragma unroll 4
        for (int k0 = 0; k0 < 64; k0 += 4) {
            float4 s4 = *reinterpret_cast<const float4*>(&SH[k0]);
            #pragma unroll
            for (int j = 0; j < 4; ++j) {
                float4 w4 = __ldg(reinterpret_cast<const float4*>(&W[(k0 + j) * 32]));
                float sv = (&s4.x)[j];
                ull ss = pk(sv, sv);
                fma2(acc0, ss, pk(w4.x, w4.y));
                fma2(acc1, ss, pk(w4.z, w4.w));
            }
        }
        float2 v0 = unpk(acc0), v1 = unpk(acc1);
        *reinterpret_cast<float4*>(&sm[S_W1O + p * 256 + a * 32 + m0]) =
            make_float4(fabsf(v0.x), fabsf(v0.y), fabsf(v1.x), fabsf(v1.y));
    }
    __syncthreads();

    // ================= hidden + final (fused, wf_W2 via LDG) ===============
    if (t < 128) {
        int p = t >> 5, m = t & 31;
        float hv = sm[S_HBP + p * 32 + m];
        const float* W1O = &sm[S_W1O + p * 256];
        const float* AQ  = &sm[S_AQ + p * 8];
        float4 q0 = *reinterpret_cast<const float4*>(&AQ[0]);
        float4 q1 = *reinterpret_cast<const float4*>(&AQ[4]);
        hv = fmaf(q0.x, W1O[0 * 32 + m], hv);
        hv = fmaf(q0.y, W1O[1 * 32 + m], hv);
        hv = fmaf(q0.z, W1O[2 * 32 + m], hv);
        hv = fmaf(q0.w, W1O[3 * 32 + m], hv);
        hv = fmaf(q1.x, W1O[4 * 32 + m], hv);
        hv = fmaf(q1.y, W1O[5 * 32 + m], hv);
        hv = fmaf(q1.z, W1O[6 * 32 + m], hv);
        hv = fmaf(q1.w, W1O[7 * 32 + m], hv);
        hv = hv > 0.f ? hv : expm1f(hv);
        const float* H2 = &sm[S_H2 + p * 64];
        float wf = sm[OFF_WFB2 + m];
        #pragma unroll 4
        for (int k0 = 0; k0 < 64; k0 += 4) {
            float4 h4 = *reinterpret_cast<const float4*>(&H2[k0]);
            wf = fmaf(h4.x, __ldg(&g_wfW2[(k0    ) * 32 + m]), wf);
            wf = fmaf(h4.y, __ldg(&g_wfW2[(k0 + 1) * 32 + m]), wf);
            wf = fmaf(h4.z, __ldg(&g_wfW2[(k0 + 2) * 32 + m]), wf);
            wf = fmaf(h4.w, __ldg(&g_wfW2[(k0 + 3) * 32 + m]), wf);
        }
        wf = fabsf(wf);
        float part = hv * wf + sm[S_H3 + p * 32 + m] * sm[OFF_VW2 + m];
        #pragma unroll
        for (int off = 16; off > 0; off >>= 1)
            part += __shfl_down_sync(0xffffffffu, part, off);
        if (m == 0) out[gp0 + p] = part + sm[OFF_VB2];
    }
}

extern "C" void kernel_launch(void* const* d_in, const int* in_sizes, int n_in,
                              void* d_out, int out_size) {
    (void)in_sizes; (void)n_in; (void)out_size;
    // inputs: 0 aq, 1 ally, 2 enemy, 3 W_al, 4 b_al, 5 W_en, 6 b_en,
    // 7 Wq, 8 bq, 9 Wk, 10 bk, 11 w1_W1, 12 w1_b1, 13 w1_W2, 14 w1_b2,
    // 15 wf_W1, 16 wf_b1, 17 wf_W2, 18 wf_b2, 19 hb_W, 20 hb_b,
    // 21 v_W1, 22 v_b1, 23 v_W2, 24 v_b2
    precompute_kernel<<<16, 256>>>(
        (const float*)d_in[7],  (const float*)d_in[9],  (const float*)d_in[10],
        (const float*)d_in[11], (const float*)d_in[15],
        (const float*)d_in[19], (const float*)d_in[21]);
    cudaFuncSetAttribute(qmixer_kernel,
                         cudaFuncAttributeMaxDynamicSharedMemorySize, SMEM_BYTES);
    qmixer_kernel<<<GRID, NTH, SMEM_BYTES>>>(
        (const float*)d_in[0],  (const float*)d_in[1],  (const float*)d_in[2],
        (const float*)d_in[3],  (const float*)d_in[4],
        (const float*)d_in[5],  (const float*)d_in[6],
        (const float*)d_in[11], (const float*)d_in[12],
        (const float*)d_in[13], (const float*)d_in[14],
        (const float*)d_in[16],
        (const float*)d_in[17], (const float*)d_in[18],
        (const float*)d_in[20],
        (const float*)d_in[22],
        (const float*)d_in[23], (const float*)d_in[24],
        (float*)d_out);
}

// round 7
// speedup vs baseline: 4.2582x; 1.1119x over previous
#include <cuda_runtime.h>
#include <math.h>

// QMixer forward on GB300 — round 7.
// Algebra: M = Wq Wk^T/sqrt(Da), u = Wq bk/sqrt(Da) (softmax over query axis).
// 4096 CTAs x 256 thr, 4 pairs per CTA, 3 CTAs/SM.
// Round-7: pair-reuse of streaming-weight LDGs in SH2/W1O/final (2 pairs per
// thread) to cut L1tex wavefronts (L1 was 87% saturated).

namespace {

constexpr int NTH   = 256;
constexpr int BSTOT = 16384;
constexpr int GRID  = BSTOT / 4;   // 4096

// ---- smem weight region, float offsets ----
constexpr int OFF_WAL  = 0;        // 32*64
constexpr int OFF_WEN  = 2048;     // 16*64
constexpr int OFF_M    = 3072;     // 64*64
constexpr int OFF_U    = 7168;     // 64
constexpr int OFF_BAL  = 7232;     // 64
constexpr int OFF_BEN  = 7296;     // 64
constexpr int OFF_W1B2 = 7360;     // 32
constexpr int OFF_WFB2 = 7392;     // 32
constexpr int OFF_BCAT = 7424;     // 192 [w1_b1 | wf_b1 | hb_b | v_b1]
constexpr int OFF_VW2  = 7616;     // 32
constexpr int OFF_VB2  = 7648;     // 1
constexpr int W_TOT_AL = 7664;

// ---- scratch (float offsets) ----
constexpr int S_U1    = W_TOT_AL;        // 4352 union
constexpr int S_FEAT  = S_U1;            //      [p*512+e*32+f]
constexpr int S_ZT    = S_U1;            //      [p*1088+c*17+e]
constexpr int S_C     = S_U1;            // 256  [p*64+hu]
constexpr int S_H2    = S_U1 + 256;      // 256  [p*64+r]
constexpr int S_HBP   = S_U1 + 512;      // 128  [p*32+m]
constexpr int S_H3    = S_U1 + 640;      // 128  [p*32+m]
constexpr int S_SH    = S_U1 + 768;      // 2048 [p*512+a*64+hu]
constexpr int S_W1O   = S_U1 + 2816;     // 1024 [p*256+a*32+m]
constexpr int S_AQ    = S_U1 + 4352;     // 32   [p*8+a]
constexpr int S_ENTT  = S_AQ + 32;       // 5120 [p*1280+d*20+e]
constexpr int S_EM    = S_ENTT + 5120;   // 1088 [p*272+i*17+j]
constexpr int S_AMEAN = S_EM + 1088;     // 64   [p*16+e]
constexpr int S_AOT   = S_AMEAN + 64;    // 256  [d*4+p]; XU overlays
constexpr int S_XU    = S_AOT;           // 64   [p*16+e]
constexpr int SMEM_FLOATS = S_AOT + 256;

constexpr int SMEM_BYTES  = SMEM_FLOATS * 4;     // 74304 B
static_assert(3 * SMEM_BYTES <= 232448, "3 CTAs must fit");

constexpr float INVS = 0.08838834764831845f;     // 1/sqrt(128)

typedef unsigned long long ull;
__device__ __forceinline__ ull pk(float a, float b) {
    ull r; asm("mov.b64 %0,{%1,%2};" : "=l"(r) : "f"(a), "f"(b)); return r;
}
__device__ __forceinline__ void fma2(ull& acc, ull a, ull b) {
    asm("fma.rn.f32x2 %0,%1,%2,%0;" : "+l"(acc) : "l"(a), "l"(b));
}
__device__ __forceinline__ float2 unpk(ull v) {
    float2 f; asm("mov.b64 {%0,%1},%2;" : "=f"(f.x), "=f"(f.y) : "l"(v)); return f;
}

__device__ float g_M[64 * 64];
__device__ float g_U[64];
__device__ float g_WCAT[64 * 192];   // [w1_W1 rows0-63 | wf_W1 | hb_W | v_W1]

} // namespace

// ------------- precompute: M, u, WCAT -------------
__global__ void precompute_kernel(const float* __restrict__ Wq,
                                  const float* __restrict__ Wk,
                                  const float* __restrict__ bk,
                                  const float* __restrict__ w1W1,
                                  const float* __restrict__ wfW1,
                                  const float* __restrict__ hbW,
                                  const float* __restrict__ vW1) {
    int t = threadIdx.x;                 // 256
    int d = blockIdx.x * 4 + (t >> 6);
    int c = t & 63;
    float s = 0.f;
    #pragma unroll 8
    for (int k = 0; k < 128; ++k)
        s = fmaf(Wq[d * 128 + k], Wk[c * 128 + k], s);
    g_M[d * 64 + c] = s * INVS;
    if (blockIdx.x == 0 && t < 64) {
        float su = 0.f;
        #pragma unroll 8
        for (int k = 0; k < 128; ++k)
            su = fmaf(Wq[t * 128 + k], bk[k], su);
        g_U[t] = su * INVS;
    }
    for (int i = blockIdx.x * NTH + t; i < 64 * 192; i += 16 * NTH) {
        int f = i / 192, cc = i % 192;
        float v;
        if (cc < 64)       v = w1W1[f * 64 + cc];
        else if (cc < 128) v = wfW1[f * 64 + cc - 64];
        else if (cc < 160) v = hbW[f * 32 + cc - 128];
        else               v = vW1[f * 32 + cc - 160];
        g_WCAT[i] = v;
    }
}

// ------------- main kernel -------------
__global__ void __launch_bounds__(NTH, 3) qmixer_kernel(
    const float* __restrict__ g_aq,     // [B,S,8]
    const float* __restrict__ g_ally,   // [8,B,S,32]
    const float* __restrict__ g_enemy,  // [8,B,S,16]
    const float* __restrict__ g_Wal,  const float* __restrict__ g_bal,
    const float* __restrict__ g_Wen,  const float* __restrict__ g_ben,
    const float* __restrict__ g_w1W1, const float* __restrict__ g_w1b1,
    const float* __restrict__ g_w1W2, const float* __restrict__ g_w1b2,
    const float* __restrict__ g_wfb1,
    const float* __restrict__ g_wfW2, const float* __restrict__ g_wfb2,
    const float* __restrict__ g_hbb,
    const float* __restrict__ g_vb1,
    const float* __restrict__ g_vW2,  const float* __restrict__ g_vb2,
    float* __restrict__ out)
{
    extern __shared__ float sm[];
    const int t = threadIdx.x;
    const int gp0 = blockIdx.x * 4;
    const float* __restrict__ g_W1A2 = g_w1W1 + 4096;   // rows 64..127

    // ---- stage smem weights ----
    {
        auto cp4 = [&](int off, const float* src, int n) {
            const float4* s4 = reinterpret_cast<const float4*>(src);
            float4* d4 = reinterpret_cast<float4*>(&sm[off]);
            for (int i = t; i < n / 4; i += NTH) d4[i] = s4[i];
        };
        cp4(OFF_WAL,  g_Wal,  2048);
        cp4(OFF_WEN,  g_Wen,  1024);
        cp4(OFF_M,    g_M,    4096);
        cp4(OFF_U,    g_U,    64);
        cp4(OFF_BAL,  g_bal,  64);
        cp4(OFF_BEN,  g_ben,  64);
        cp4(OFF_W1B2, g_w1b2, 32);
        cp4(OFF_WFB2, g_wfb2, 32);
        cp4(OFF_VW2,  g_vW2,  32);
        if (t < 192) {
            float b;
            if (t < 64)       b = g_w1b1[t];
            else if (t < 128) b = g_wfb1[t - 64];
            else if (t < 160) b = g_hbb[t - 128];
            else              b = g_vb1[t - 160];
            sm[OFF_BCAT + t] = b;
        }
        if (t == 0) sm[OFF_VB2] = g_vb2[0];
    }

    // ================= Phase A: load 4 pairs' inputs ========================
    {
        int p = t >> 6, e = (t >> 3) & 7, f4 = t & 7;
        reinterpret_cast<float4*>(&sm[S_FEAT + p * 512 + e * 32])[f4] =
            reinterpret_cast<const float4*>(&g_ally[(e * BSTOT + gp0 + p) * 32])[f4];
        if (t < 128) {
            int pp = t >> 5, ee = (t >> 2) & 7, ff4 = t & 3;
            reinterpret_cast<float4*>(&sm[S_FEAT + pp * 512 + (8 + ee) * 32])[ff4] =
                reinterpret_cast<const float4*>(&g_enemy[(ee * BSTOT + gp0 + pp) * 16])[ff4];
        }
        if (t < 32) {
            int pp = t >> 3, a = t & 7;
            sm[S_AQ + pp * 8 + a] = g_aq[(gp0 + pp) * 8 + a];
        }
    }
    __syncthreads();

    // ================= Phase B: embeddings -> ENTT[p][d*20+e] ==============
    {
        int p = t >> 6, d = t & 63;
        float acc[16];
        float ba = sm[OFF_BAL + d], be = sm[OFF_BEN + d];
        #pragma unroll
        for (int e = 0; e < 8; ++e) { acc[e] = ba; acc[8 + e] = be; }
        const float* FEAT = &sm[S_FEAT + p * 512];
        #pragma unroll
        for (int f4 = 0; f4 < 8; ++f4) {
            int f = f4 * 4;
            float w0 = sm[OFF_WAL + f * 64 + d];
            float w1 = sm[OFF_WAL + (f + 1) * 64 + d];
            float w2 = sm[OFF_WAL + (f + 2) * 64 + d];
            float w3 = sm[OFF_WAL + (f + 3) * 64 + d];
            #pragma unroll
            for (int e = 0; e < 8; ++e) {
                float4 x = *reinterpret_cast<const float4*>(&FEAT[e * 32 + f]);
                acc[e] = fmaf(x.x, w0, acc[e]);
                acc[e] = fmaf(x.y, w1, acc[e]);
                acc[e] = fmaf(x.z, w2, acc[e]);
                acc[e] = fmaf(x.w, w3, acc[e]);
            }
        }
        #pragma unroll
        for (int f4 = 0; f4 < 4; ++f4) {
            int f = f4 * 4;
            float w0 = sm[OFF_WEN + f * 64 + d];
            float w1 = sm[OFF_WEN + (f + 1) * 64 + d];
            float w2 = sm[OFF_WEN + (f + 2) * 64 + d];
            float w3 = sm[OFF_WEN + (f + 3) * 64 + d];
            #pragma unroll
            for (int e = 0; e < 8; ++e) {
                float4 x = *reinterpret_cast<const float4*>(&FEAT[(8 + e) * 32 + f]);
                acc[8+e] = fmaf(x.x, w0, acc[8+e]);
                acc[8+e] = fmaf(x.y, w1, acc[8+e]);
                acc[8+e] = fmaf(x.z, w2, acc[8+e]);
                acc[8+e] = fmaf(x.w, w3, acc[8+e]);
            }
        }
        float* er = &sm[S_ENTT + p * 1280 + d * 20];
        *reinterpret_cast<float4*>(&er[0])  = make_float4(acc[0], acc[1], acc[2], acc[3]);
        *reinterpret_cast<float4*>(&er[4])  = make_float4(acc[4], acc[5], acc[6], acc[7]);
        *reinterpret_cast<float4*>(&er[8])  = make_float4(acc[8], acc[9], acc[10], acc[11]);
        *reinterpret_cast<float4*>(&er[12]) = make_float4(acc[12], acc[13], acc[14], acc[15]);
    }
    __syncthreads();

    // ================= Phase Z: Z = X^T M  -> Zt[p][c*17+e] ================
    {
        int p = t >> 6, r = t & 63;
        int e0 = (r >> 4) * 4, c0 = (r & 15) * 4;
        ull acc[4][2];
        #pragma unroll
        for (int e = 0; e < 4; ++e) { acc[e][0] = 0ull; acc[e][1] = 0ull; }
        const float* X = &sm[S_ENTT + p * 1280 + e0];
        const float* M = &sm[OFF_M + c0];
        #pragma unroll 4
        for (int d = 0; d < 64; ++d) {
            float4 m4 = *reinterpret_cast<const float4*>(M + d * 64);
            float4 x4 = *reinterpret_cast<const float4*>(X + d * 20);
            ull mp0 = pk(m4.x, m4.y), mp1 = pk(m4.z, m4.w);
            ull xs0 = pk(x4.x, x4.x), xs1 = pk(x4.y, x4.y);
            ull xs2 = pk(x4.z, x4.z), xs3 = pk(x4.w, x4.w);
            fma2(acc[0][0], xs0, mp0); fma2(acc[0][1], xs0, mp1);
            fma2(acc[1][0], xs1, mp0); fma2(acc[1][1], xs1, mp1);
            fma2(acc[2][0], xs2, mp0); fma2(acc[2][1], xs2, mp1);
            fma2(acc[3][0], xs3, mp0); fma2(acc[3][1], xs3, mp1);
        }
        float* Zt = &sm[S_ZT + p * 1088];
        #pragma unroll
        for (int e = 0; e < 4; ++e) {
            float2 v0 = unpk(acc[e][0]), v1 = unpk(acc[e][1]);
            Zt[(c0    ) * 17 + e0 + e] = v0.x;
            Zt[(c0 + 1) * 17 + e0 + e] = v0.y;
            Zt[(c0 + 2) * 17 + e0 + e] = v1.x;
            Zt[(c0 + 3) * 17 + e0 + e] = v1.y;
        }
    }
    __syncthreads();

    // ================= Phase E: E[i][j] = Z[i]·x_j ; spare threads: xu ======
    if (t < 128) {
        int p = t >> 5, q = t & 31;
        int i0 = (q >> 2) * 2, j0 = (q & 3) * 4;
        const float* Zt = &sm[S_ZT + p * 1088];
        const float* X  = &sm[S_ENTT + p * 1280 + j0];
        ull acc[2][2];
        acc[0][0] = acc[0][1] = acc[1][0] = acc[1][1] = 0ull;
        #pragma unroll 4
        for (int c = 0; c < 64; ++c) {
            float z0 = Zt[c * 17 + i0];
            float z1 = Zt[c * 17 + i0 + 1];
            float4 x4 = *reinterpret_cast<const float4*>(X + c * 20);
            ull xp0 = pk(x4.x, x4.y), xp1 = pk(x4.z, x4.w);
            ull zs0 = pk(z0, z0), zs1 = pk(z1, z1);
            fma2(acc[0][0], zs0, xp0); fma2(acc[0][1], zs0, xp1);
            fma2(acc[1][0], zs1, xp0); fma2(acc[1][1], zs1, xp1);
        }
        float* E = &sm[S_EM + p * 272];
        #pragma unroll
        for (int ii = 0; ii < 2; ++ii) {
            float2 v0 = unpk(acc[ii][0]), v1 = unpk(acc[ii][1]);
            E[(i0 + ii) * 17 + j0]     = v0.x;
            E[(i0 + ii) * 17 + j0 + 1] = v0.y;
            E[(i0 + ii) * 17 + j0 + 2] = v1.x;
            E[(i0 + ii) * 17 + j0 + 3] = v1.y;
        }
    } else if (t < 192) {
        int idx = t - 128;
        int p = idx >> 4, e = idx & 15;
        const float* X = &sm[S_ENTT + p * 1280 + e];
        float s = 0.f;
        #pragma unroll 8
        for (int d = 0; d < 64; ++d)
            s = fmaf(X[d * 20], sm[OFF_U + d], s);
        sm[S_XU + p * 16 + e] = s;
    }
    __syncthreads();

    // ================= softmax over i (per column j) + amean ================
    if (t < 64) {
        int p = t >> 4, j = t & 15;
        float* E = &sm[S_EM + p * 272];
        const float* XU = &sm[S_XU + p * 16];
        float col[16];
        #pragma unroll
        for (int i = 0; i < 16; ++i) col[i] = E[i * 17 + j] + XU[i];
        float mx = col[0];
        #pragma unroll
        for (int i = 1; i < 16; ++i) mx = fmaxf(mx, col[i]);
        float ssum = 0.f;
        #pragma unroll
        for (int i = 0; i < 16; ++i) { col[i] = __expf(col[i] - mx); ssum += col[i]; }
        float inv = 1.0f / ssum;
        #pragma unroll
        for (int i = 0; i < 16; ++i) E[i * 17 + j] = col[i] * inv;
        __syncwarp();
        int i = j;
        const float* Er = &sm[S_EM + p * 272 + i * 17];
        float s = 0.f;
        #pragma unroll
        for (int jj = 0; jj < 16; ++jj) s += Er[jj];
        sm[S_AMEAN + p * 16 + i] = s * 0.0625f;
    }
    __syncthreads();

    // ================= attn_out -> AOT[d*4+p] (overlays XU, now dead) =======
    {
        int p = t >> 6, d = t & 63;
        const float* X = &sm[S_ENTT + p * 1280 + d * 20];
        const float* AM = &sm[S_AMEAN + p * 16];
        float4 x0 = *reinterpret_cast<const float4*>(X);
        float4 x1 = *reinterpret_cast<const float4*>(X + 4);
        float4 x2 = *reinterpret_cast<const float4*>(X + 8);
        float4 x3 = *reinterpret_cast<const float4*>(X + 12);
        float4 a0 = *reinterpret_cast<const float4*>(AM);
        float4 a1 = *reinterpret_cast<const float4*>(AM + 4);
        float4 a2 = *reinterpret_cast<const float4*>(AM + 8);
        float4 a3 = *reinterpret_cast<const float4*>(AM + 12);
        float s = x0.x*a0.x + x0.y*a0.y + x0.z*a0.z + x0.w*a0.w
                + x1.x*a1.x + x1.y*a1.y + x1.z*a1.z + x1.w*a1.w
                + x2.x*a2.x + x2.y*a2.y + x2.z*a2.z + x2.w*a2.w
                + x3.x*a3.x + x3.y*a3.y + x3.z*a3.z + x3.w*a3.w;
        __syncthreads();   // XU reads done before overlay write
        sm[S_AOT + d * 4 + p] = s;
    }
    __syncthreads();

    // ================= AOG: all attn_out projections (weights via LDG) =====
    if (t < 192) {
        const int col = t;
        const float* __restrict__ WC = &g_WCAT[col];
        const float* AOT = &sm[S_AOT];
        float a0 = 0.f, a1 = 0.f, a2 = 0.f, a3 = 0.f;
        #pragma unroll 8
        for (int f = 0; f < 64; ++f) {
            float w = __ldg(&WC[f * 192]);
            float4 ao = *reinterpret_cast<const float4*>(&AOT[f * 4]);
            a0 = fmaf(w, ao.x, a0);
            a1 = fmaf(w, ao.y, a1);
            a2 = fmaf(w, ao.z, a2);
            a3 = fmaf(w, ao.w, a3);
        }
        float b = sm[OFF_BCAT + col];
        a0 += b; a1 += b; a2 += b; a3 += b;
        if (col < 64) {
            sm[S_C +   0 + col] = a0;
            sm[S_C +  64 + col] = a1;
            sm[S_C + 128 + col] = a2;
            sm[S_C + 192 + col] = a3;
        } else if (col < 128) {
            int r = col - 64;
            sm[S_H2 +   0 + r] = fmaxf(a0, 0.f);
            sm[S_H2 +  64 + r] = fmaxf(a1, 0.f);
            sm[S_H2 + 128 + r] = fmaxf(a2, 0.f);
            sm[S_H2 + 192 + r] = fmaxf(a3, 0.f);
        } else if (col < 160) {
            int m = col - 128;
            sm[S_HBP +  0 + m] = a0;
            sm[S_HBP + 32 + m] = a1;
            sm[S_HBP + 64 + m] = a2;
            sm[S_HBP + 96 + m] = a3;
        } else {
            int m = col - 160;
            sm[S_H3 +  0 + m] = fmaxf(a0, 0.f);
            sm[S_H3 + 32 + m] = fmaxf(a1, 0.f);
            sm[S_H3 + 64 + m] = fmaxf(a2, 0.f);
            sm[S_H3 + 96 + m] = fmaxf(a3, 0.f);
        }
    }
    __syncthreads();

    // ======= SH2: s_h = relu(C + x_a @ W1A2); 2 pairs/thread, LDG reused ====
    if (t < 128) {
        int pg = t >> 6;                 // pairs {2pg, 2pg+1}
        int r  = t & 63;
        int ap  = r & 3;                 // agents 2ap, 2ap+1 packed (f32x2)
        int hu0 = (r >> 2) * 4;
        ull acc[2][4];
        const float* C0 = &sm[S_C + (2 * pg)     * 64 + hu0];
        const float* C1 = &sm[S_C + (2 * pg + 1) * 64 + hu0];
        #pragma unroll
        for (int j = 0; j < 4; ++j) {
            float c0 = C0[j], c1 = C1[j];
            acc[0][j] = pk(c0, c0);
            acc[1][j] = pk(c1, c1);
        }
        const float* __restrict__ W = &g_W1A2[hu0];
        const float* X0 = &sm[S_ENTT + (2 * pg)     * 1280 + 2 * ap];
        const float* X1 = &sm[S_ENTT + (2 * pg + 1) * 1280 + 2 * ap];
        #pragma unroll 4
        for (int f = 0; f < 64; ++f) {
            float4 w4 = __ldg(reinterpret_cast<const float4*>(&W[f * 64]));
            ull xp0 = *reinterpret_cast<const ull*>(&X0[f * 20]);
            ull xp1 = *reinterpret_cast<const ull*>(&X1[f * 20]);
            ull wx = pk(w4.x, w4.x), wy = pk(w4.y, w4.y);
            ull wz = pk(w4.z, w4.z), ww = pk(w4.w, w4.w);
            fma2(acc[0][0], xp0, wx); fma2(acc[1][0], xp1, wx);
            fma2(acc[0][1], xp0, wy); fma2(acc[1][1], xp1, wy);
            fma2(acc[0][2], xp0, wz); fma2(acc[1][2], xp1, wz);
            fma2(acc[0][3], xp0, ww); fma2(acc[1][3], xp1, ww);
        }
        #pragma unroll
        for (int pp = 0; pp < 2; ++pp) {
            float* SH = &sm[S_SH + (2 * pg + pp) * 512];
            #pragma unroll
            for (int j = 0; j < 4; ++j) {
                float2 v = unpk(acc[pp][j]);
                SH[(2 * ap)     * 64 + hu0 + j] = fmaxf(v.x, 0.f);
                SH[(2 * ap + 1) * 64 + hu0 + j] = fmaxf(v.y, 0.f);
            }
        }
    }
    __syncthreads();

    // ======= W1O: w1[a][m] = |SH[a] @ w1_W2 + b2|; 2 pairs/thread ==========
    if (t < 128) {
        int pg = t >> 6;
        int r  = t & 63;
        int a = r >> 3, m0 = (r & 7) * 4;
        ull b0 = pk(sm[OFF_W1B2 + m0],     sm[OFF_W1B2 + m0 + 1]);
        ull b1 = pk(sm[OFF_W1B2 + m0 + 2], sm[OFF_W1B2 + m0 + 3]);
        ull acc[2][2];
        acc[0][0] = b0; acc[0][1] = b1;
        acc[1][0] = b0; acc[1][1] = b1;
        const float* SH0 = &sm[S_SH + (2 * pg)     * 512 + a * 64];
        const float* SH1 = &sm[S_SH + (2 * pg + 1) * 512 + a * 64];
        const float* __restrict__ W = &g_w1W2[m0];
        #pragma unroll 4
        for (int k0 = 0; k0 < 64; k0 += 4) {
            float4 s4a = *reinterpret_cast<const float4*>(&SH0[k0]);
            float4 s4b = *reinterpret_cast<const float4*>(&SH1[k0]);
            #pragma unroll
            for (int j = 0; j < 4; ++j) {
                float4 w4 = __ldg(reinterpret_cast<const float4*>(&W[(k0 + j) * 32]));
                ull wlo = pk(w4.x, w4.y), whi = pk(w4.z, w4.w);
                float sa = (&s4a.x)[j], sb = (&s4b.x)[j];
                ull ssa = pk(sa, sa), ssb = pk(sb, sb);
                fma2(acc[0][0], ssa, wlo); fma2(acc[0][1], ssa, whi);
                fma2(acc[1][0], ssb, wlo); fma2(acc[1][1], ssb, whi);
            }
        }
        #pragma unroll
        for (int pp = 0; pp < 2; ++pp) {
            float2 v0 = unpk(acc[pp][0]), v1 = unpk(acc[pp][1]);
            *reinterpret_cast<float4*>(&sm[S_W1O + (2 * pg + pp) * 256 + a * 32 + m0]) =
                make_float4(fabsf(v0.x), fabsf(v0.y), fabsf(v1.x), fabsf(v1.y));
        }
    }
    __syncthreads();

    // ======= hidden + final (fused); 2 pairs/thread, wfW2 LDG reused =======
    if (t < 64) {
        int pg = t >> 5, m = t & 31;
        float hv0, hv1;
        {
            const float* AQ0 = &sm[S_AQ + (2 * pg) * 8];
            const float* AQ1 = &sm[S_AQ + (2 * pg + 1) * 8];
            const float* W1O0 = &sm[S_W1O + (2 * pg) * 256];
            const float* W1O1 = &sm[S_W1O + (2 * pg + 1) * 256];
            hv0 = sm[S_HBP + (2 * pg) * 32 + m];
            hv1 = sm[S_HBP + (2 * pg + 1) * 32 + m];
            #pragma unroll
            for (int a = 0; a < 8; ++a) {
                hv0 = fmaf(AQ0[a], W1O0[a * 32 + m], hv0);
                hv1 = fmaf(AQ1[a], W1O1[a * 32 + m], hv1);
            }
            hv0 = hv0 > 0.f ? hv0 : expm1f(hv0);
            hv1 = hv1 > 0.f ? hv1 : expm1f(hv1);
        }
        const float* H20 = &sm[S_H2 + (2 * pg) * 64];
        const float* H21 = &sm[S_H2 + (2 * pg + 1) * 64];
        float wfb = sm[OFF_WFB2 + m];
        float wf0 = wfb, wf1 = wfb;
        #pragma unroll 4
        for (int k0 = 0; k0 < 64; k0 += 4) {
            float4 ha = *reinterpret_cast<const float4*>(&H20[k0]);
            float4 hb = *reinterpret_cast<const float4*>(&H21[k0]);
            float w0 = __ldg(&g_wfW2[(k0    ) * 32 + m]);
            float w1 = __ldg(&g_wfW2[(k0 + 1) * 32 + m]);
            float w2 = __ldg(&g_wfW2[(k0 + 2) * 32 + m]);
            float w3 = __ldg(&g_wfW2[(k0 + 3) * 32 + m]);
            wf0 = fmaf(ha.x, w0, wf0); wf1 = fmaf(hb.x, w0, wf1);
            wf0 = fmaf(ha.y, w1, wf0); wf1 = fmaf(hb.y, w1, wf1);
            wf0 = fmaf(ha.z, w2, wf0); wf1 = fmaf(hb.z, w2, wf1);
            wf0 = fmaf(ha.w, w3, wf0); wf1 = fmaf(hb.w, w3, wf1);
        }
        wf0 = fabsf(wf0); wf1 = fabsf(wf1);
        float vw2 = sm[OFF_VW2 + m];
        float part0 = hv0 * wf0 + sm[S_H3 + (2 * pg) * 32 + m] * vw2;
        float part1 = hv1 * wf1 + sm[S_H3 + (2 * pg + 1) * 32 + m] * vw2;
        #pragma unroll
        for (int off = 16; off > 0; off >>= 1) {
            part0 += __shfl_down_sync(0xffffffffu, part0, off);
            part1 += __shfl_down_sync(0xffffffffu, part1, off);
        }
        if (m == 0) {
            float vb2 = sm[OFF_VB2];
            out[gp0 + 2 * pg]     = part0 + vb2;
            out[gp0 + 2 * pg + 1] = part1 + vb2;
        }
    }
}

extern "C" void kernel_launch(void* const* d_in, const int* in_sizes, int n_in,
                              void* d_out, int out_size) {
    (void)in_sizes; (void)n_in; (void)out_size;
    precompute_kernel<<<16, 256>>>(
        (const float*)d_in[7],  (const float*)d_in[9],  (const float*)d_in[10],
        (const float*)d_in[11], (const float*)d_in[15],
        (const float*)d_in[19], (const float*)d_in[21]);
    cudaFuncSetAttribute(qmixer_kernel,
                         cudaFuncAttributeMaxDynamicSharedMemorySize, SMEM_BYTES);
    qmixer_kernel<<<GRID, NTH, SMEM_BYTES>>>(
        (const float*)d_in[0],  (const float*)d_in[1],  (const float*)d_in[2],
        (const float*)d_in[3],  (const float*)d_in[4],
        (const float*)d_in[5],  (const float*)d_in[6],
        (const float*)d_in[11], (const float*)d_in[12],
        (const float*)d_in[13], (const float*)d_in[14],
        (const float*)d_in[16],
        (const float*)d_in[17], (const float*)d_in[18],
        (const float*)d_in[20],
        (const float*)d_in[22],
        (const float*)d_in[23], (const float*)d_in[24],
        (float*)d_out);
}

// round 8
// speedup vs baseline: 4.3937x; 1.0318x over previous
#include <cuda_runtime.h>
#include <math.h>

// QMixer forward on GB300 — round 8.
// Algebra: M = Wq Wk^T/sqrt(Da), u = Wq bk/sqrt(Da) (softmax over query axis).
// 4096 CTAs x 256 thr, 4 pairs/CTA, target 4 CTAs/SM (regs<=64, smem ~53.8KB).
// M and WEN served from L2 via LDG (coalesced); Phase B register-slimmed.

namespace {

constexpr int NTH   = 256;
constexpr int BSTOT = 16384;
constexpr int GRID  = BSTOT / 4;   // 4096

// ---- smem weight region, float offsets ----
constexpr int OFF_WAL  = 0;        // 32*64
constexpr int OFF_U    = 2048;     // 64
constexpr int OFF_BAL  = 2112;     // 64
constexpr int OFF_BEN  = 2176;     // 64
constexpr int OFF_W1B2 = 2240;     // 32
constexpr int OFF_WFB2 = 2272;     // 32
constexpr int OFF_BCAT = 2304;     // 192 [w1_b1 | wf_b1 | hb_b | v_b1]
constexpr int OFF_VW2  = 2496;     // 32
constexpr int OFF_VB2  = 2528;     // 1
constexpr int W_TOT_AL = 2544;     // 16-float aligned

// ---- scratch (float offsets) ----
constexpr int S_U1    = W_TOT_AL;        // 4352 union
constexpr int S_FEAT  = S_U1;            //      [p*512+e*32+f]
constexpr int S_ZT    = S_U1;            //      [p*1088+c*17+e]
constexpr int S_C     = S_U1;            // 256  [p*64+hu]
constexpr int S_H2    = S_U1 + 256;      // 256  [p*64+r]
constexpr int S_HBP   = S_U1 + 512;      // 128  [p*32+m]
constexpr int S_H3    = S_U1 + 640;      // 128  [p*32+m]
constexpr int S_SH    = S_U1 + 768;      // 2048 [p*512+a*64+hu]
constexpr int S_W1O   = S_U1 + 2816;     // 1024 [p*256+a*32+m]
constexpr int S_AQ    = S_U1 + 4352;     // 32   [p*8+a]
constexpr int S_ENTT  = S_AQ + 32;       // 5120 [p*1280+d*20+e]
constexpr int S_EM    = S_ENTT + 5120;   // 1088 [p*272+i*17+j]
constexpr int S_AMEAN = S_EM + 1088;     // 64   [p*16+e]
constexpr int S_AOT   = S_AMEAN + 64;    // 256  [d*4+p]; XU overlays
constexpr int S_XU    = S_AOT;           // 64   [p*16+e]
constexpr int SMEM_FLOATS = S_AOT + 256;

constexpr int SMEM_BYTES  = SMEM_FLOATS * 4;     // 53824 B
static_assert(4 * (SMEM_BYTES + 1024) <= 232448, "4 CTAs must fit with reserve");

constexpr float INVS = 0.08838834764831845f;     // 1/sqrt(128)

typedef unsigned long long ull;
__device__ __forceinline__ ull pk(float a, float b) {
    ull r; asm("mov.b64 %0,{%1,%2};" : "=l"(r) : "f"(a), "f"(b)); return r;
}
__device__ __forceinline__ void fma2(ull& acc, ull a, ull b) {
    asm("fma.rn.f32x2 %0,%1,%2,%0;" : "+l"(acc) : "l"(a), "l"(b));
}
__device__ __forceinline__ float2 unpk(ull v) {
    float2 f; asm("mov.b64 {%0,%1},%2;" : "=f"(f.x), "=f"(f.y) : "l"(v)); return f;
}

__device__ __align__(16) float g_M[64 * 64];
__device__ __align__(16) float g_U[64];
__device__ __align__(16) float g_WCAT[64 * 192];   // [w1_W1 r0-63 | wf_W1 | hb_W | v_W1]

} // namespace

// ------------- precompute: M, u, WCAT -------------
__global__ void precompute_kernel(const float* __restrict__ Wq,
                                  const float* __restrict__ Wk,
                                  const float* __restrict__ bk,
                                  const float* __restrict__ w1W1,
                                  const float* __restrict__ wfW1,
                                  const float* __restrict__ hbW,
                                  const float* __restrict__ vW1) {
    int t = threadIdx.x;                 // 256
    int d = blockIdx.x * 4 + (t >> 6);
    int c = t & 63;
    float s = 0.f;
    #pragma unroll 8
    for (int k = 0; k < 128; ++k)
        s = fmaf(Wq[d * 128 + k], Wk[c * 128 + k], s);
    g_M[d * 64 + c] = s * INVS;
    if (blockIdx.x == 0 && t < 64) {
        float su = 0.f;
        #pragma unroll 8
        for (int k = 0; k < 128; ++k)
            su = fmaf(Wq[t * 128 + k], bk[k], su);
        g_U[t] = su * INVS;
    }
    for (int i = blockIdx.x * NTH + t; i < 64 * 192; i += 16 * NTH) {
        int f = i / 192, cc = i % 192;
        float v;
        if (cc < 64)       v = w1W1[f * 64 + cc];
        else if (cc < 128) v = wfW1[f * 64 + cc - 64];
        else if (cc < 160) v = hbW[f * 32 + cc - 128];
        else               v = vW1[f * 32 + cc - 160];
        g_WCAT[i] = v;
    }
}

// ------------- main kernel -------------
__global__ void __launch_bounds__(NTH, 4) qmixer_kernel(
    const float* __restrict__ g_aq,     // [B,S,8]
    const float* __restrict__ g_ally,   // [8,B,S,32]
    const float* __restrict__ g_enemy,  // [8,B,S,16]
    const float* __restrict__ g_Wal,  const float* __restrict__ g_bal,
    const float* __restrict__ g_Wen,  const float* __restrict__ g_ben,
    const float* __restrict__ g_w1W1, const float* __restrict__ g_w1b1,
    const float* __restrict__ g_w1W2, const float* __restrict__ g_w1b2,
    const float* __restrict__ g_wfb1,
    const float* __restrict__ g_wfW2, const float* __restrict__ g_wfb2,
    const float* __restrict__ g_hbb,
    const float* __restrict__ g_vb1,
    const float* __restrict__ g_vW2,  const float* __restrict__ g_vb2,
    float* __restrict__ out)
{
    extern __shared__ float sm[];
    const int t = threadIdx.x;
    const int gp0 = blockIdx.x * 4;
    const float* __restrict__ g_W1A2 = g_w1W1 + 4096;   // rows 64..127

    // ---- stage smem weights ----
    {
        auto cp4 = [&](int off, const float* src, int n) {
            const float4* s4 = reinterpret_cast<const float4*>(src);
            float4* d4 = reinterpret_cast<float4*>(&sm[off]);
            for (int i = t; i < n / 4; i += NTH) d4[i] = s4[i];
        };
        cp4(OFF_WAL,  g_Wal,  2048);
        cp4(OFF_U,    g_U,    64);
        cp4(OFF_BAL,  g_bal,  64);
        cp4(OFF_BEN,  g_ben,  64);
        cp4(OFF_W1B2, g_w1b2, 32);
        cp4(OFF_WFB2, g_wfb2, 32);
        cp4(OFF_VW2,  g_vW2,  32);
        if (t < 192) {
            float b;
            if (t < 64)       b = g_w1b1[t];
            else if (t < 128) b = g_wfb1[t - 64];
            else if (t < 160) b = g_hbb[t - 128];
            else              b = g_vb1[t - 160];
            sm[OFF_BCAT + t] = b;
        }
        if (t == 0) sm[OFF_VB2] = g_vb2[0];
    }

    // ================= Phase A: load 4 pairs' inputs ========================
    {
        int p = t >> 6, e = (t >> 3) & 7, f4 = t & 7;
        reinterpret_cast<float4*>(&sm[S_FEAT + p * 512 + e * 32])[f4] =
            reinterpret_cast<const float4*>(&g_ally[(e * BSTOT + gp0 + p) * 32])[f4];
        if (t < 128) {
            int pp = t >> 5, ee = (t >> 2) & 7, ff4 = t & 3;
            reinterpret_cast<float4*>(&sm[S_FEAT + pp * 512 + (8 + ee) * 32])[ff4] =
                reinterpret_cast<const float4*>(&g_enemy[(ee * BSTOT + gp0 + pp) * 16])[ff4];
        }
        if (t < 32) {
            int pp = t >> 3, a = t & 7;
            sm[S_AQ + pp * 8 + a] = g_aq[(gp0 + pp) * 8 + a];
        }
    }
    __syncthreads();

    // ===== Phase B: embeddings -> ENTT[p][d*20+e], two 8-acc chunks =========
    {
        int p = t >> 6, d = t & 63;
        const float* FEAT = &sm[S_FEAT + p * 512];
        float* er = &sm[S_ENTT + p * 1280 + d * 20];
        // ---- ally chunk (e 0..7), weights from SMEM ----
        {
            float acc[8];
            float ba = sm[OFF_BAL + d];
            #pragma unroll
            for (int e = 0; e < 8; ++e) acc[e] = ba;
            #pragma unroll
            for (int f4 = 0; f4 < 8; ++f4) {
                int f = f4 * 4;
                float w0 = sm[OFF_WAL + f * 64 + d];
                float w1 = sm[OFF_WAL + (f + 1) * 64 + d];
                float w2 = sm[OFF_WAL + (f + 2) * 64 + d];
                float w3 = sm[OFF_WAL + (f + 3) * 64 + d];
                #pragma unroll
                for (int e = 0; e < 8; ++e) {
                    float4 x = *reinterpret_cast<const float4*>(&FEAT[e * 32 + f]);
                    acc[e] = fmaf(x.x, w0, acc[e]);
                    acc[e] = fmaf(x.y, w1, acc[e]);
                    acc[e] = fmaf(x.z, w2, acc[e]);
                    acc[e] = fmaf(x.w, w3, acc[e]);
                }
            }
            *reinterpret_cast<float4*>(&er[0]) = make_float4(acc[0], acc[1], acc[2], acc[3]);
            *reinterpret_cast<float4*>(&er[4]) = make_float4(acc[4], acc[5], acc[6], acc[7]);
        }
        // ---- enemy chunk (e 8..15), weights via LDG (coalesced 128B/warp) ----
        {
            float acc[8];
            float be = sm[OFF_BEN + d];
            #pragma unroll
            for (int e = 0; e < 8; ++e) acc[e] = be;
            #pragma unroll
            for (int f4 = 0; f4 < 4; ++f4) {
                int f = f4 * 4;
                float w0 = __ldg(&g_Wen[f * 64 + d]);
                float w1 = __ldg(&g_Wen[(f + 1) * 64 + d]);
                float w2 = __ldg(&g_Wen[(f + 2) * 64 + d]);
                float w3 = __ldg(&g_Wen[(f + 3) * 64 + d]);
                #pragma unroll
                for (int e = 0; e < 8; ++e) {
                    float4 x = *reinterpret_cast<const float4*>(&FEAT[(8 + e) * 32 + f]);
                    acc[e] = fmaf(x.x, w0, acc[e]);
                    acc[e] = fmaf(x.y, w1, acc[e]);
                    acc[e] = fmaf(x.z, w2, acc[e]);
                    acc[e] = fmaf(x.w, w3, acc[e]);
                }
            }
            *reinterpret_cast<float4*>(&er[8])  = make_float4(acc[0], acc[1], acc[2], acc[3]);
            *reinterpret_cast<float4*>(&er[12]) = make_float4(acc[4], acc[5], acc[6], acc[7]);
        }
    }
    __syncthreads();

    // ===== Phase Z: Z = X^T M -> Zt[p][c*17+e]; M via LDG (coalesced) ======
    {
        int p = t >> 6, r = t & 63;
        int e0 = (r >> 4) * 4, c0 = (r & 15) * 4;
        ull acc[4][2];
        #pragma unroll
        for (int e = 0; e < 4; ++e) { acc[e][0] = 0ull; acc[e][1] = 0ull; }
        const float* X = &sm[S_ENTT + p * 1280 + e0];
        #pragma unroll 4
        for (int d = 0; d < 64; ++d) {
            float4 m4 = __ldg(reinterpret_cast<const float4*>(&g_M[d * 64 + c0]));
            float4 x4 = *reinterpret_cast<const float4*>(X + d * 20);
            ull mp0 = pk(m4.x, m4.y), mp1 = pk(m4.z, m4.w);
            ull xs0 = pk(x4.x, x4.x), xs1 = pk(x4.y, x4.y);
            ull xs2 = pk(x4.z, x4.z), xs3 = pk(x4.w, x4.w);
            fma2(acc[0][0], xs0, mp0); fma2(acc[0][1], xs0, mp1);
            fma2(acc[1][0], xs1, mp0); fma2(acc[1][1], xs1, mp1);
            fma2(acc[2][0], xs2, mp0); fma2(acc[2][1], xs2, mp1);
            fma2(acc[3][0], xs3, mp0); fma2(acc[3][1], xs3, mp1);
        }
        float* Zt = &sm[S_ZT + p * 1088];
        #pragma unroll
        for (int e = 0; e < 4; ++e) {
            float2 v0 = unpk(acc[e][0]), v1 = unpk(acc[e][1]);
            Zt[(c0    ) * 17 + e0 + e] = v0.x;
            Zt[(c0 + 1) * 17 + e0 + e] = v0.y;
            Zt[(c0 + 2) * 17 + e0 + e] = v1.x;
            Zt[(c0 + 3) * 17 + e0 + e] = v1.y;
        }
    }
    __syncthreads();

    // ===== Phase E: E[i][j] = Z[i]·x_j ; spare threads: xu ==================
    if (t < 128) {
        int p = t >> 5, q = t & 31;
        int i0 = (q >> 2) * 2, j0 = (q & 3) * 4;
        const float* Zt = &sm[S_ZT + p * 1088];
        const float* X  = &sm[S_ENTT + p * 1280 + j0];
        ull acc[2][2];
        acc[0][0] = acc[0][1] = acc[1][0] = acc[1][1] = 0ull;
        #pragma unroll 4
        for (int c = 0; c < 64; ++c) {
            float z0 = Zt[c * 17 + i0];
            float z1 = Zt[c * 17 + i0 + 1];
            float4 x4 = *reinterpret_cast<const float4*>(X + c * 20);
            ull xp0 = pk(x4.x, x4.y), xp1 = pk(x4.z, x4.w);
            ull zs0 = pk(z0, z0), zs1 = pk(z1, z1);
            fma2(acc[0][0], zs0, xp0); fma2(acc[0][1], zs0, xp1);
            fma2(acc[1][0], zs1, xp0); fma2(acc[1][1], zs1, xp1);
        }
        float* E = &sm[S_EM + p * 272];
        #pragma unroll
        for (int ii = 0; ii < 2; ++ii) {
            float2 v0 = unpk(acc[ii][0]), v1 = unpk(acc[ii][1]);
            E[(i0 + ii) * 17 + j0]     = v0.x;
            E[(i0 + ii) * 17 + j0 + 1] = v0.y;
            E[(i0 + ii) * 17 + j0 + 2] = v1.x;
            E[(i0 + ii) * 17 + j0 + 3] = v1.y;
        }
    } else if (t < 192) {
        int idx = t - 128;
        int p = idx >> 4, e = idx & 15;
        const float* X = &sm[S_ENTT + p * 1280 + e];
        float s = 0.f;
        #pragma unroll 8
        for (int d = 0; d < 64; ++d)
            s = fmaf(X[d * 20], sm[OFF_U + d], s);
        sm[S_XU + p * 16 + e] = s;
    }
    __syncthreads();

    // ===== softmax over i (per column j) + amean ============================
    if (t < 64) {
        int p = t >> 4, j = t & 15;
        float* E = &sm[S_EM + p * 272];
        const float* XU = &sm[S_XU + p * 16];
        float col[16];
        #pragma unroll
        for (int i = 0; i < 16; ++i) col[i] = E[i * 17 + j] + XU[i];
        float mx = col[0];
        #pragma unroll
        for (int i = 1; i < 16; ++i) mx = fmaxf(mx, col[i]);
        float ssum = 0.f;
        #pragma unroll
        for (int i = 0; i < 16; ++i) { col[i] = __expf(col[i] - mx); ssum += col[i]; }
        float inv = 1.0f / ssum;
        #pragma unroll
        for (int i = 0; i < 16; ++i) E[i * 17 + j] = col[i] * inv;
        __syncwarp();
        int i = j;
        const float* Er = &sm[S_EM + p * 272 + i * 17];
        float s = 0.f;
        #pragma unroll
        for (int jj = 0; jj < 16; ++jj) s += Er[jj];
        sm[S_AMEAN + p * 16 + i] = s * 0.0625f;
    }
    __syncthreads();

    // ===== attn_out -> AOT[d*4+p] (overlays XU, now dead) ===================
    {
        int p = t >> 6, d = t & 63;
        const float* X = &sm[S_ENTT + p * 1280 + d * 20];
        const float* AM = &sm[S_AMEAN + p * 16];
        float4 x0 = *reinterpret_cast<const float4*>(X);
        float4 x1 = *reinterpret_cast<const float4*>(X + 4);
        float4 x2 = *reinterpret_cast<const float4*>(X + 8);
        float4 x3 = *reinterpret_cast<const float4*>(X + 12);
        float4 a0 = *reinterpret_cast<const float4*>(AM);
        float4 a1 = *reinterpret_cast<const float4*>(AM + 4);
        float4 a2 = *reinterpret_cast<const float4*>(AM + 8);
        float4 a3 = *reinterpret_cast<const float4*>(AM + 12);
        float s = x0.x*a0.x + x0.y*a0.y + x0.z*a0.z + x0.w*a0.w
                + x1.x*a1.x + x1.y*a1.y + x1.z*a1.z + x1.w*a1.w
                + x2.x*a2.x + x2.y*a2.y + x2.z*a2.z + x2.w*a2.w
                + x3.x*a3.x + x3.y*a3.y + x3.z*a3.z + x3.w*a3.w;
        __syncthreads();   // XU reads done before overlay write
        sm[S_AOT + d * 4 + p] = s;
    }
    __syncthreads();

    // ===== AOG: all attn_out projections (weights via LDG) ==================
    if (t < 192) {
        const int col = t;
        const float* __restrict__ WC = &g_WCAT[col];
        const float* AOT = &sm[S_AOT];
        float a0 = 0.f, a1 = 0.f, a2 = 0.f, a3 = 0.f;
        #pragma unroll 8
        for (int f = 0; f < 64; ++f) {
            float w = __ldg(&WC[f * 192]);
            float4 ao = *reinterpret_cast<const float4*>(&AOT[f * 4]);
            a0 = fmaf(w, ao.x, a0);
            a1 = fmaf(w, ao.y, a1);
            a2 = fmaf(w, ao.z, a2);
            a3 = fmaf(w, ao.w, a3);
        }
        float b = sm[OFF_BCAT + col];
        a0 += b; a1 += b; a2 += b; a3 += b;
        if (col < 64) {
            sm[S_C +   0 + col] = a0;
            sm[S_C +  64 + col] = a1;
            sm[S_C + 128 + col] = a2;
            sm[S_C + 192 + col] = a3;
        } else if (col < 128) {
            int r = col - 64;
            sm[S_H2 +   0 + r] = fmaxf(a0, 0.f);
            sm[S_H2 +  64 + r] = fmaxf(a1, 0.f);
            sm[S_H2 + 128 + r] = fmaxf(a2, 0.f);
            sm[S_H2 + 192 + r] = fmaxf(a3, 0.f);
        } else if (col < 160) {
            int m = col - 128;
            sm[S_HBP +  0 + m] = a0;
            sm[S_HBP + 32 + m] = a1;
            sm[S_HBP + 64 + m] = a2;
            sm[S_HBP + 96 + m] = a3;
        } else {
            int m = col - 160;
            sm[S_H3 +  0 + m] = fmaxf(a0, 0.f);
            sm[S_H3 + 32 + m] = fmaxf(a1, 0.f);
            sm[S_H3 + 64 + m] = fmaxf(a2, 0.f);
            sm[S_H3 + 96 + m] = fmaxf(a3, 0.f);
        }
    }
    __syncthreads();

    // ===== SH2: s_h = relu(C + x_a @ W1A2); 2 pairs/thread, LDG reused ======
    if (t < 128) {
        int pg = t >> 6;                 // pairs {2pg, 2pg+1}
        int r  = t & 63;
        int ap  = r & 3;                 // agents 2ap, 2ap+1 packed (f32x2)
        int hu0 = (r >> 2) * 4;
        ull acc[2][4];
        const float* C0 = &sm[S_C + (2 * pg)     * 64 + hu0];
        const float* C1 = &sm[S_C + (2 * pg + 1) * 64 + hu0];
        #pragma unroll
        for (int j = 0; j < 4; ++j) {
            float c0 = C0[j], c1 = C1[j];
            acc[0][j] = pk(c0, c0);
            acc[1][j] = pk(c1, c1);
        }
        const float* __restrict__ W = &g_W1A2[hu0];
        const float* X0 = &sm[S_ENTT + (2 * pg)     * 1280 + 2 * ap];
        const float* X1 = &sm[S_ENTT + (2 * pg + 1) * 1280 + 2 * ap];
        #pragma unroll 4
        for (int f = 0; f < 64; ++f) {
            float4 w4 = __ldg(reinterpret_cast<const float4*>(&W[f * 64]));
            ull xp0 = *reinterpret_cast<const ull*>(&X0[f * 20]);
            ull xp1 = *reinterpret_cast<const ull*>(&X1[f * 20]);
            ull wx = pk(w4.x, w4.x), wy = pk(w4.y, w4.y);
            ull wz = pk(w4.z, w4.z), ww = pk(w4.w, w4.w);
            fma2(acc[0][0], xp0, wx); fma2(acc[1][0], xp1, wx);
            fma2(acc[0][1], xp0, wy); fma2(acc[1][1], xp1, wy);
            fma2(acc[0][2], xp0, wz); fma2(acc[1][2], xp1, wz);
            fma2(acc[0][3], xp0, ww); fma2(acc[1][3], xp1, ww);
        }
        #pragma unroll
        for (int pp = 0; pp < 2; ++pp) {
            float* SH = &sm[S_SH + (2 * pg + pp) * 512];
            #pragma unroll
            for (int j = 0; j < 4; ++j) {
                float2 v = unpk(acc[pp][j]);
                SH[(2 * ap)     * 64 + hu0 + j] = fmaxf(v.x, 0.f);
                SH[(2 * ap + 1) * 64 + hu0 + j] = fmaxf(v.y, 0.f);
            }
        }
    }
    __syncthreads();

    // ===== W1O: w1[a][m] = |SH[a] @ w1_W2 + b2|; 2 pairs/thread =============
    if (t < 128) {
        int pg = t >> 6;
        int r  = t & 63;
        int a = r >> 3, m0 = (r & 7) * 4;
        ull b0 = pk(sm[OFF_W1B2 + m0],     sm[OFF_W1B2 + m0 + 1]);
        ull b1 = pk(sm[OFF_W1B2 + m0 + 2], sm[OFF_W1B2 + m0 + 3]);
        ull acc[2][2];
        acc[0][0] = b0; acc[0][1] = b1;
        acc[1][0] = b0; acc[1][1] = b1;
        const float* SH0 = &sm[S_SH + (2 * pg)     * 512 + a * 64];
        const float* SH1 = &sm[S_SH + (2 * pg + 1) * 512 + a * 64];
        const float* __restrict__ W = &g_w1W2[m0];
        #pragma unroll 4
        for (int k0 = 0; k0 < 64; k0 += 4) {
            float4 s4a = *reinterpret_cast<const float4*>(&SH0[k0]);
            float4 s4b = *reinterpret_cast<const float4*>(&SH1[k0]);
            #pragma unroll
            for (int j = 0; j < 4; ++j) {
                float4 w4 = __ldg(reinterpret_cast<const float4*>(&W[(k0 + j) * 32]));
                ull wlo = pk(w4.x, w4.y), whi = pk(w4.z, w4.w);
                float sa = (&s4a.x)[j], sb = (&s4b.x)[j];
                ull ssa = pk(sa, sa), ssb = pk(sb, sb);
                fma2(acc[0][0], ssa, wlo); fma2(acc[0][1], ssa, whi);
                fma2(acc[1][0], ssb, wlo); fma2(acc[1][1], ssb, whi);
            }
        }
        #pragma unroll
        for (int pp = 0; pp < 2; ++pp) {
            float2 v0 = unpk(acc[pp][0]), v1 = unpk(acc[pp][1]);
            *reinterpret_cast<float4*>(&sm[S_W1O + (2 * pg + pp) * 256 + a * 32 + m0]) =
                make_float4(fabsf(v0.x), fabsf(v0.y), fabsf(v1.x), fabsf(v1.y));
        }
    }
    __syncthreads();

    // ===== hidden + final (fused); 2 pairs/thread, wfW2 LDG reused ==========
    if (t < 64) {
        int pg = t >> 5, m = t & 31;
        float hv0, hv1;
        {
            const float* AQ0 = &sm[S_AQ + (2 * pg) * 8];
            const float* AQ1 = &sm[S_AQ + (2 * pg + 1) * 8];
            const float* W1O0 = &sm[S_W1O + (2 * pg) * 256];
            const float* W1O1 = &sm[S_W1O + (2 * pg + 1) * 256];
            hv0 = sm[S_HBP + (2 * pg) * 32 + m];
            hv1 = sm[S_HBP + (2 * pg + 1) * 32 + m];
            #pragma unroll
            for (int a = 0; a < 8; ++a) {
                hv0 = fmaf(AQ0[a], W1O0[a * 32 + m], hv0);
                hv1 = fmaf(AQ1[a], W1O1[a * 32 + m], hv1);
            }
            hv0 = hv0 > 0.f ? hv0 : expm1f(hv0);
            hv1 = hv1 > 0.f ? hv1 : expm1f(hv1);
        }
        const float* H20 = &sm[S_H2 + (2 * pg) * 64];
        const float* H21 = &sm[S_H2 + (2 * pg + 1) * 64];
        float wfb = sm[OFF_WFB2 + m];
        float wf0 = wfb, wf1 = wfb;
        #pragma unroll 4
        for (int k0 = 0; k0 < 64; k0 += 4) {
            float4 ha = *reinterpret_cast<const float4*>(&H20[k0]);
            float4 hb = *reinterpret_cast<const float4*>(&H21[k0]);
            float w0 = __ldg(&g_wfW2[(k0    ) * 32 + m]);
            float w1 = __ldg(&g_wfW2[(k0 + 1) * 32 + m]);
            float w2 = __ldg(&g_wfW2[(k0 + 2) * 32 + m]);
            float w3 = __ldg(&g_wfW2[(k0 + 3) * 32 + m]);
            wf0 = fmaf(ha.x, w0, wf0); wf1 = fmaf(hb.x, w0, wf1);
            wf0 = fmaf(ha.y, w1, wf0); wf1 = fmaf(hb.y, w1, wf1);
            wf0 = fmaf(ha.z, w2, wf0); wf1 = fmaf(hb.z, w2, wf1);
            wf0 = fmaf(ha.w, w3, wf0); wf1 = fmaf(hb.w, w3, wf1);
        }
        wf0 = fabsf(wf0); wf1 = fabsf(wf1);
        float vw2 = sm[OFF_VW2 + m];
        float part0 = hv0 * wf0 + sm[S_H3 + (2 * pg) * 32 + m] * vw2;
        float part1 = hv1 * wf1 + sm[S_H3 + (2 * pg + 1) * 32 + m] * vw2;
        #pragma unroll
        for (int off = 16; off > 0; off >>= 1) {
            part0 += __shfl_down_sync(0xffffffffu, part0, off);
            part1 += __shfl_down_sync(0xffffffffu, part1, off);
        }
        if (m == 0) {
            float vb2 = sm[OFF_VB2];
            out[gp0 + 2 * pg]     = part0 + vb2;
            out[gp0 + 2 * pg + 1] = part1 + vb2;
        }
    }
}

extern "C" void kernel_launch(void* const* d_in, const int* in_sizes, int n_in,
                              void* d_out, int out_size) {
    (void)in_sizes; (void)n_in; (void)out_size;
    precompute_kernel<<<16, 256>>>(
        (const float*)d_in[7],  (const float*)d_in[9],  (const float*)d_in[10],
        (const float*)d_in[11], (const float*)d_in[15],
        (const float*)d_in[19], (const float*)d_in[21]);
    cudaFuncSetAttribute(qmixer_kernel,
                         cudaFuncAttributeMaxDynamicSharedMemorySize, SMEM_BYTES);
    qmixer_kernel<<<GRID, NTH, SMEM_BYTES>>>(
        (const float*)d_in[0],  (const float*)d_in[1],  (const float*)d_in[2],
        (const float*)d_in[3],  (const float*)d_in[4],
        (const float*)d_in[5],  (const float*)d_in[6],
        (const float*)d_in[11], (const float*)d_in[12],
        (const float*)d_in[13], (const float*)d_in[14],
        (const float*)d_in[16],
        (const float*)d_in[17], (const float*)d_in[18],
        (const float*)d_in[20],
        (const float*)d_in[22],
        (const float*)d_in[23], (const float*)d_in[24],
        (float*)d_out);
}

// round 9
// speedup vs baseline: 4.5160x; 1.0278x over previous
#include <cuda_runtime.h>
#include <math.h>

// QMixer forward on GB300 — round 9.
// Algebra: M = Wq Wk^T/sqrt(Da), u = Wq bk/sqrt(Da) (softmax over query axis).
// 4096 CTAs x 256 thr, 4 pairs/CTA, 4 CTAs/SM (regs<=64, smem ~55.6KB).
// Round-9: L1tex wavefront cuts — Z remap (1-wf M loads, half-c per warp),
// Phase-B ally/enemy warp split (dedup broadcasts), E retile (4i x 2j).

namespace {

constexpr int NTH   = 256;
constexpr int BSTOT = 16384;
constexpr int GRID  = BSTOT / 4;   // 4096

// ---- smem weight region, float offsets ----
constexpr int OFF_WAL  = 0;        // 32*64
constexpr int OFF_U    = 2048;     // 64
constexpr int OFF_BAL  = 2112;     // 64
constexpr int OFF_BEN  = 2176;     // 64
constexpr int OFF_W1B2 = 2240;     // 32
constexpr int OFF_WFB2 = 2272;     // 32
constexpr int OFF_BCAT = 2304;     // 192 [w1_b1 | wf_b1 | hb_b | v_b1]
constexpr int OFF_VW2  = 2496;     // 32
constexpr int OFF_VB2  = 2528;     // 1
constexpr int W_TOT_AL = 2544;

// ---- scratch (float offsets) ----
// Union U1 (5120): FEAT (A/B) -> ZT[c*20+e] (Z/E) -> {C,H2,HBP,H3,SH,W1O}
constexpr int S_U1    = W_TOT_AL;
constexpr int S_FEAT  = S_U1;            // 2048 [p*512+e*32+f]
constexpr int S_ZT    = S_U1;            // 5120 [p*1280+c*20+e]
constexpr int S_C     = S_U1;            // 256  [p*64+hu]
constexpr int S_H2    = S_U1 + 256;      // 256  [p*64+r]
constexpr int S_HBP   = S_U1 + 512;      // 128  [p*32+m]
constexpr int S_H3    = S_U1 + 640;      // 128  [p*32+m]
constexpr int S_SH    = S_U1 + 768;      // 2048 [p*512+a*64+hu]
constexpr int S_W1O   = S_U1 + 2816;     // 1024 [p*256+a*32+m]
constexpr int S_AQ    = S_U1 + 5120;     // 32   [p*8+a]
constexpr int S_ENTT  = S_AQ + 32;       // 5120 [p*1280+d*20+e]
constexpr int S_EM    = S_ENTT + 5120;   // 1088 [p*272+i*17+j]
constexpr int S_AMEAN = S_EM + 1088;     // 64   [p*16+e]
constexpr int S_AOT   = S_AMEAN + 64;    // 256  [d*4+p]; XU overlays (dead before AOT write)
constexpr int S_XU    = S_AOT;           // 64   [p*16+e]
constexpr int SMEM_FLOATS = S_AOT + 256;

constexpr int SMEM_BYTES  = SMEM_FLOATS * 4;     // 56896 B
static_assert(4 * (SMEM_BYTES + 1024) <= 232448, "4 CTAs must fit with reserve");

constexpr float INVS = 0.08838834764831845f;     // 1/sqrt(128)

typedef unsigned long long ull;
__device__ __forceinline__ ull pk(float a, float b) {
    ull r; asm("mov.b64 %0,{%1,%2};" : "=l"(r) : "f"(a), "f"(b)); return r;
}
__device__ __forceinline__ void fma2(ull& acc, ull a, ull b) {
    asm("fma.rn.f32x2 %0,%1,%2,%0;" : "+l"(acc) : "l"(a), "l"(b));
}
__device__ __forceinline__ float2 unpk(ull v) {
    float2 f; asm("mov.b64 {%0,%1},%2;" : "=f"(f.x), "=f"(f.y) : "l"(v)); return f;
}

__device__ __align__(16) float g_M[64 * 64];
__device__ __align__(16) float g_U[64];
__device__ __align__(16) float g_WCAT[64 * 192];   // [w1_W1 r0-63 | wf_W1 | hb_W | v_W1]

} // namespace

// ------------- precompute: M, u, WCAT -------------
__global__ void precompute_kernel(const float* __restrict__ Wq,
                                  const float* __restrict__ Wk,
                                  const float* __restrict__ bk,
                                  const float* __restrict__ w1W1,
                                  const float* __restrict__ wfW1,
                                  const float* __restrict__ hbW,
                                  const float* __restrict__ vW1) {
    int t = threadIdx.x;                 // 256
    int d = blockIdx.x * 4 + (t >> 6);
    int c = t & 63;
    float s = 0.f;
    #pragma unroll 8
    for (int k = 0; k < 128; ++k)
        s = fmaf(Wq[d * 128 + k], Wk[c * 128 + k], s);
    g_M[d * 64 + c] = s * INVS;
    if (blockIdx.x == 0 && t < 64) {
        float su = 0.f;
        #pragma unroll 8
        for (int k = 0; k < 128; ++k)
            su = fmaf(Wq[t * 128 + k], bk[k], su);
        g_U[t] = su * INVS;
    }
    for (int i = blockIdx.x * NTH + t; i < 64 * 192; i += 16 * NTH) {
        int f = i / 192, cc = i % 192;
        float v;
        if (cc < 64)       v = w1W1[f * 64 + cc];
        else if (cc < 128) v = wfW1[f * 64 + cc - 64];
        else if (cc < 160) v = hbW[f * 32 + cc - 128];
        else               v = vW1[f * 32 + cc - 160];
        g_WCAT[i] = v;
    }
}

// ------------- main kernel -------------
__global__ void __launch_bounds__(NTH, 4) qmixer_kernel(
    const float* __restrict__ g_aq,     // [B,S,8]
    const float* __restrict__ g_ally,   // [8,B,S,32]
    const float* __restrict__ g_enemy,  // [8,B,S,16]
    const float* __restrict__ g_Wal,  const float* __restrict__ g_bal,
    const float* __restrict__ g_Wen,  const float* __restrict__ g_ben,
    const float* __restrict__ g_w1W1, const float* __restrict__ g_w1b1,
    const float* __restrict__ g_w1W2, const float* __restrict__ g_w1b2,
    const float* __restrict__ g_wfb1,
    const float* __restrict__ g_wfW2, const float* __restrict__ g_wfb2,
    const float* __restrict__ g_hbb,
    const float* __restrict__ g_vb1,
    const float* __restrict__ g_vW2,  const float* __restrict__ g_vb2,
    float* __restrict__ out)
{
    extern __shared__ float sm[];
    const int t = threadIdx.x;
    const int gp0 = blockIdx.x * 4;
    const float* __restrict__ g_W1A2 = g_w1W1 + 4096;   // rows 64..127

    // ---- stage smem weights ----
    {
        auto cp4 = [&](int off, const float* src, int n) {
            const float4* s4 = reinterpret_cast<const float4*>(src);
            float4* d4 = reinterpret_cast<float4*>(&sm[off]);
            for (int i = t; i < n / 4; i += NTH) d4[i] = s4[i];
        };
        cp4(OFF_WAL,  g_Wal,  2048);
        cp4(OFF_U,    g_U,    64);
        cp4(OFF_BAL,  g_bal,  64);
        cp4(OFF_BEN,  g_ben,  64);
        cp4(OFF_W1B2, g_w1b2, 32);
        cp4(OFF_WFB2, g_wfb2, 32);
        cp4(OFF_VW2,  g_vW2,  32);
        if (t < 192) {
            float b;
            if (t < 64)       b = g_w1b1[t];
            else if (t < 128) b = g_wfb1[t - 64];
            else if (t < 160) b = g_hbb[t - 128];
            else              b = g_vb1[t - 160];
            sm[OFF_BCAT + t] = b;
        }
        if (t == 0) sm[OFF_VB2] = g_vb2[0];
    }

    // ================= Phase A: load 4 pairs' inputs ========================
    {
        int p = t >> 6, e = (t >> 3) & 7, f4 = t & 7;
        reinterpret_cast<float4*>(&sm[S_FEAT + p * 512 + e * 32])[f4] =
            reinterpret_cast<const float4*>(&g_ally[(e * BSTOT + gp0 + p) * 32])[f4];
        if (t < 128) {
            int pp = t >> 5, ee = (t >> 2) & 7, ff4 = t & 3;
            reinterpret_cast<float4*>(&sm[S_FEAT + pp * 512 + (8 + ee) * 32])[ff4] =
                reinterpret_cast<const float4*>(&g_enemy[(ee * BSTOT + gp0 + pp) * 16])[ff4];
        }
        if (t < 32) {
            int pp = t >> 3, a = t & 7;
            sm[S_AQ + pp * 8 + a] = g_aq[(gp0 + pp) * 8 + a];
        }
    }
    __syncthreads();

    // ===== Phase B: embeddings -> ENTT[p][d*20+e]; warp0=ally, warp1=enemy ==
    {
        int p = t >> 6;
        int wv = (t >> 5) & 1;           // 0 -> ally (e0-7), 1 -> enemy (e8-15)
        int lane = t & 31;               // d and d+32
        const float* FEAT = &sm[S_FEAT + p * 512 + wv * 256];
        float* er = &sm[S_ENTT + p * 1280 + wv * 8];
        float acc[2][8];
        if (wv == 0) {
            float b0 = sm[OFF_BAL + lane], b1 = sm[OFF_BAL + lane + 32];
            #pragma unroll
            for (int e = 0; e < 8; ++e) { acc[0][e] = b0; acc[1][e] = b1; }
            #pragma unroll
            for (int f4 = 0; f4 < 8; ++f4) {
                int f = f4 * 4;
                float wA[4], wB[4];
                #pragma unroll
                for (int j = 0; j < 4; ++j) {
                    wA[j] = sm[OFF_WAL + (f + j) * 64 + lane];
                    wB[j] = sm[OFF_WAL + (f + j) * 64 + lane + 32];
                }
                #pragma unroll
                for (int e = 0; e < 8; ++e) {
                    float4 x = *reinterpret_cast<const float4*>(&FEAT[e * 32 + f]);
                    acc[0][e] = fmaf(x.x, wA[0], acc[0][e]);
                    acc[0][e] = fmaf(x.y, wA[1], acc[0][e]);
                    acc[0][e] = fmaf(x.z, wA[2], acc[0][e]);
                    acc[0][e] = fmaf(x.w, wA[3], acc[0][e]);
                    acc[1][e] = fmaf(x.x, wB[0], acc[1][e]);
                    acc[1][e] = fmaf(x.y, wB[1], acc[1][e]);
                    acc[1][e] = fmaf(x.z, wB[2], acc[1][e]);
                    acc[1][e] = fmaf(x.w, wB[3], acc[1][e]);
                }
            }
        } else {
            float b0 = sm[OFF_BEN + lane], b1 = sm[OFF_BEN + lane + 32];
            #pragma unroll
            for (int e = 0; e < 8; ++e) { acc[0][e] = b0; acc[1][e] = b1; }
            #pragma unroll
            for (int f4 = 0; f4 < 4; ++f4) {
                int f = f4 * 4;
                float wA[4], wB[4];
                #pragma unroll
                for (int j = 0; j < 4; ++j) {
                    wA[j] = __ldg(&g_Wen[(f + j) * 64 + lane]);
                    wB[j] = __ldg(&g_Wen[(f + j) * 64 + lane + 32]);
                }
                #pragma unroll
                for (int e = 0; e < 8; ++e) {
                    float4 x = *reinterpret_cast<const float4*>(&FEAT[e * 32 + f]);
                    acc[0][e] = fmaf(x.x, wA[0], acc[0][e]);
                    acc[0][e] = fmaf(x.y, wA[1], acc[0][e]);
                    acc[0][e] = fmaf(x.z, wA[2], acc[0][e]);
                    acc[0][e] = fmaf(x.w, wA[3], acc[0][e]);
                    acc[1][e] = fmaf(x.x, wB[0], acc[1][e]);
                    acc[1][e] = fmaf(x.y, wB[1], acc[1][e]);
                    acc[1][e] = fmaf(x.z, wB[2], acc[1][e]);
                    acc[1][e] = fmaf(x.w, wB[3], acc[1][e]);
                }
            }
        }
        #pragma unroll
        for (int d2 = 0; d2 < 2; ++d2) {
            float* row = &er[(lane + 32 * d2) * 20];
            *reinterpret_cast<float4*>(&row[0]) =
                make_float4(acc[d2][0], acc[d2][1], acc[d2][2], acc[d2][3]);
            *reinterpret_cast<float4*>(&row[4]) =
                make_float4(acc[d2][4], acc[d2][5], acc[d2][6], acc[d2][7]);
        }
    }
    __syncthreads();

    // ===== Phase Z: Z = X^T M -> ZT[p][c*20+e]; 4e x 4c per thread ==========
    // Warp covers half the c-range -> M LDG.128 = 128B/instr (1 wf).
    {
        int p = t >> 6, r = t & 63;
        int lane = r & 31;
        int e0 = (lane >> 3) * 4;                  // {0,4,8,12}
        int c0 = (lane & 7) * 4 + (r >> 5) * 32;   // warp-half of c
        ull acc[4][2];
        #pragma unroll
        for (int e = 0; e < 4; ++e) { acc[e][0] = 0ull; acc[e][1] = 0ull; }
        const float* X = &sm[S_ENTT + p * 1280 + e0];
        #pragma unroll 4
        for (int d = 0; d < 64; ++d) {
            float4 m4 = __ldg(reinterpret_cast<const float4*>(&g_M[d * 64 + c0]));
            float4 x4 = *reinterpret_cast<const float4*>(&X[d * 20]);
            ull mp0 = pk(m4.x, m4.y), mp1 = pk(m4.z, m4.w);
            ull xs;
            xs = pk(x4.x, x4.x); fma2(acc[0][0], xs, mp0); fma2(acc[0][1], xs, mp1);
            xs = pk(x4.y, x4.y); fma2(acc[1][0], xs, mp0); fma2(acc[1][1], xs, mp1);
            xs = pk(x4.z, x4.z); fma2(acc[2][0], xs, mp0); fma2(acc[2][1], xs, mp1);
            xs = pk(x4.w, x4.w); fma2(acc[3][0], xs, mp0); fma2(acc[3][1], xs, mp1);
        }
        float* Zt = &sm[S_ZT + p * 1280];
        #pragma unroll
        for (int k = 0; k < 2; ++k) {
            float2 u0 = unpk(acc[0][k]), u1 = unpk(acc[1][k]);
            float2 u2 = unpk(acc[2][k]), u3 = unpk(acc[3][k]);
            *reinterpret_cast<float4*>(&Zt[(c0 + 2 * k) * 20 + e0]) =
                make_float4(u0.x, u1.x, u2.x, u3.x);
            *reinterpret_cast<float4*>(&Zt[(c0 + 2 * k + 1) * 20 + e0]) =
                make_float4(u0.y, u1.y, u2.y, u3.y);
        }
    }
    __syncthreads();

    // ===== Phase E: E[i][j] = sum_c Z[i,c]·X[j,c]; 4i x 2j per thread =======
    if (t < 128) {
        int p = t >> 5, q = t & 31;
        int i0 = (q >> 3) * 4;        // {0,4,8,12}
        int j0 = (q & 7) * 2;         // {0,2,...,14}
        const float* Zt = &sm[S_ZT + p * 1280];
        const float* X  = &sm[S_ENTT + p * 1280];
        ull acc[4];
        acc[0] = acc[1] = acc[2] = acc[3] = 0ull;
        #pragma unroll 4
        for (int c = 0; c < 64; ++c) {
            float4 z4 = *reinterpret_cast<const float4*>(&Zt[c * 20 + i0]);
            ull x2 = *reinterpret_cast<const ull*>(&X[c * 20 + j0]);
            fma2(acc[0], pk(z4.x, z4.x), x2);
            fma2(acc[1], pk(z4.y, z4.y), x2);
            fma2(acc[2], pk(z4.z, z4.z), x2);
            fma2(acc[3], pk(z4.w, z4.w), x2);
        }
        float* E = &sm[S_EM + p * 272];
        #pragma unroll
        for (int ii = 0; ii < 4; ++ii) {
            float2 v = unpk(acc[ii]);
            E[(i0 + ii) * 17 + j0]     = v.x;
            E[(i0 + ii) * 17 + j0 + 1] = v.y;
        }
    } else if (t < 192) {
        int idx = t - 128;
        int p = idx >> 4, e = idx & 15;
        const float* X = &sm[S_ENTT + p * 1280 + e];
        float s = 0.f;
        #pragma unroll 8
        for (int d = 0; d < 64; ++d)
            s = fmaf(X[d * 20], sm[OFF_U + d], s);
        sm[S_XU + p * 16 + e] = s;
    }
    __syncthreads();

    // ===== softmax over i (per column j) + amean ============================
    if (t < 64) {
        int p = t >> 4, j = t & 15;
        float* E = &sm[S_EM + p * 272];
        const float* XU = &sm[S_XU + p * 16];
        float col[16];
        #pragma unroll
        for (int i = 0; i < 16; ++i) col[i] = E[i * 17 + j] + XU[i];
        float mx = col[0];
        #pragma unroll
        for (int i = 1; i < 16; ++i) mx = fmaxf(mx, col[i]);
        float ssum = 0.f;
        #pragma unroll
        for (int i = 0; i < 16; ++i) { col[i] = __expf(col[i] - mx); ssum += col[i]; }
        float inv = 1.0f / ssum;
        #pragma unroll
        for (int i = 0; i < 16; ++i) E[i * 17 + j] = col[i] * inv;
        __syncwarp();
        int i = j;
        const float* Er = &sm[S_EM + p * 272 + i * 17];
        float s = 0.f;
        #pragma unroll
        for (int jj = 0; jj < 16; ++jj) s += Er[jj];
        sm[S_AMEAN + p * 16 + i] = s * 0.0625f;
    }
    __syncthreads();

    // ===== attn_out -> AOT[d*4+p] (overlays XU, now dead) ===================
    {
        int p = t >> 6, d = t & 63;
        const float* X = &sm[S_ENTT + p * 1280 + d * 20];
        const float* AM = &sm[S_AMEAN + p * 16];
        float4 x0 = *reinterpret_cast<const float4*>(X);
        float4 x1 = *reinterpret_cast<const float4*>(X + 4);
        float4 x2 = *reinterpret_cast<const float4*>(X + 8);
        float4 x3 = *reinterpret_cast<const float4*>(X + 12);
        float4 a0 = *reinterpret_cast<const float4*>(AM);
        float4 a1 = *reinterpret_cast<const float4*>(AM + 4);
        float4 a2 = *reinterpret_cast<const float4*>(AM + 8);
        float4 a3 = *reinterpret_cast<const float4*>(AM + 12);
        float s = x0.x*a0.x + x0.y*a0.y + x0.z*a0.z + x0.w*a0.w
                + x1.x*a1.x + x1.y*a1.y + x1.z*a1.z + x1.w*a1.w
                + x2.x*a2.x + x2.y*a2.y + x2.z*a2.z + x2.w*a2.w
                + x3.x*a3.x + x3.y*a3.y + x3.z*a3.z + x3.w*a3.w;
        __syncthreads();   // XU reads done before overlay write
        sm[S_AOT + d * 4 + p] = s;
    }
    __syncthreads();

    // ===== AOG: all attn_out projections (weights via LDG) ==================
    if (t < 192) {
        const int col = t;
        const float* __restrict__ WC = &g_WCAT[col];
        const float* AOT = &sm[S_AOT];
        float a0 = 0.f, a1 = 0.f, a2 = 0.f, a3 = 0.f;
        #pragma unroll 8
        for (int f = 0; f < 64; ++f) {
            float w = __ldg(&WC[f * 192]);
            float4 ao = *reinterpret_cast<const float4*>(&AOT[f * 4]);
            a0 = fmaf(w, ao.x, a0);
            a1 = fmaf(w, ao.y, a1);
            a2 = fmaf(w, ao.z, a2);
            a3 = fmaf(w, ao.w, a3);
        }
        float b = sm[OFF_BCAT + col];
        a0 += b; a1 += b; a2 += b; a3 += b;
        if (col < 64) {
            sm[S_C +   0 + col] = a0;
            sm[S_C +  64 + col] = a1;
            sm[S_C + 128 + col] = a2;
            sm[S_C + 192 + col] = a3;
        } else if (col < 128) {
            int r = col - 64;
            sm[S_H2 +   0 + r] = fmaxf(a0, 0.f);
            sm[S_H2 +  64 + r] = fmaxf(a1, 0.f);
            sm[S_H2 + 128 + r] = fmaxf(a2, 0.f);
            sm[S_H2 + 192 + r] = fmaxf(a3, 0.f);
        } else if (col < 160) {
            int m = col - 128;
            sm[S_HBP +  0 + m] = a0;
            sm[S_HBP + 32 + m] = a1;
            sm[S_HBP + 64 + m] = a2;
            sm[S_HBP + 96 + m] = a3;
        } else {
            int m = col - 160;
            sm[S_H3 +  0 + m] = fmaxf(a0, 0.f);
            sm[S_H3 + 32 + m] = fmaxf(a1, 0.f);
            sm[S_H3 + 64 + m] = fmaxf(a2, 0.f);
            sm[S_H3 + 96 + m] = fmaxf(a3, 0.f);
        }
    }
    __syncthreads();

    // ===== SH2: s_h = relu(C + x_a @ W1A2); 2 pairs/thread, LDG reused ======
    if (t < 128) {
        int pg = t >> 6;                 // pairs {2pg, 2pg+1}
        int r  = t & 63;
        int ap  = r & 3;                 // agents 2ap, 2ap+1 packed (f32x2)
        int hu0 = (r >> 2) * 4;
        ull acc[2][4];
        const float* C0 = &sm[S_C + (2 * pg)     * 64 + hu0];
        const float* C1 = &sm[S_C + (2 * pg + 1) * 64 + hu0];
        #pragma unroll
        for (int j = 0; j < 4; ++j) {
            float c0 = C0[j], c1 = C1[j];
            acc[0][j] = pk(c0, c0);
            acc[1][j] = pk(c1, c1);
        }
        const float* __restrict__ W = &g_W1A2[hu0];
        const float* X0 = &sm[S_ENTT + (2 * pg)     * 1280 + 2 * ap];
        const float* X1 = &sm[S_ENTT + (2 * pg + 1) * 1280 + 2 * ap];
        #pragma unroll 4
        for (int f = 0; f < 64; ++f) {
            float4 w4 = __ldg(reinterpret_cast<const float4*>(&W[f * 64]));
            ull xp0 = *reinterpret_cast<const ull*>(&X0[f * 20]);
            ull xp1 = *reinterpret_cast<const ull*>(&X1[f * 20]);
            ull wx = pk(w4.x, w4.x), wy = pk(w4.y, w4.y);
            ull wz = pk(w4.z, w4.z), ww = pk(w4.w, w4.w);
            fma2(acc[0][0], xp0, wx); fma2(acc[1][0], xp1, wx);
            fma2(acc[0][1], xp0, wy); fma2(acc[1][1], xp1, wy);
            fma2(acc[0][2], xp0, wz); fma2(acc[1][2], xp1, wz);
            fma2(acc[0][3], xp0, ww); fma2(acc[1][3], xp1, ww);
        }
        #pragma unroll
        for (int pp = 0; pp < 2; ++pp) {
            float* SH = &sm[S_SH + (2 * pg + pp) * 512];
            #pragma unroll
            for (int j = 0; j < 4; ++j) {
                float2 v = unpk(acc[pp][j]);
                SH[(2 * ap)     * 64 + hu0 + j] = fmaxf(v.x, 0.f);
                SH[(2 * ap + 1) * 64 + hu0 + j] = fmaxf(v.y, 0.f);
            }
        }
    }
    __syncthreads();

    // ===== W1O: w1[a][m] = |SH[a] @ w1_W2 + b2|; 2 pairs/thread =============
    if (t < 128) {
        int pg = t >> 6;
        int r  = t & 63;
        int a = r >> 3, m0 = (r & 7) * 4;
        ull b0 = pk(sm[OFF_W1B2 + m0],     sm[OFF_W1B2 + m0 + 1]);
        ull b1 = pk(sm[OFF_W1B2 + m0 + 2], sm[OFF_W1B2 + m0 + 3]);
        ull acc[2][2];
        acc[0][0] = b0; acc[0][1] = b1;
        acc[1][0] = b0; acc[1][1] = b1;
        const float* SH0 = &sm[S_SH + (2 * pg)     * 512 + a * 64];
        const float* SH1 = &sm[S_SH + (2 * pg + 1) * 512 + a * 64];
        const float* __restrict__ W = &g_w1W2[m0];
        #pragma unroll 4
        for (int k0 = 0; k0 < 64; k0 += 4) {
            float4 s4a = *reinterpret_cast<const float4*>(&SH0[k0]);
            float4 s4b = *reinterpret_cast<const float4*>(&SH1[k0]);
            #pragma unroll
            for (int j = 0; j < 4; ++j) {
                float4 w4 = __ldg(reinterpret_cast<const float4*>(&W[(k0 + j) * 32]));
                ull wlo = pk(w4.x, w4.y), whi = pk(w4.z, w4.w);
                float sa = (&s4a.x)[j], sb = (&s4b.x)[j];
                ull ssa = pk(sa, sa), ssb = pk(sb, sb);
                fma2(acc[0][0], ssa, wlo); fma2(acc[0][1], ssa, whi);
                fma2(acc[1][0], ssb, wlo); fma2(acc[1][1], ssb, whi);
            }
        }
        #pragma unroll
        for (int pp = 0; pp < 2; ++pp) {
            float2 v0 = unpk(acc[pp][0]), v1 = unpk(acc[pp][1]);
            *reinterpret_cast<float4*>(&sm[S_W1O + (2 * pg + pp) * 256 + a * 32 + m0]) =
                make_float4(fabsf(v0.x), fabsf(v0.y), fabsf(v1.x), fabsf(v1.y));
        }
    }
    __syncthreads();

    // ===== hidden + final (fused); 2 pairs/thread, wfW2 LDG reused ==========
    if (t < 64) {
        int pg = t >> 5, m = t & 31;
        float hv0, hv1;
        {
            const float* AQ0 = &sm[S_AQ + (2 * pg) * 8];
            const float* AQ1 = &sm[S_AQ + (2 * pg + 1) * 8];
            const float* W1O0 = &sm[S_W1O + (2 * pg) * 256];
            const float* W1O1 = &sm[S_W1O + (2 * pg + 1) * 256];
            hv0 = sm[S_HBP + (2 * pg) * 32 + m];
            hv1 = sm[S_HBP + (2 * pg + 1) * 32 + m];
            #pragma unroll
            for (int a = 0; a < 8; ++a) {
                hv0 = fmaf(AQ0[a], W1O0[a * 32 + m], hv0);
                hv1 = fmaf(AQ1[a], W1O1[a * 32 + m], hv1);
            }
            hv0 = hv0 > 0.f ? hv0 : expm1f(hv0);
            hv1 = hv1 > 0.f ? hv1 : expm1f(hv1);
        }
        const float* H20 = &sm[S_H2 + (2 * pg) * 64];
        const float* H21 = &sm[S_H2 + (2 * pg + 1) * 64];
        float wfb = sm[OFF_WFB2 + m];
        float wf0 = wfb, wf1 = wfb;
        #pragma unroll 4
        for (int k0 = 0; k0 < 64; k0 += 4) {
            float4 ha = *reinterpret_cast<const float4*>(&H20[k0]);
            float4 hb = *reinterpret_cast<const float4*>(&H21[k0]);
            float w0 = __ldg(&g_wfW2[(k0    ) * 32 + m]);
            float w1 = __ldg(&g_wfW2[(k0 + 1) * 32 + m]);
            float w2 = __ldg(&g_wfW2[(k0 + 2) * 32 + m]);
            float w3 = __ldg(&g_wfW2[(k0 + 3) * 32 + m]);
            wf0 = fmaf(ha.x, w0, wf0); wf1 = fmaf(hb.x, w0, wf1);
            wf0 = fmaf(ha.y, w1, wf0); wf1 = fmaf(hb.y, w1, wf1);
            wf0 = fmaf(ha.z, w2, wf0); wf1 = fmaf(hb.z, w2, wf1);
            wf0 = fmaf(ha.w, w3, wf0); wf1 = fmaf(hb.w, w3, wf1);
        }
        wf0 = fabsf(wf0); wf1 = fabsf(wf1);
        float vw2 = sm[OFF_VW2 + m];
        float part0 = hv0 * wf0 + sm[S_H3 + (2 * pg) * 32 + m] * vw2;
        float part1 = hv1 * wf1 + sm[S_H3 + (2 * pg + 1) * 32 + m] * vw2;
        #pragma unroll
        for (int off = 16; off > 0; off >>= 1) {
            part0 += __shfl_down_sync(0xffffffffu, part0, off);
            part1 += __shfl_down_sync(0xffffffffu, part1, off);
        }
        if (m == 0) {
            float vb2 = sm[OFF_VB2];
            out[gp0 + 2 * pg]     = part0 + vb2;
            out[gp0 + 2 * pg + 1] = part1 + vb2;
        }
    }
}

extern "C" void kernel_launch(void* const* d_in, const int* in_sizes, int n_in,
                              void* d_out, int out_size) {
    (void)in_sizes; (void)n_in; (void)out_size;
    precompute_kernel<<<16, 256>>>(
        (const float*)d_in[7],  (const float*)d_in[9],  (const float*)d_in[10],
        (const float*)d_in[11], (const float*)d_in[15],
        (const float*)d_in[19], (const float*)d_in[21]);
    cudaFuncSetAttribute(qmixer_kernel,
                         cudaFuncAttributeMaxDynamicSharedMemorySize, SMEM_BYTES);
    qmixer_kernel<<<GRID, NTH, SMEM_BYTES>>>(
        (const float*)d_in[0],  (const float*)d_in[1],  (const float*)d_in[2],
        (const float*)d_in[3],  (const float*)d_in[4],
        (const float*)d_in[5],  (const float*)d_in[6],
        (const float*)d_in[11], (const float*)d_in[12],
        (const float*)d_in[13], (const float*)d_in[14],
        (const float*)d_in[16],
        (const float*)d_in[17], (const float*)d_in[18],
        (const float*)d_in[20],
        (const float*)d_in[22],
        (const float*)d_in[23], (const float*)d_in[24],
        (float*)d_out);
}